// round 1
// baseline (speedup 1.0000x reference)
#include <cuda_runtime.h>
#include <cuda_bf16.h>
#include <math.h>

// Problem constants
#define BATCH 16
#define CH    256
#define NH    4
#define DH    64
#define DKQ   32
#define LPIX  1024
#define CQKV  512            // CH + DK*NH*2
#define SCALE 0.17677669529663687f   // 32^-0.5

// Scratch (allocation-free: __device__ globals)
__device__ float g_qkv[(long)BATCH * CQKV * LPIX];   // [b][o][l]
__device__ float g_mid[(long)BATCH * CH * LPIX];     // [b][c][l]

// ---------------------------------------------------------------------------
// Batched SGEMM + BN epilogue: Y[b][m][n] = (sum_k A[m][k] * X[b][k][n]) * s[m] + bias[m]
// BM=BN=128, BK=16, 256 threads, 8x8 per-thread microtile.
// Requires M%128==0, N%128==0, K%16==0.
// ---------------------------------------------------------------------------
__global__ __launch_bounds__(256, 2)
void gemm_bn(const float* __restrict__ A, const float* __restrict__ X,
             float* __restrict__ Y, const float* __restrict__ scale,
             const float* __restrict__ bias, int M, int N, int K)
{
    __shared__ float As[16][132];
    __shared__ float Bs[16][132];

    const int tid = threadIdx.x;
    const int tx = tid & 15, ty = tid >> 4;
    const int n0 = blockIdx.x * 128;
    const int m0 = blockIdx.y * 128;
    const long bz = blockIdx.z;
    const float* Xb = X + bz * (long)K * N;
    float* Yb = Y + bz * (long)M * N;

    float acc[8][8];
#pragma unroll
    for (int i = 0; i < 8; i++)
#pragma unroll
        for (int j = 0; j < 8; j++) acc[i][j] = 0.f;

    for (int k0 = 0; k0 < K; k0 += 16) {
        // A tile 128x16 -> As[k][m] (transposed)
#pragma unroll
        for (int i = 0; i < 2; i++) {
            int f = tid + i * 256;            // 0..511
            int row = f >> 2;                 // 0..127
            int kq = (f & 3) * 4;             // 0,4,8,12
            float4 v = *reinterpret_cast<const float4*>(&A[(long)(m0 + row) * K + k0 + kq]);
            As[kq + 0][row] = v.x;
            As[kq + 1][row] = v.y;
            As[kq + 2][row] = v.z;
            As[kq + 3][row] = v.w;
        }
        // B tile 16x128 -> Bs[k][n]
#pragma unroll
        for (int i = 0; i < 2; i++) {
            int f = tid + i * 256;            // 0..511
            int kr = f >> 5;                  // 0..15
            int n4 = (f & 31) * 4;            // 0..124
            float4 v = *reinterpret_cast<const float4*>(&Xb[(long)(k0 + kr) * N + n0 + n4]);
            *reinterpret_cast<float4*>(&Bs[kr][n4]) = v;
        }
        __syncthreads();

#pragma unroll
        for (int kk = 0; kk < 16; kk++) {
            float a[8], b[8];
            *reinterpret_cast<float4*>(&a[0]) = *reinterpret_cast<const float4*>(&As[kk][ty * 8]);
            *reinterpret_cast<float4*>(&a[4]) = *reinterpret_cast<const float4*>(&As[kk][ty * 8 + 4]);
            *reinterpret_cast<float4*>(&b[0]) = *reinterpret_cast<const float4*>(&Bs[kk][tx * 8]);
            *reinterpret_cast<float4*>(&b[4]) = *reinterpret_cast<const float4*>(&Bs[kk][tx * 8 + 4]);
#pragma unroll
            for (int i = 0; i < 8; i++)
#pragma unroll
                for (int j = 0; j < 8; j++)
                    acc[i][j] = fmaf(a[i], b[j], acc[i][j]);
        }
        __syncthreads();
    }

#pragma unroll
    for (int i = 0; i < 8; i++) {
        int m = m0 + ty * 8 + i;
        float s = scale[m], bb = bias[m];
        float4 o0, o1;
        o0.x = acc[i][0] * s + bb; o0.y = acc[i][1] * s + bb;
        o0.z = acc[i][2] * s + bb; o0.w = acc[i][3] * s + bb;
        o1.x = acc[i][4] * s + bb; o1.y = acc[i][5] * s + bb;
        o1.z = acc[i][6] * s + bb; o1.w = acc[i][7] * s + bb;
        *reinterpret_cast<float4*>(&Yb[(long)m * N + n0 + tx * 8]) = o0;
        *reinterpret_cast<float4*>(&Yb[(long)m * N + n0 + tx * 8 + 4]) = o1;
    }
}

// ---------------------------------------------------------------------------
// Flash attention: per CTA one (b, h, query-tile of 128). Online softmax over
// key tiles of 128. S and P staged through smem; O accumulated in registers.
// Thread (ty 0..15, tx 0..15): S frag = 8 queries x 8 keys; O frag = 8 q x 4 d.
// Output written to g_mid[b][h*64 + d][l].
// ---------------------------------------------------------------------------
#define ATT_SMEM_FLOATS (32*128 + 32*128 + 128*68 + 128*129 + 128 + 128 + 128*16)

__global__ __launch_bounds__(256, 1)
void attn_kernel(const float* __restrict__ qkv, float* __restrict__ outm)
{
    extern __shared__ float sm[];
    float* sQ   = sm;                    // [32][128]  q (pre-scaled)
    float* sK   = sQ + 32 * 128;         // [32][128]
    float* sVt  = sK + 32 * 128;         // [128][68]  V transposed: sVt[j][d]
    float* sP   = sVt + 128 * 68;        // [128][129]
    float* sM   = sP + 128 * 129;        // [128] running max
    float* sL   = sM + 128;              // [128] running sum
    float* sRed = sL + 128;              // [128][16] reduction buffer

    const int tid = threadIdx.x;
    const int tx = tid & 15, ty = tid >> 4;
    const int qt = blockIdx.x;   // 0..7
    const int h  = blockIdx.y;   // 0..3
    const int b  = blockIdx.z;   // 0..15

    const float* base = qkv + ((long)b * CQKV + h * 128) * LPIX;
    const float* qg = base;
    const float* kg = base + 32 * LPIX;
    const float* vg = base + 64 * LPIX;

    // Load Q tile [32][128], scaled
#pragma unroll
    for (int i = 0; i < 4; i++) {
        int f = tid + i * 256;           // 0..1023
        int d = f >> 5;                  // 0..31
        int j4 = (f & 31) * 4;
        float4 v = *reinterpret_cast<const float4*>(&qg[(long)d * LPIX + qt * 128 + j4]);
        v.x *= SCALE; v.y *= SCALE; v.z *= SCALE; v.w *= SCALE;
        *reinterpret_cast<float4*>(&sQ[d * 128 + j4]) = v;
    }
    if (tid < 128) { sM[tid] = -INFINITY; sL[tid] = 0.f; }

    float O[8][4];
#pragma unroll
    for (int r = 0; r < 8; r++)
#pragma unroll
        for (int c = 0; c < 4; c++) O[r][c] = 0.f;

    for (int kt = 0; kt < 8; kt++) {
        // K tile [32][128]
#pragma unroll
        for (int i = 0; i < 4; i++) {
            int f = tid + i * 256;
            int d = f >> 5;
            int j4 = (f & 31) * 4;
            float4 v = *reinterpret_cast<const float4*>(&kg[(long)d * LPIX + kt * 128 + j4]);
            *reinterpret_cast<float4*>(&sK[d * 128 + j4]) = v;
        }
        // V tile [64][128] -> transposed sVt[j][d]
#pragma unroll
        for (int i = 0; i < 8; i++) {
            int f = tid + i * 256;           // 0..2047
            int d = f >> 5;                  // 0..63
            int j4 = (f & 31) * 4;
            float4 v = *reinterpret_cast<const float4*>(&vg[(long)d * LPIX + kt * 128 + j4]);
            sVt[(j4 + 0) * 68 + d] = v.x;
            sVt[(j4 + 1) * 68 + d] = v.y;
            sVt[(j4 + 2) * 68 + d] = v.z;
            sVt[(j4 + 3) * 68 + d] = v.w;
        }
        __syncthreads();

        // S = Q^T K  (8x8 per thread)
        float s[8][8];
#pragma unroll
        for (int r = 0; r < 8; r++)
#pragma unroll
            for (int c = 0; c < 8; c++) s[r][c] = 0.f;
#pragma unroll
        for (int kk = 0; kk < 32; kk++) {
            float a[8], bb[8];
            *reinterpret_cast<float4*>(&a[0]) = *reinterpret_cast<const float4*>(&sQ[kk * 128 + ty * 8]);
            *reinterpret_cast<float4*>(&a[4]) = *reinterpret_cast<const float4*>(&sQ[kk * 128 + ty * 8 + 4]);
            *reinterpret_cast<float4*>(&bb[0]) = *reinterpret_cast<const float4*>(&sK[kk * 128 + tx * 8]);
            *reinterpret_cast<float4*>(&bb[4]) = *reinterpret_cast<const float4*>(&sK[kk * 128 + tx * 8 + 4]);
#pragma unroll
            for (int r = 0; r < 8; r++)
#pragma unroll
                for (int c = 0; c < 8; c++)
                    s[r][c] = fmaf(a[r], bb[c], s[r][c]);
        }

        // Row-max partial -> sRed
#pragma unroll
        for (int r = 0; r < 8; r++) {
            float pm = s[r][0];
#pragma unroll
            for (int c = 1; c < 8; c++) pm = fmaxf(pm, s[r][c]);
            sRed[(ty * 8 + r) * 16 + tx] = pm;
        }
        __syncthreads();

        float mnew[8], corr[8];
#pragma unroll
        for (int r = 0; r < 8; r++) {
            int i = ty * 8 + r;
            float ml = sRed[i * 16 + 0];
#pragma unroll
            for (int t = 1; t < 16; t++) ml = fmaxf(ml, sRed[i * 16 + t]);
            mnew[r] = fmaxf(sM[i], ml);
            corr[r] = __expf(sM[i] - mnew[r]);
        }
        __syncthreads();   // done reading maxes; sRed reused for sums

        // P = exp(S - m), partial sums -> sRed
#pragma unroll
        for (int r = 0; r < 8; r++) {
            int i = ty * 8 + r;
            float ps = 0.f;
#pragma unroll
            for (int c = 0; c < 8; c++) {
                float p = __expf(s[r][c] - mnew[r]);
                sP[i * 129 + tx * 8 + c] = p;
                ps += p;
            }
            sRed[i * 16 + tx] = ps;
        }
        __syncthreads();

        if (tx == 0) {
#pragma unroll
            for (int r = 0; r < 8; r++) {
                int i = ty * 8 + r;
                float tot = 0.f;
#pragma unroll
                for (int t = 0; t < 16; t++) tot += sRed[i * 16 + t];
                sL[i] = sL[i] * corr[r] + tot;
                sM[i] = mnew[r];
            }
        }

        // O = O*corr + P @ V^T
#pragma unroll
        for (int r = 0; r < 8; r++)
#pragma unroll
            for (int c2 = 0; c2 < 4; c2++) O[r][c2] *= corr[r];

        const float* pbase = &sP[(ty * 8) * 129];
#pragma unroll 4
        for (int j = 0; j < 128; j++) {
            float4 v = *reinterpret_cast<const float4*>(&sVt[j * 68 + tx * 4]);
#pragma unroll
            for (int r = 0; r < 8; r++) {
                float p = pbase[r * 129 + j];
                O[r][0] = fmaf(p, v.x, O[r][0]);
                O[r][1] = fmaf(p, v.y, O[r][1]);
                O[r][2] = fmaf(p, v.z, O[r][2]);
                O[r][3] = fmaf(p, v.w, O[r][3]);
            }
        }
        __syncthreads();
    }

    // Normalize and write: out channel c = h*64 + d, position l = qt*128 + i
#pragma unroll
    for (int r = 0; r < 8; r++) {
        int i = ty * 8 + r;
        float inv = 1.f / sL[i];
#pragma unroll
        for (int c2 = 0; c2 < 4; c2++) {
            int d = tx * 4 + c2;
            outm[((long)b * CH + h * 64 + d) * LPIX + qt * 128 + i] = O[r][c2] * inv;
        }
    }
}

// ---------------------------------------------------------------------------
// Depthwise 3x3 conv (+BN), accumulated into g_mid.
// One CTA per (b, c) plane (32x32), 1024 threads.
// v channel c maps to qkv row (c/64)*128 + 64 + (c%64).
// ---------------------------------------------------------------------------
__global__ __launch_bounds__(1024)
void dw_kernel(const float* __restrict__ qkv, const float* __restrict__ w,
               const float* __restrict__ s, const float* __restrict__ bb,
               float* __restrict__ outm)
{
    const int c = blockIdx.x & 255;
    const int b = blockIdx.x >> 8;
    const int t = threadIdx.x;           // pixel index 0..1023
    const int y = t >> 5, x = t & 31;
    const int h = c >> 6, d = c & 63;
    const float* vp = qkv + ((long)b * CQKV + h * 128 + 64 + d) * LPIX;

    __shared__ float tile[34][34];
    tile[y + 1][x + 1] = vp[t];
    if (t < 34) {
        tile[0][t] = 0.f; tile[33][t] = 0.f;
        tile[t][0] = 0.f; tile[t][33] = 0.f;
    }
    __syncthreads();

    float acc = 0.f;
#pragma unroll
    for (int ky = 0; ky < 3; ky++)
#pragma unroll
        for (int kx = 0; kx < 3; kx++)
            acc = fmaf(tile[y + ky][x + kx], w[c * 9 + ky * 3 + kx], acc);

    outm[((long)b * CH + c) * LPIX + t] += acc * s[c] + bb[c];
}

// ---------------------------------------------------------------------------
extern "C" void kernel_launch(void* const* d_in, const int* in_sizes, int n_in,
                              void* d_out, int out_size)
{
    const float* x     = (const float*)d_in[0];
    const float* w_qkv = (const float*)d_in[1];
    const float* s_qkv = (const float*)d_in[2];
    const float* b_qkv = (const float*)d_in[3];
    const float* w_dw  = (const float*)d_in[4];
    const float* s_dw  = (const float*)d_in[5];
    const float* b_dw  = (const float*)d_in[6];
    const float* w_pw  = (const float*)d_in[7];
    const float* s_pw  = (const float*)d_in[8];
    const float* b_pw  = (const float*)d_in[9];
    float* out = (float*)d_out;

    float *qkvbuf = nullptr, *midbuf = nullptr;
    cudaGetSymbolAddress((void**)&qkvbuf, g_qkv);
    cudaGetSymbolAddress((void**)&midbuf, g_mid);

    const int att_smem = ATT_SMEM_FLOATS * (int)sizeof(float);
    cudaFuncSetAttribute(attn_kernel, cudaFuncAttributeMaxDynamicSharedMemorySize, att_smem);

    // 1) qkv = bn(W_qkv @ x)
    gemm_bn<<<dim3(8, 4, 16), 256>>>(w_qkv, x, qkvbuf, s_qkv, b_qkv, CQKV, LPIX, CH);
    // 2) attention -> g_mid
    attn_kernel<<<dim3(8, 4, 16), 256, att_smem>>>(qkvbuf, midbuf);
    // 3) g_mid += bn(dwconv3(v))
    dw_kernel<<<dim3(BATCH * CH), 1024>>>(qkvbuf, w_dw, s_dw, b_dw, midbuf);
    // 4) out = bn(W_pw @ g_mid)
    gemm_bn<<<dim3(8, 2, 16), 256>>>(w_pw, midbuf, out, s_pw, b_pw, CH, LPIX, CH);
}

// round 3
// speedup vs baseline: 1.2026x; 1.2026x over previous
#include <cuda_runtime.h>
#include <cuda_bf16.h>
#include <math.h>

// Problem constants
#define BATCH 16
#define CH    256
#define NH    4
#define DH    64
#define DKQ   32
#define LPIX  1024
#define CQKV  512            // CH + DK*NH*2
#define SCALE 0.17677669529663687f   // 32^-0.5

// Scratch (allocation-free: __device__ globals)
__device__ float g_qkv[(long)BATCH * CQKV * LPIX];   // [b][o][l]
__device__ float g_mid[(long)BATCH * CH * LPIX];     // [b][c][l]

// ---------------------------------------------------------------------------
// Batched SGEMM + BN epilogue: Y[b][m][n] = (sum_k A[m][k] * X[b][k][n]) * s[m] + bias[m]
// ---------------------------------------------------------------------------
__global__ __launch_bounds__(256, 2)
void gemm_bn(const float* __restrict__ A, const float* __restrict__ X,
             float* __restrict__ Y, const float* __restrict__ scale,
             const float* __restrict__ bias, int M, int N, int K)
{
    __shared__ float As[16][132];
    __shared__ float Bs[16][132];

    const int tid = threadIdx.x;
    const int tx = tid & 15, ty = tid >> 4;
    const int n0 = blockIdx.x * 128;
    const int m0 = blockIdx.y * 128;
    const long bz = blockIdx.z;
    const float* Xb = X + bz * (long)K * N;
    float* Yb = Y + bz * (long)M * N;

    float acc[8][8];
#pragma unroll
    for (int i = 0; i < 8; i++)
#pragma unroll
        for (int j = 0; j < 8; j++) acc[i][j] = 0.f;

    for (int k0 = 0; k0 < K; k0 += 16) {
#pragma unroll
        for (int i = 0; i < 2; i++) {
            int f = tid + i * 256;
            int row = f >> 2;
            int kq = (f & 3) * 4;
            float4 v = *reinterpret_cast<const float4*>(&A[(long)(m0 + row) * K + k0 + kq]);
            As[kq + 0][row] = v.x;
            As[kq + 1][row] = v.y;
            As[kq + 2][row] = v.z;
            As[kq + 3][row] = v.w;
        }
#pragma unroll
        for (int i = 0; i < 2; i++) {
            int f = tid + i * 256;
            int kr = f >> 5;
            int n4 = (f & 31) * 4;
            float4 v = *reinterpret_cast<const float4*>(&Xb[(long)(k0 + kr) * N + n0 + n4]);
            *reinterpret_cast<float4*>(&Bs[kr][n4]) = v;
        }
        __syncthreads();

#pragma unroll
        for (int kk = 0; kk < 16; kk++) {
            float a[8], b[8];
            *reinterpret_cast<float4*>(&a[0]) = *reinterpret_cast<const float4*>(&As[kk][ty * 8]);
            *reinterpret_cast<float4*>(&a[4]) = *reinterpret_cast<const float4*>(&As[kk][ty * 8 + 4]);
            *reinterpret_cast<float4*>(&b[0]) = *reinterpret_cast<const float4*>(&Bs[kk][tx * 8]);
            *reinterpret_cast<float4*>(&b[4]) = *reinterpret_cast<const float4*>(&Bs[kk][tx * 8 + 4]);
#pragma unroll
            for (int i = 0; i < 8; i++)
#pragma unroll
                for (int j = 0; j < 8; j++)
                    acc[i][j] = fmaf(a[i], b[j], acc[i][j]);
        }
        __syncthreads();
    }

#pragma unroll
    for (int i = 0; i < 8; i++) {
        int m = m0 + ty * 8 + i;
        float s = scale[m], bb = bias[m];
        float4 o0, o1;
        o0.x = acc[i][0] * s + bb; o0.y = acc[i][1] * s + bb;
        o0.z = acc[i][2] * s + bb; o0.w = acc[i][3] * s + bb;
        o1.x = acc[i][4] * s + bb; o1.y = acc[i][5] * s + bb;
        o1.z = acc[i][6] * s + bb; o1.w = acc[i][7] * s + bb;
        *reinterpret_cast<float4*>(&Yb[(long)m * N + n0 + tx * 8]) = o0;
        *reinterpret_cast<float4*>(&Yb[(long)m * N + n0 + tx * 8 + 4]) = o1;
    }
}

// ---------------------------------------------------------------------------
// Flash attention v2: CTA = (b, h, 128-query tile). Key tiles of 64, double-
// buffered. Shuffle-based softmax (row stats in registers). Vectorized PV.
// 256 threads: thread (ty=tid/16 -> 8 query rows, tx=tid%16 -> 4 cols).
// smem: sQ[32][132] | sK[2][32][68] | sVt[2][64][68] | sP[128][68]
// ---------------------------------------------------------------------------
#define KT 64
#define ATT_SQ   (32 * 132)
#define ATT_SK   (2 * 32 * 68)
#define ATT_SVT  (2 * 64 * 68)
#define ATT_SP   (128 * 68)
#define ATT_SMEM_FLOATS (ATT_SQ + ATT_SK + ATT_SVT + ATT_SP)

__global__ __launch_bounds__(256, 2)
void attn_kernel(const float* __restrict__ qkv, float* __restrict__ outm)
{
    extern __shared__ float sm[];
    float* sQ  = sm;                       // [32][132]
    float* sK  = sQ + ATT_SQ;              // [2][32][68]
    float* sVt = sK + ATT_SK;              // [2][64][68]
    float* sP  = sVt + ATT_SVT;            // [128][68]; reused as sOut[128][65]

    const int tid = threadIdx.x;
    const int tx = tid & 15, ty = tid >> 4;
    const int qt = blockIdx.x;   // 0..7
    const int h  = blockIdx.y;   // 0..3
    const int b  = blockIdx.z;   // 0..15

    const float* base = qkv + ((long)b * CQKV + h * 128) * LPIX;
    const float* qg = base;
    const float* kg = base + 32 * LPIX;
    const float* vg = base + 64 * LPIX;

    // Load Q tile [32 d][128 i], pre-scaled
#pragma unroll
    for (int i = 0; i < 4; i++) {
        int f = tid + i * 256;
        int d = f >> 5;
        int j4 = (f & 31) * 4;
        float4 v = *reinterpret_cast<const float4*>(&qg[(long)d * LPIX + qt * 128 + j4]);
        v.x *= SCALE; v.y *= SCALE; v.z *= SCALE; v.w *= SCALE;
        *reinterpret_cast<float4*>(&sQ[d * 132 + j4]) = v;
    }

    float O[8][4];
    float m_run[8], l_run[8];
#pragma unroll
    for (int r = 0; r < 8; r++) {
        m_run[r] = -INFINITY; l_run[r] = 0.f;
#pragma unroll
        for (int c = 0; c < 4; c++) O[r][c] = 0.f;
    }

    // Preload first K/V tile into buffer 0
    {
        float* sKb = sK;
        float* sVb = sVt;
#pragma unroll
        for (int i = 0; i < 2; i++) {
            int f = tid + i * 256;
            int d = f >> 4;
            int j4 = (f & 15) * 4;
            float4 v = *reinterpret_cast<const float4*>(&kg[(long)d * LPIX + j4]);
            *reinterpret_cast<float4*>(&sKb[d * 68 + j4]) = v;
        }
#pragma unroll
        for (int i = 0; i < 4; i++) {
            int f = tid + i * 256;
            int d = f >> 4;
            int j4 = (f & 15) * 4;
            float4 v = *reinterpret_cast<const float4*>(&vg[(long)d * LPIX + j4]);
            sVb[(j4 + 0) * 68 + d] = v.x;
            sVb[(j4 + 1) * 68 + d] = v.y;
            sVb[(j4 + 2) * 68 + d] = v.z;
            sVb[(j4 + 3) * 68 + d] = v.w;
        }
    }
    __syncthreads();

    for (int kt = 0; kt < 16; kt++) {
        const int buf = kt & 1;
        float* sKb = sK + buf * (32 * 68);
        float* sVb = sVt + buf * (64 * 68);

        // Prefetch next tile into the other buffer (no barrier needed before
        // reading it: next iteration's first sync covers it).
        if (kt + 1 < 16) {
            float* sKn = sK + (1 - buf) * (32 * 68);
            float* sVn = sVt + (1 - buf) * (64 * 68);
            const int koff = (kt + 1) * KT;
#pragma unroll
            for (int i = 0; i < 2; i++) {
                int f = tid + i * 256;
                int d = f >> 4;
                int j4 = (f & 15) * 4;
                float4 v = *reinterpret_cast<const float4*>(&kg[(long)d * LPIX + koff + j4]);
                *reinterpret_cast<float4*>(&sKn[d * 68 + j4]) = v;
            }
#pragma unroll
            for (int i = 0; i < 4; i++) {
                int f = tid + i * 256;
                int d = f >> 4;
                int j4 = (f & 15) * 4;
                float4 v = *reinterpret_cast<const float4*>(&vg[(long)d * LPIX + koff + j4]);
                sVn[(j4 + 0) * 68 + d] = v.x;
                sVn[(j4 + 1) * 68 + d] = v.y;
                sVn[(j4 + 2) * 68 + d] = v.z;
                sVn[(j4 + 3) * 68 + d] = v.w;
            }
        }

        // S = Q^T K : per-thread 8 rows x 4 cols
        float s[8][4];
#pragma unroll
        for (int r = 0; r < 8; r++)
#pragma unroll
            for (int c = 0; c < 4; c++) s[r][c] = 0.f;
#pragma unroll
        for (int kk = 0; kk < 32; kk++) {
            float a[8], bb[4];
            *reinterpret_cast<float4*>(&a[0]) = *reinterpret_cast<const float4*>(&sQ[kk * 132 + ty * 8]);
            *reinterpret_cast<float4*>(&a[4]) = *reinterpret_cast<const float4*>(&sQ[kk * 132 + ty * 8 + 4]);
            *reinterpret_cast<float4*>(&bb[0]) = *reinterpret_cast<const float4*>(&sKb[kk * 68 + tx * 4]);
#pragma unroll
            for (int r = 0; r < 8; r++)
#pragma unroll
                for (int c = 0; c < 4; c++)
                    s[r][c] = fmaf(a[r], bb[c], s[r][c]);
        }

        // Online softmax with shuffle reductions (16-lane groups share rows)
        float psum[8];
#pragma unroll
        for (int r = 0; r < 8; r++) {
            float pm = fmaxf(fmaxf(s[r][0], s[r][1]), fmaxf(s[r][2], s[r][3]));
#pragma unroll
            for (int off = 1; off < 16; off <<= 1)
                pm = fmaxf(pm, __shfl_xor_sync(0xffffffffu, pm, off, 16));
            float mnew = fmaxf(m_run[r], pm);
            float corr = __expf(m_run[r] - mnew);
            m_run[r] = mnew;
#pragma unroll
            for (int c = 0; c < 4; c++) O[r][c] *= corr;
            float4 p;
            p.x = __expf(s[r][0] - mnew);
            p.y = __expf(s[r][1] - mnew);
            p.z = __expf(s[r][2] - mnew);
            p.w = __expf(s[r][3] - mnew);
            *reinterpret_cast<float4*>(&sP[(ty * 8 + r) * 68 + tx * 4]) = p;
            psum[r] = (p.x + p.y) + (p.z + p.w);
            l_run[r] *= corr;
        }
#pragma unroll
        for (int r = 0; r < 8; r++) {
            float ps = psum[r];
#pragma unroll
            for (int off = 1; off < 16; off <<= 1)
                ps += __shfl_xor_sync(0xffffffffu, ps, off, 16);
            l_run[r] += ps;
        }
        __syncthreads();   // sP visible to all

        // O += P @ V  (per-thread 8 rows x 4 d-cols), vectorized over j
#pragma unroll 4
        for (int j = 0; j < KT; j += 4) {
            float4 v0 = *reinterpret_cast<const float4*>(&sVb[(j + 0) * 68 + tx * 4]);
            float4 v1 = *reinterpret_cast<const float4*>(&sVb[(j + 1) * 68 + tx * 4]);
            float4 v2 = *reinterpret_cast<const float4*>(&sVb[(j + 2) * 68 + tx * 4]);
            float4 v3 = *reinterpret_cast<const float4*>(&sVb[(j + 3) * 68 + tx * 4]);
#pragma unroll
            for (int r = 0; r < 8; r++) {
                float4 p = *reinterpret_cast<const float4*>(&sP[(ty * 8 + r) * 68 + j]);
                O[r][0] = fmaf(p.x, v0.x, O[r][0]);
                O[r][1] = fmaf(p.x, v0.y, O[r][1]);
                O[r][2] = fmaf(p.x, v0.z, O[r][2]);
                O[r][3] = fmaf(p.x, v0.w, O[r][3]);
                O[r][0] = fmaf(p.y, v1.x, O[r][0]);
                O[r][1] = fmaf(p.y, v1.y, O[r][1]);
                O[r][2] = fmaf(p.y, v1.z, O[r][2]);
                O[r][3] = fmaf(p.y, v1.w, O[r][3]);
                O[r][0] = fmaf(p.z, v2.x, O[r][0]);
                O[r][1] = fmaf(p.z, v2.y, O[r][1]);
                O[r][2] = fmaf(p.z, v2.z, O[r][2]);
                O[r][3] = fmaf(p.z, v2.w, O[r][3]);
                O[r][0] = fmaf(p.w, v3.x, O[r][0]);
                O[r][1] = fmaf(p.w, v3.y, O[r][1]);
                O[r][2] = fmaf(p.w, v3.z, O[r][2]);
                O[r][3] = fmaf(p.w, v3.w, O[r][3]);
            }
        }
        __syncthreads();   // done with sP (rewritten next tile) and sKb/sVb
    }

    // Stage normalized O into smem [i][65] (conflict-free re-read), then
    // write channel-major coalesced.
    float* sOut = sP;      // reuse; 128*65 <= 128*68
#pragma unroll
    for (int r = 0; r < 8; r++) {
        float inv = 1.f / l_run[r];
#pragma unroll
        for (int c = 0; c < 4; c++)
            sOut[(ty * 8 + r) * 65 + tx * 4 + c] = O[r][c] * inv;
    }
    __syncthreads();

    float* op = outm + ((long)b * CH + h * 64) * LPIX + qt * 128;
#pragma unroll
    for (int it = 0; it < 32; it++) {
        int f = tid + it * 256;     // 0..8191
        int d = f >> 7;             // 0..63
        int i = f & 127;            // 0..127
        op[(long)d * LPIX + i] = sOut[i * 65 + d];
    }
}

// ---------------------------------------------------------------------------
// Depthwise 3x3 conv (+BN), accumulated into g_mid.
// ---------------------------------------------------------------------------
__global__ __launch_bounds__(1024)
void dw_kernel(const float* __restrict__ qkv, const float* __restrict__ w,
               const float* __restrict__ s, const float* __restrict__ bb,
               float* __restrict__ outm)
{
    const int c = blockIdx.x & 255;
    const int b = blockIdx.x >> 8;
    const int t = threadIdx.x;
    const int y = t >> 5, x = t & 31;
    const int h = c >> 6, d = c & 63;
    const float* vp = qkv + ((long)b * CQKV + h * 128 + 64 + d) * LPIX;

    __shared__ float tile[34][34];
    tile[y + 1][x + 1] = vp[t];
    if (t < 34) {
        tile[0][t] = 0.f; tile[33][t] = 0.f;
        tile[t][0] = 0.f; tile[t][33] = 0.f;
    }
    __syncthreads();

    float acc = 0.f;
#pragma unroll
    for (int ky = 0; ky < 3; ky++)
#pragma unroll
        for (int kx = 0; kx < 3; kx++)
            acc = fmaf(tile[y + ky][x + kx], w[c * 9 + ky * 3 + kx], acc);

    outm[((long)b * CH + c) * LPIX + t] += acc * s[c] + bb[c];
}

// ---------------------------------------------------------------------------
extern "C" void kernel_launch(void* const* d_in, const int* in_sizes, int n_in,
                              void* d_out, int out_size)
{
    const float* x     = (const float*)d_in[0];
    const float* w_qkv = (const float*)d_in[1];
    const float* s_qkv = (const float*)d_in[2];
    const float* b_qkv = (const float*)d_in[3];
    const float* w_dw  = (const float*)d_in[4];
    const float* s_dw  = (const float*)d_in[5];
    const float* b_dw  = (const float*)d_in[6];
    const float* w_pw  = (const float*)d_in[7];
    const float* s_pw  = (const float*)d_in[8];
    const float* b_pw  = (const float*)d_in[9];
    float* out = (float*)d_out;

    float *qkvbuf = nullptr, *midbuf = nullptr;
    cudaGetSymbolAddress((void**)&qkvbuf, g_qkv);
    cudaGetSymbolAddress((void**)&midbuf, g_mid);

    const int att_smem = ATT_SMEM_FLOATS * (int)sizeof(float);
    cudaFuncSetAttribute(attn_kernel, cudaFuncAttributeMaxDynamicSharedMemorySize, att_smem);

    // 1) qkv = bn(W_qkv @ x)
    gemm_bn<<<dim3(8, 4, 16), 256>>>(w_qkv, x, qkvbuf, s_qkv, b_qkv, CQKV, LPIX, CH);
    // 2) attention -> g_mid
    attn_kernel<<<dim3(8, 4, 16), 256, att_smem>>>(qkvbuf, midbuf);
    // 3) g_mid += bn(dwconv3(v))
    dw_kernel<<<dim3(BATCH * CH), 1024>>>(qkvbuf, w_dw, s_dw, b_dw, midbuf);
    // 4) out = bn(W_pw @ g_mid)
    gemm_bn<<<dim3(8, 2, 16), 256>>>(w_pw, midbuf, out, s_pw, b_pw, CH, LPIX, CH);
}

// round 4
// speedup vs baseline: 1.2245x; 1.0182x over previous
#include <cuda_runtime.h>
#include <cuda_bf16.h>
#include <math.h>

// Problem constants
#define BATCH 16
#define CH    256
#define NH    4
#define DH    64
#define DKQ   32
#define LPIX  1024
#define CQKV  512            // CH + DK*NH*2
#define SCALE 0.17677669529663687f   // 32^-0.5

typedef unsigned long long u64;

// Packed fp32x2 helpers (Blackwell: one FFMA2 = two IEEE fp32 FMAs)
__device__ __forceinline__ u64 pk2(float lo, float hi) {
    u64 r;
    asm("mov.b64 %0, {%1, %2};" : "=l"(r) : "f"(lo), "f"(hi));
    return r;
}
__device__ __forceinline__ u64 dup2(float v) {
    u64 r;
    asm("mov.b64 %0, {%1, %1};" : "=l"(r) : "f"(v));
    return r;
}
__device__ __forceinline__ u64 fma2(u64 a, u64 b, u64 c) {
    u64 d;
    asm("fma.rn.f32x2 %0, %1, %2, %3;" : "=l"(d) : "l"(a), "l"(b), "l"(c));
    return d;
}
__device__ __forceinline__ u64 mul2(u64 a, u64 b) {
    u64 d;
    asm("mul.rn.f32x2 %0, %1, %2;" : "=l"(d) : "l"(a), "l"(b));
    return d;
}
__device__ __forceinline__ void upk2(u64 v, float& lo, float& hi) {
    asm("mov.b64 {%0, %1}, %2;" : "=f"(lo), "=f"(hi) : "l"(v));
}

// Scratch (allocation-free: __device__ globals)
__device__ float g_qkv[(long)BATCH * CQKV * LPIX];   // [b][o][l]
__device__ float g_mid[(long)BATCH * CH * LPIX];     // [b][c][l]

// ---------------------------------------------------------------------------
// Batched SGEMM + BN epilogue, packed f32x2 accumulators.
// Y[b][m][n] = (sum_k A[m][k] * X[b][k][n]) * s[m] + bias[m]
// ---------------------------------------------------------------------------
__global__ __launch_bounds__(256, 2)
void gemm_bn(const float* __restrict__ A, const float* __restrict__ X,
             float* __restrict__ Y, const float* __restrict__ scale,
             const float* __restrict__ bias, int M, int N, int K)
{
    __shared__ float As[16][132];
    __shared__ float Bs[16][132];

    const int tid = threadIdx.x;
    const int tx = tid & 15, ty = tid >> 4;
    const int n0 = blockIdx.x * 128;
    const int m0 = blockIdx.y * 128;
    const long bz = blockIdx.z;
    const float* Xb = X + bz * (long)K * N;
    float* Yb = Y + bz * (long)M * N;

    u64 acc2[8][4];
    const u64 z2 = pk2(0.f, 0.f);
#pragma unroll
    for (int i = 0; i < 8; i++)
#pragma unroll
        for (int j = 0; j < 4; j++) acc2[i][j] = z2;

    for (int k0 = 0; k0 < K; k0 += 16) {
#pragma unroll
        for (int i = 0; i < 2; i++) {
            int f = tid + i * 256;
            int row = f >> 2;
            int kq = (f & 3) * 4;
            float4 v = *reinterpret_cast<const float4*>(&A[(long)(m0 + row) * K + k0 + kq]);
            As[kq + 0][row] = v.x;
            As[kq + 1][row] = v.y;
            As[kq + 2][row] = v.z;
            As[kq + 3][row] = v.w;
        }
#pragma unroll
        for (int i = 0; i < 2; i++) {
            int f = tid + i * 256;
            int kr = f >> 5;
            int n4 = (f & 31) * 4;
            float4 v = *reinterpret_cast<const float4*>(&Xb[(long)(k0 + kr) * N + n0 + n4]);
            *reinterpret_cast<float4*>(&Bs[kr][n4]) = v;
        }
        __syncthreads();

#pragma unroll
        for (int kk = 0; kk < 16; kk++) {
            float a[8];
            float4 b0 = *reinterpret_cast<const float4*>(&Bs[kk][tx * 8]);
            float4 b1 = *reinterpret_cast<const float4*>(&Bs[kk][tx * 8 + 4]);
            *reinterpret_cast<float4*>(&a[0]) = *reinterpret_cast<const float4*>(&As[kk][ty * 8]);
            *reinterpret_cast<float4*>(&a[4]) = *reinterpret_cast<const float4*>(&As[kk][ty * 8 + 4]);
            u64 b2[4];
            b2[0] = pk2(b0.x, b0.y);
            b2[1] = pk2(b0.z, b0.w);
            b2[2] = pk2(b1.x, b1.y);
            b2[3] = pk2(b1.z, b1.w);
#pragma unroll
            for (int i = 0; i < 8; i++) {
                u64 ad = dup2(a[i]);
#pragma unroll
                for (int j = 0; j < 4; j++)
                    acc2[i][j] = fma2(ad, b2[j], acc2[i][j]);
            }
        }
        __syncthreads();
    }

#pragma unroll
    for (int i = 0; i < 8; i++) {
        int m = m0 + ty * 8 + i;
        float s = scale[m], bb = bias[m];
        float r[8];
        upk2(acc2[i][0], r[0], r[1]);
        upk2(acc2[i][1], r[2], r[3]);
        upk2(acc2[i][2], r[4], r[5]);
        upk2(acc2[i][3], r[6], r[7]);
        float4 o0, o1;
        o0.x = r[0] * s + bb; o0.y = r[1] * s + bb;
        o0.z = r[2] * s + bb; o0.w = r[3] * s + bb;
        o1.x = r[4] * s + bb; o1.y = r[5] * s + bb;
        o1.z = r[6] * s + bb; o1.w = r[7] * s + bb;
        *reinterpret_cast<float4*>(&Yb[(long)m * N + n0 + tx * 8]) = o0;
        *reinterpret_cast<float4*>(&Yb[(long)m * N + n0 + tx * 8 + 4]) = o1;
    }
}

// ---------------------------------------------------------------------------
// Flash attention: CTA = (b, h, 128-query tile). Key tiles of 64, double-
// buffered. Shuffle softmax. Packed f32x2 QK and PV.
// 256 threads: (ty -> 8 query rows, tx -> 4 key/d cols).
// smem: sQ[32][132] | sK[2][32][68] | sVt[2][64][68] | sP[128][68]
// ---------------------------------------------------------------------------
#define KT 64
#define ATT_SQ   (32 * 132)
#define ATT_SK   (2 * 32 * 68)
#define ATT_SVT  (2 * 64 * 68)
#define ATT_SP   (128 * 68)
#define ATT_SMEM_FLOATS (ATT_SQ + ATT_SK + ATT_SVT + ATT_SP)

__global__ __launch_bounds__(256, 2)
void attn_kernel(const float* __restrict__ qkv, float* __restrict__ outm)
{
    extern __shared__ float sm[];
    float* sQ  = sm;                       // [32][132]
    float* sK  = sQ + ATT_SQ;              // [2][32][68]
    float* sVt = sK + ATT_SK;              // [2][64][68]
    float* sP  = sVt + ATT_SVT;            // [128][68]; reused as sOut[128][65]

    const int tid = threadIdx.x;
    const int tx = tid & 15, ty = tid >> 4;
    const int qt = blockIdx.x;
    const int h  = blockIdx.y;
    const int b  = blockIdx.z;

    const float* base = qkv + ((long)b * CQKV + h * 128) * LPIX;
    const float* qg = base;
    const float* kg = base + 32 * LPIX;
    const float* vg = base + 64 * LPIX;

    // Load Q tile [32 d][128 i], pre-scaled
#pragma unroll
    for (int i = 0; i < 4; i++) {
        int f = tid + i * 256;
        int d = f >> 5;
        int j4 = (f & 31) * 4;
        float4 v = *reinterpret_cast<const float4*>(&qg[(long)d * LPIX + qt * 128 + j4]);
        v.x *= SCALE; v.y *= SCALE; v.z *= SCALE; v.w *= SCALE;
        *reinterpret_cast<float4*>(&sQ[d * 132 + j4]) = v;
    }

    u64 O2[8][2];
    float m_run[8], l_run[8];
    const u64 z2 = pk2(0.f, 0.f);
#pragma unroll
    for (int r = 0; r < 8; r++) {
        m_run[r] = -INFINITY; l_run[r] = 0.f;
        O2[r][0] = z2; O2[r][1] = z2;
    }

    // Preload first K/V tile into buffer 0
    {
        float* sKb = sK;
        float* sVb = sVt;
#pragma unroll
        for (int i = 0; i < 2; i++) {
            int f = tid + i * 256;
            int d = f >> 4;
            int j4 = (f & 15) * 4;
            float4 v = *reinterpret_cast<const float4*>(&kg[(long)d * LPIX + j4]);
            *reinterpret_cast<float4*>(&sKb[d * 68 + j4]) = v;
        }
#pragma unroll
        for (int i = 0; i < 4; i++) {
            int f = tid + i * 256;
            int d = f >> 4;
            int j4 = (f & 15) * 4;
            float4 v = *reinterpret_cast<const float4*>(&vg[(long)d * LPIX + j4]);
            sVb[(j4 + 0) * 68 + d] = v.x;
            sVb[(j4 + 1) * 68 + d] = v.y;
            sVb[(j4 + 2) * 68 + d] = v.z;
            sVb[(j4 + 3) * 68 + d] = v.w;
        }
    }
    __syncthreads();

    for (int kt = 0; kt < 16; kt++) {
        const int buf = kt & 1;
        float* sKb = sK + buf * (32 * 68);
        float* sVb = sVt + buf * (64 * 68);

        // Prefetch next tile into the other buffer.
        if (kt + 1 < 16) {
            float* sKn = sK + (1 - buf) * (32 * 68);
            float* sVn = sVt + (1 - buf) * (64 * 68);
            const int koff = (kt + 1) * KT;
#pragma unroll
            for (int i = 0; i < 2; i++) {
                int f = tid + i * 256;
                int d = f >> 4;
                int j4 = (f & 15) * 4;
                float4 v = *reinterpret_cast<const float4*>(&kg[(long)d * LPIX + koff + j4]);
                *reinterpret_cast<float4*>(&sKn[d * 68 + j4]) = v;
            }
#pragma unroll
            for (int i = 0; i < 4; i++) {
                int f = tid + i * 256;
                int d = f >> 4;
                int j4 = (f & 15) * 4;
                float4 v = *reinterpret_cast<const float4*>(&vg[(long)d * LPIX + koff + j4]);
                sVn[(j4 + 0) * 68 + d] = v.x;
                sVn[(j4 + 1) * 68 + d] = v.y;
                sVn[(j4 + 2) * 68 + d] = v.z;
                sVn[(j4 + 3) * 68 + d] = v.w;
            }
        }

        // S = Q^T K : packed pairs along key cols; 8 rows x 2 pair-cols
        u64 s2[8][2];
#pragma unroll
        for (int r = 0; r < 8; r++) { s2[r][0] = z2; s2[r][1] = z2; }
#pragma unroll
        for (int kk = 0; kk < 32; kk++) {
            float a[8];
            float4 bb = *reinterpret_cast<const float4*>(&sKb[kk * 68 + tx * 4]);
            *reinterpret_cast<float4*>(&a[0]) = *reinterpret_cast<const float4*>(&sQ[kk * 132 + ty * 8]);
            *reinterpret_cast<float4*>(&a[4]) = *reinterpret_cast<const float4*>(&sQ[kk * 132 + ty * 8 + 4]);
            u64 b20 = pk2(bb.x, bb.y);
            u64 b21 = pk2(bb.z, bb.w);
#pragma unroll
            for (int r = 0; r < 8; r++) {
                u64 ad = dup2(a[r]);
                s2[r][0] = fma2(ad, b20, s2[r][0]);
                s2[r][1] = fma2(ad, b21, s2[r][1]);
            }
        }

        // Online softmax with shuffle reductions (16-lane groups share rows)
        float psum[8];
#pragma unroll
        for (int r = 0; r < 8; r++) {
            float s0, s1, s2f, s3;
            upk2(s2[r][0], s0, s1);
            upk2(s2[r][1], s2f, s3);
            float pm = fmaxf(fmaxf(s0, s1), fmaxf(s2f, s3));
#pragma unroll
            for (int off = 1; off < 16; off <<= 1)
                pm = fmaxf(pm, __shfl_xor_sync(0xffffffffu, pm, off, 16));
            float mnew = fmaxf(m_run[r], pm);
            float corr = __expf(m_run[r] - mnew);
            m_run[r] = mnew;
            u64 cd = dup2(corr);
            O2[r][0] = mul2(O2[r][0], cd);
            O2[r][1] = mul2(O2[r][1], cd);
            float4 p;
            p.x = __expf(s0 - mnew);
            p.y = __expf(s1 - mnew);
            p.z = __expf(s2f - mnew);
            p.w = __expf(s3 - mnew);
            *reinterpret_cast<float4*>(&sP[(ty * 8 + r) * 68 + tx * 4]) = p;
            psum[r] = (p.x + p.y) + (p.z + p.w);
            l_run[r] *= corr;
        }
#pragma unroll
        for (int r = 0; r < 8; r++) {
            float ps = psum[r];
#pragma unroll
            for (int off = 1; off < 16; off <<= 1)
                ps += __shfl_xor_sync(0xffffffffu, ps, off, 16);
            l_run[r] += ps;
        }
        __syncthreads();   // sP visible to all

        // O += P @ V, packed pairs along d
#pragma unroll 4
        for (int j = 0; j < KT; j += 4) {
            float4 v0 = *reinterpret_cast<const float4*>(&sVb[(j + 0) * 68 + tx * 4]);
            float4 v1 = *reinterpret_cast<const float4*>(&sVb[(j + 1) * 68 + tx * 4]);
            float4 v2 = *reinterpret_cast<const float4*>(&sVb[(j + 2) * 68 + tx * 4]);
            float4 v3 = *reinterpret_cast<const float4*>(&sVb[(j + 3) * 68 + tx * 4]);
            u64 v20a = pk2(v0.x, v0.y), v20b = pk2(v0.z, v0.w);
            u64 v21a = pk2(v1.x, v1.y), v21b = pk2(v1.z, v1.w);
            u64 v22a = pk2(v2.x, v2.y), v22b = pk2(v2.z, v2.w);
            u64 v23a = pk2(v3.x, v3.y), v23b = pk2(v3.z, v3.w);
#pragma unroll
            for (int r = 0; r < 8; r++) {
                float4 p = *reinterpret_cast<const float4*>(&sP[(ty * 8 + r) * 68 + j]);
                u64 pd;
                pd = dup2(p.x);
                O2[r][0] = fma2(pd, v20a, O2[r][0]);
                O2[r][1] = fma2(pd, v20b, O2[r][1]);
                pd = dup2(p.y);
                O2[r][0] = fma2(pd, v21a, O2[r][0]);
                O2[r][1] = fma2(pd, v21b, O2[r][1]);
                pd = dup2(p.z);
                O2[r][0] = fma2(pd, v22a, O2[r][0]);
                O2[r][1] = fma2(pd, v22b, O2[r][1]);
                pd = dup2(p.w);
                O2[r][0] = fma2(pd, v23a, O2[r][0]);
                O2[r][1] = fma2(pd, v23b, O2[r][1]);
            }
        }
        __syncthreads();   // done with sP and sKb/sVb
    }

    // Stage normalized O into smem [i][65], then coalesced channel-major write.
    float* sOut = sP;
#pragma unroll
    for (int r = 0; r < 8; r++) {
        float inv = 1.f / l_run[r];
        float o0, o1, o2, o3;
        upk2(O2[r][0], o0, o1);
        upk2(O2[r][1], o2, o3);
        sOut[(ty * 8 + r) * 65 + tx * 4 + 0] = o0 * inv;
        sOut[(ty * 8 + r) * 65 + tx * 4 + 1] = o1 * inv;
        sOut[(ty * 8 + r) * 65 + tx * 4 + 2] = o2 * inv;
        sOut[(ty * 8 + r) * 65 + tx * 4 + 3] = o3 * inv;
    }
    __syncthreads();

    float* op = outm + ((long)b * CH + h * 64) * LPIX + qt * 128;
#pragma unroll
    for (int it = 0; it < 32; it++) {
        int f = tid + it * 256;
        int d = f >> 7;
        int i = f & 127;
        op[(long)d * LPIX + i] = sOut[i * 65 + d];
    }
}

// ---------------------------------------------------------------------------
// Depthwise 3x3 conv (+BN), accumulated into g_mid.
// ---------------------------------------------------------------------------
__global__ __launch_bounds__(1024)
void dw_kernel(const float* __restrict__ qkv, const float* __restrict__ w,
               const float* __restrict__ s, const float* __restrict__ bb,
               float* __restrict__ outm)
{
    const int c = blockIdx.x & 255;
    const int b = blockIdx.x >> 8;
    const int t = threadIdx.x;
    const int y = t >> 5, x = t & 31;
    const int h = c >> 6, d = c & 63;
    const float* vp = qkv + ((long)b * CQKV + h * 128 + 64 + d) * LPIX;

    __shared__ float tile[34][34];
    tile[y + 1][x + 1] = vp[t];
    if (t < 34) {
        tile[0][t] = 0.f; tile[33][t] = 0.f;
        tile[t][0] = 0.f; tile[t][33] = 0.f;
    }
    __syncthreads();

    float acc = 0.f;
#pragma unroll
    for (int ky = 0; ky < 3; ky++)
#pragma unroll
        for (int kx = 0; kx < 3; kx++)
            acc = fmaf(tile[y + ky][x + kx], w[c * 9 + ky * 3 + kx], acc);

    outm[((long)b * CH + c) * LPIX + t] += acc * s[c] + bb[c];
}

// ---------------------------------------------------------------------------
extern "C" void kernel_launch(void* const* d_in, const int* in_sizes, int n_in,
                              void* d_out, int out_size)
{
    const float* x     = (const float*)d_in[0];
    const float* w_qkv = (const float*)d_in[1];
    const float* s_qkv = (const float*)d_in[2];
    const float* b_qkv = (const float*)d_in[3];
    const float* w_dw  = (const float*)d_in[4];
    const float* s_dw  = (const float*)d_in[5];
    const float* b_dw  = (const float*)d_in[6];
    const float* w_pw  = (const float*)d_in[7];
    const float* s_pw  = (const float*)d_in[8];
    const float* b_pw  = (const float*)d_in[9];
    float* out = (float*)d_out;

    float *qkvbuf = nullptr, *midbuf = nullptr;
    cudaGetSymbolAddress((void**)&qkvbuf, g_qkv);
    cudaGetSymbolAddress((void**)&midbuf, g_mid);

    const int att_smem = ATT_SMEM_FLOATS * (int)sizeof(float);
    cudaFuncSetAttribute(attn_kernel, cudaFuncAttributeMaxDynamicSharedMemorySize, att_smem);

    // 1) qkv = bn(W_qkv @ x)
    gemm_bn<<<dim3(8, 4, 16), 256>>>(w_qkv, x, qkvbuf, s_qkv, b_qkv, CQKV, LPIX, CH);
    // 2) attention -> g_mid
    attn_kernel<<<dim3(8, 4, 16), 256, att_smem>>>(qkvbuf, midbuf);
    // 3) g_mid += bn(dwconv3(v))
    dw_kernel<<<dim3(BATCH * CH), 1024>>>(qkvbuf, w_dw, s_dw, b_dw, midbuf);
    // 4) out = bn(W_pw @ g_mid)
    gemm_bn<<<dim3(8, 2, 16), 256>>>(w_pw, midbuf, out, s_pw, b_pw, CH, LPIX, CH);
}

// round 7
// speedup vs baseline: 1.4280x; 1.1662x over previous
#include <cuda_runtime.h>
#include <cuda_bf16.h>
#include <math.h>

// Problem constants
#define BATCH 16
#define CH    256
#define NH    4
#define DH    64
#define LPIX  1024
#define CQKV  512
#define SCALE 0.17677669529663687f   // 32^-0.5

typedef unsigned long long u64;

// ---------------- packed f32x2 helpers (used by attention) ----------------
__device__ __forceinline__ u64 pk2(float lo, float hi) {
    u64 r; asm("mov.b64 %0, {%1, %2};" : "=l"(r) : "f"(lo), "f"(hi)); return r;
}
__device__ __forceinline__ u64 dup2(float v) {
    u64 r; asm("mov.b64 %0, {%1, %1};" : "=l"(r) : "f"(v)); return r;
}
__device__ __forceinline__ u64 fma2(u64 a, u64 b, u64 c) {
    u64 d; asm("fma.rn.f32x2 %0, %1, %2, %3;" : "=l"(d) : "l"(a), "l"(b), "l"(c)); return d;
}
__device__ __forceinline__ u64 mul2(u64 a, u64 b) {
    u64 d; asm("mul.rn.f32x2 %0, %1, %2;" : "=l"(d) : "l"(a), "l"(b)); return d;
}
__device__ __forceinline__ void upk2(u64 v, float& lo, float& hi) {
    asm("mov.b64 {%0, %1}, %2;" : "=f"(lo), "=f"(hi) : "l"(v));
}

__device__ __forceinline__ unsigned smem_u32(const void* p) {
    unsigned r;
    asm("{ .reg .u64 t; cvta.to.shared.u64 t, %1; cvt.u32.u64 %0, t; }" : "=r"(r) : "l"(p));
    return r;
}

// ---------------- mma.sync helpers (baseline sm_100 HMMA path) ----------------
__device__ __forceinline__ void ldm_x4(unsigned* r, unsigned addr) {
    asm volatile("ldmatrix.sync.aligned.m8n8.x4.shared.b16 {%0,%1,%2,%3}, [%4];"
                 : "=r"(r[0]), "=r"(r[1]), "=r"(r[2]), "=r"(r[3]) : "r"(addr));
}
__device__ __forceinline__ void mma_bf16(float* c, const unsigned* a, unsigned b0, unsigned b1) {
    asm volatile(
        "mma.sync.aligned.m16n8k16.row.col.f32.bf16.bf16.f32 "
        "{%0,%1,%2,%3}, {%4,%5,%6,%7}, {%8,%9}, {%0,%1,%2,%3};"
        : "+f"(c[0]), "+f"(c[1]), "+f"(c[2]), "+f"(c[3])
        : "r"(a[0]), "r"(a[1]), "r"(a[2]), "r"(a[3]), "r"(b0), "r"(b1));
}

// ---------------- scratch (allocation-free: __device__ globals) ----------------
__device__ float g_qkv[(long)BATCH * CQKV * LPIX];   // [b][o][l]
__device__ float g_mid[(long)BATCH * CH * LPIX];     // [b][c][l]
__device__ __nv_bfloat16 g_wqh[CQKV * CH], g_wql[CQKV * CH];
__device__ __nv_bfloat16 g_wph[CH * CH],   g_wpl[CH * CH];
__device__ __nv_bfloat16 g_xth[(long)BATCH * LPIX * CH], g_xtl[(long)BATCH * LPIX * CH];
__device__ __nv_bfloat16 g_mth[(long)BATCH * LPIX * CH], g_mtl[(long)BATCH * LPIX * CH];

// ---------------------------------------------------------------------------
// Split fp32 -> bf16 hi/lo (elementwise, weights; layout preserved)
// ---------------------------------------------------------------------------
__global__ void split_w_kernel(const float* __restrict__ w,
                               __nv_bfloat16* __restrict__ h,
                               __nv_bfloat16* __restrict__ l, int n)
{
    int i = blockIdx.x * 256 + threadIdx.x;
    if (i < n) {
        float v = w[i];
        __nv_bfloat16 hh = __float2bfloat16(v);
        h[i] = hh;
        l[i] = __float2bfloat16(v - __bfloat162float(hh));
    }
}

// ---------------------------------------------------------------------------
// Transpose + split: X[b][k][n] fp32 -> T[b][n][k] bf16 hi/lo. 64x64 tiles.
// ---------------------------------------------------------------------------
__global__ __launch_bounds__(256)
void split_t_kernel(const float* __restrict__ X,
                    __nv_bfloat16* __restrict__ Th,
                    __nv_bfloat16* __restrict__ Tl, int K, int N)
{
    __shared__ float t[64][65];
    const int n0 = blockIdx.x * 64;
    const int k0 = blockIdx.y * 64;
    const long b = blockIdx.z;
    const float* Xb = X + b * (long)K * N;
    __nv_bfloat16* ThB = Th + b * (long)K * N;
    __nv_bfloat16* TlB = Tl + b * (long)K * N;
    const int tx = threadIdx.x & 63, ty = threadIdx.x >> 6;

#pragma unroll
    for (int i = 0; i < 16; i++)
        t[ty + i * 4][tx] = Xb[(long)(k0 + ty + i * 4) * N + n0 + tx];
    __syncthreads();

#pragma unroll
    for (int i = 0; i < 16; i++) {
        int n = ty + i * 4;
        float v = t[tx][n];
        __nv_bfloat16 hh = __float2bfloat16(v);
        ThB[(long)(n0 + n) * K + k0 + tx] = hh;
        TlB[(long)(n0 + n) * K + k0 + tx] = __float2bfloat16(v - __bfloat162float(hh));
    }
}

// ---------------------------------------------------------------------------
// HMMA bf16-split GEMM + BN: Y[b][m][n] = (sum_k A[m][k]*Bt[b][n][k])*s[m]+bias[m]
// A row-major [m][k] (hi/lo), Bt [n][k] (= col-major KxN, hi/lo).
// CTA 128x128, 8 warps: wm=wid&3 (m, 32 each), wn=wid>>2 (n, 64 each).
// Warp tile 32x64 = 2 (m16) x 8 (n8) mma tiles. K chunks of 64 in smem.
// 3-term split: AhBh + AhBl + AlBh, fp32 accumulate. K must be multiple of 64.
// ---------------------------------------------------------------------------
#define HT_PAD 72                         // bf16 row stride (64 + 8 pad)
#define HT_ASZ (128 * HT_PAD)             // elems per operand tile
#define HT_SMEM (4 * HT_ASZ * 2)          // bytes (73728)

__global__ __launch_bounds__(256, 2)
void hmma_gemm_bn(const __nv_bfloat16* __restrict__ Ah, const __nv_bfloat16* __restrict__ Al,
                  const __nv_bfloat16* __restrict__ Bh, const __nv_bfloat16* __restrict__ Bl,
                  float* __restrict__ Y, const float* __restrict__ scale,
                  const float* __restrict__ bias, int M, int N, int K)
{
    extern __shared__ __nv_bfloat16 hs[];
    __nv_bfloat16* sAh = hs;
    __nv_bfloat16* sAl = hs + HT_ASZ;
    __nv_bfloat16* sBh = hs + 2 * HT_ASZ;
    __nv_bfloat16* sBl = hs + 3 * HT_ASZ;

    const int tid = threadIdx.x;
    const int wid = tid >> 5, lane = tid & 31;
    const int wm = wid & 3, wn = wid >> 2;
    const int n0 = blockIdx.x * 128;
    const int m0 = blockIdx.y * 128;
    const long bz = blockIdx.z;
    const __nv_bfloat16* Bhb = Bh + bz * (long)N * K;
    const __nv_bfloat16* Blb = Bl + bz * (long)N * K;
    float* Yb = Y + bz * (long)M * N;

    float acc[2][8][4];
#pragma unroll
    for (int mi = 0; mi < 2; mi++)
#pragma unroll
        for (int ni = 0; ni < 8; ni++)
#pragma unroll
            for (int j = 0; j < 4; j++) acc[mi][ni][j] = 0.f;

    // Per-warp ldmatrix base addresses (byte, shared space)
    const unsigned aRow = (unsigned)(wm * 32 + (lane & 15));
    const unsigned bRow = (unsigned)(wn * 64 + (lane & 15));
    const unsigned kHalf = (unsigned)((lane >> 4) * 8);
    const unsigned aOffE = aRow * HT_PAD + kHalf;          // elems
    const unsigned sAh32 = smem_u32(sAh), sAl32 = smem_u32(sAl);
    const unsigned sBh32 = smem_u32(sBh), sBl32 = smem_u32(sBl);

    for (int kc = 0; kc < K; kc += 64) {
        // Load 4 operand tiles (128 rows x 64 bf16 each), coalesced 16B
#pragma unroll
        for (int i = 0; i < 4; i++) {
            int f = tid + i * 256;
            int r = f >> 3, c8 = (f & 7) * 8;
            long aoff = (long)(m0 + r) * K + kc + c8;
            long boff = (long)(n0 + r) * K + kc + c8;
            *reinterpret_cast<uint4*>(&sAh[r * HT_PAD + c8]) = *reinterpret_cast<const uint4*>(Ah + aoff);
            *reinterpret_cast<uint4*>(&sAl[r * HT_PAD + c8]) = *reinterpret_cast<const uint4*>(Al + aoff);
            *reinterpret_cast<uint4*>(&sBh[r * HT_PAD + c8]) = *reinterpret_cast<const uint4*>(Bhb + boff);
            *reinterpret_cast<uint4*>(&sBl[r * HT_PAD + c8]) = *reinterpret_cast<const uint4*>(Blb + boff);
        }
        __syncthreads();

#pragma unroll
        for (int k16 = 0; k16 < 64; k16 += 16) {
            unsigned ah[2][4], al[2][4];
#pragma unroll
            for (int mi = 0; mi < 2; mi++) {
                unsigned eo = (aOffE + mi * 16 * HT_PAD + k16) * 2;
                ldm_x4(ah[mi], sAh32 + eo);
                ldm_x4(al[mi], sAl32 + eo);
            }
            unsigned bh[8][2], bl[8][2];
#pragma unroll
            for (int np = 0; np < 4; np++) {
                unsigned eo = ((bRow + np * 16) * HT_PAD + kHalf + k16) * 2;
                unsigned r4[4];
                ldm_x4(r4, sBh32 + eo);
                bh[np * 2][0] = r4[0]; bh[np * 2][1] = r4[2];
                bh[np * 2 + 1][0] = r4[1]; bh[np * 2 + 1][1] = r4[3];
                ldm_x4(r4, sBl32 + eo);
                bl[np * 2][0] = r4[0]; bl[np * 2][1] = r4[2];
                bl[np * 2 + 1][0] = r4[1]; bl[np * 2 + 1][1] = r4[3];
            }
#pragma unroll
            for (int mi = 0; mi < 2; mi++)
#pragma unroll
                for (int ni = 0; ni < 8; ni++) {
                    mma_bf16(acc[mi][ni], ah[mi], bh[ni][0], bh[ni][1]);
                    mma_bf16(acc[mi][ni], ah[mi], bl[ni][0], bl[ni][1]);
                    mma_bf16(acc[mi][ni], al[mi], bh[ni][0], bh[ni][1]);
                }
        }
        __syncthreads();
    }

    // Epilogue: BN + store. acc[mi][ni]: rows m0+wm*32+mi*16+{lane>>2, +8},
    // cols n0+wn*64+ni*8+(lane&3)*2 (+1).
#pragma unroll
    for (int mi = 0; mi < 2; mi++) {
        int r1 = m0 + wm * 32 + mi * 16 + (lane >> 2);
        int r2 = r1 + 8;
        float s1 = scale[r1], b1 = bias[r1];
        float s2 = scale[r2], b2 = bias[r2];
        float* y1 = &Yb[(long)r1 * N + n0 + wn * 64 + (lane & 3) * 2];
        float* y2 = &Yb[(long)r2 * N + n0 + wn * 64 + (lane & 3) * 2];
#pragma unroll
        for (int ni = 0; ni < 8; ni++) {
            float2 o1, o2;
            o1.x = acc[mi][ni][0] * s1 + b1;
            o1.y = acc[mi][ni][1] * s1 + b1;
            o2.x = acc[mi][ni][2] * s2 + b2;
            o2.y = acc[mi][ni][3] * s2 + b2;
            *reinterpret_cast<float2*>(y1 + ni * 8) = o1;
            *reinterpret_cast<float2*>(y2 + ni * 8) = o2;
        }
    }
}

// ---------------------------------------------------------------------------
// Flash attention (unchanged from best-passing round).
// ---------------------------------------------------------------------------
#define KT 64
#define ATT_SQ   (32 * 132)
#define ATT_SK   (2 * 32 * 68)
#define ATT_SVT  (2 * 64 * 68)
#define ATT_SP   (128 * 68)
#define ATT_SMEM_FLOATS (ATT_SQ + ATT_SK + ATT_SVT + ATT_SP)

__global__ __launch_bounds__(256, 2)
void attn_kernel(const float* __restrict__ qkv, float* __restrict__ outm)
{
    extern __shared__ float sm[];
    float* sQ  = sm;
    float* sK  = sQ + ATT_SQ;
    float* sVt = sK + ATT_SK;
    float* sP  = sVt + ATT_SVT;

    const int tid = threadIdx.x;
    const int tx = tid & 15, ty = tid >> 4;
    const int qt = blockIdx.x;
    const int h  = blockIdx.y;
    const int b  = blockIdx.z;

    const float* base = qkv + ((long)b * CQKV + h * 128) * LPIX;
    const float* qg = base;
    const float* kg = base + 32 * LPIX;
    const float* vg = base + 64 * LPIX;

#pragma unroll
    for (int i = 0; i < 4; i++) {
        int f = tid + i * 256;
        int d = f >> 5;
        int j4 = (f & 31) * 4;
        float4 v = *reinterpret_cast<const float4*>(&qg[(long)d * LPIX + qt * 128 + j4]);
        v.x *= SCALE; v.y *= SCALE; v.z *= SCALE; v.w *= SCALE;
        *reinterpret_cast<float4*>(&sQ[d * 132 + j4]) = v;
    }

    u64 O2[8][2];
    float m_run[8], l_run[8];
    const u64 z2 = pk2(0.f, 0.f);
#pragma unroll
    for (int r = 0; r < 8; r++) {
        m_run[r] = -INFINITY; l_run[r] = 0.f;
        O2[r][0] = z2; O2[r][1] = z2;
    }

    {
        float* sKb = sK;
        float* sVb = sVt;
#pragma unroll
        for (int i = 0; i < 2; i++) {
            int f = tid + i * 256;
            int d = f >> 4;
            int j4 = (f & 15) * 4;
            float4 v = *reinterpret_cast<const float4*>(&kg[(long)d * LPIX + j4]);
            *reinterpret_cast<float4*>(&sKb[d * 68 + j4]) = v;
        }
#pragma unroll
        for (int i = 0; i < 4; i++) {
            int f = tid + i * 256;
            int d = f >> 4;
            int j4 = (f & 15) * 4;
            float4 v = *reinterpret_cast<const float4*>(&vg[(long)d * LPIX + j4]);
            sVb[(j4 + 0) * 68 + d] = v.x;
            sVb[(j4 + 1) * 68 + d] = v.y;
            sVb[(j4 + 2) * 68 + d] = v.z;
            sVb[(j4 + 3) * 68 + d] = v.w;
        }
    }
    __syncthreads();

    for (int kt = 0; kt < 16; kt++) {
        const int buf = kt & 1;
        float* sKb = sK + buf * (32 * 68);
        float* sVb = sVt + buf * (64 * 68);

        if (kt + 1 < 16) {
            float* sKn = sK + (1 - buf) * (32 * 68);
            float* sVn = sVt + (1 - buf) * (64 * 68);
            const int koff = (kt + 1) * KT;
#pragma unroll
            for (int i = 0; i < 2; i++) {
                int f = tid + i * 256;
                int d = f >> 4;
                int j4 = (f & 15) * 4;
                float4 v = *reinterpret_cast<const float4*>(&kg[(long)d * LPIX + koff + j4]);
                *reinterpret_cast<float4*>(&sKn[d * 68 + j4]) = v;
            }
#pragma unroll
            for (int i = 0; i < 4; i++) {
                int f = tid + i * 256;
                int d = f >> 4;
                int j4 = (f & 15) * 4;
                float4 v = *reinterpret_cast<const float4*>(&vg[(long)d * LPIX + koff + j4]);
                sVn[(j4 + 0) * 68 + d] = v.x;
                sVn[(j4 + 1) * 68 + d] = v.y;
                sVn[(j4 + 2) * 68 + d] = v.z;
                sVn[(j4 + 3) * 68 + d] = v.w;
            }
        }

        u64 s2[8][2];
#pragma unroll
        for (int r = 0; r < 8; r++) { s2[r][0] = z2; s2[r][1] = z2; }
#pragma unroll
        for (int kk = 0; kk < 32; kk++) {
            float a[8];
            float4 bb = *reinterpret_cast<const float4*>(&sKb[kk * 68 + tx * 4]);
            *reinterpret_cast<float4*>(&a[0]) = *reinterpret_cast<const float4*>(&sQ[kk * 132 + ty * 8]);
            *reinterpret_cast<float4*>(&a[4]) = *reinterpret_cast<const float4*>(&sQ[kk * 132 + ty * 8 + 4]);
            u64 b20 = pk2(bb.x, bb.y);
            u64 b21 = pk2(bb.z, bb.w);
#pragma unroll
            for (int r = 0; r < 8; r++) {
                u64 ad = dup2(a[r]);
                s2[r][0] = fma2(ad, b20, s2[r][0]);
                s2[r][1] = fma2(ad, b21, s2[r][1]);
            }
        }

        float psum[8];
#pragma unroll
        for (int r = 0; r < 8; r++) {
            float s0, s1, s2f, s3;
            upk2(s2[r][0], s0, s1);
            upk2(s2[r][1], s2f, s3);
            float pm = fmaxf(fmaxf(s0, s1), fmaxf(s2f, s3));
#pragma unroll
            for (int off = 1; off < 16; off <<= 1)
                pm = fmaxf(pm, __shfl_xor_sync(0xffffffffu, pm, off, 16));
            float mnew = fmaxf(m_run[r], pm);
            float corr = __expf(m_run[r] - mnew);
            m_run[r] = mnew;
            u64 cd = dup2(corr);
            O2[r][0] = mul2(O2[r][0], cd);
            O2[r][1] = mul2(O2[r][1], cd);
            float4 p;
            p.x = __expf(s0 - mnew);
            p.y = __expf(s1 - mnew);
            p.z = __expf(s2f - mnew);
            p.w = __expf(s3 - mnew);
            *reinterpret_cast<float4*>(&sP[(ty * 8 + r) * 68 + tx * 4]) = p;
            psum[r] = (p.x + p.y) + (p.z + p.w);
            l_run[r] *= corr;
        }
#pragma unroll
        for (int r = 0; r < 8; r++) {
            float ps = psum[r];
#pragma unroll
            for (int off = 1; off < 16; off <<= 1)
                ps += __shfl_xor_sync(0xffffffffu, ps, off, 16);
            l_run[r] += ps;
        }
        __syncthreads();

#pragma unroll 4
        for (int j = 0; j < KT; j += 4) {
            float4 v0 = *reinterpret_cast<const float4*>(&sVb[(j + 0) * 68 + tx * 4]);
            float4 v1 = *reinterpret_cast<const float4*>(&sVb[(j + 1) * 68 + tx * 4]);
            float4 v2 = *reinterpret_cast<const float4*>(&sVb[(j + 2) * 68 + tx * 4]);
            float4 v3 = *reinterpret_cast<const float4*>(&sVb[(j + 3) * 68 + tx * 4]);
            u64 v20a = pk2(v0.x, v0.y), v20b = pk2(v0.z, v0.w);
            u64 v21a = pk2(v1.x, v1.y), v21b = pk2(v1.z, v1.w);
            u64 v22a = pk2(v2.x, v2.y), v22b = pk2(v2.z, v2.w);
            u64 v23a = pk2(v3.x, v3.y), v23b = pk2(v3.z, v3.w);
#pragma unroll
            for (int r = 0; r < 8; r++) {
                float4 p = *reinterpret_cast<const float4*>(&sP[(ty * 8 + r) * 68 + j]);
                u64 pd;
                pd = dup2(p.x);
                O2[r][0] = fma2(pd, v20a, O2[r][0]);
                O2[r][1] = fma2(pd, v20b, O2[r][1]);
                pd = dup2(p.y);
                O2[r][0] = fma2(pd, v21a, O2[r][0]);
                O2[r][1] = fma2(pd, v21b, O2[r][1]);
                pd = dup2(p.z);
                O2[r][0] = fma2(pd, v22a, O2[r][0]);
                O2[r][1] = fma2(pd, v22b, O2[r][1]);
                pd = dup2(p.w);
                O2[r][0] = fma2(pd, v23a, O2[r][0]);
                O2[r][1] = fma2(pd, v23b, O2[r][1]);
            }
        }
        __syncthreads();
    }

    float* sOut = sP;
#pragma unroll
    for (int r = 0; r < 8; r++) {
        float inv = 1.f / l_run[r];
        float o0, o1, o2, o3;
        upk2(O2[r][0], o0, o1);
        upk2(O2[r][1], o2, o3);
        sOut[(ty * 8 + r) * 65 + tx * 4 + 0] = o0 * inv;
        sOut[(ty * 8 + r) * 65 + tx * 4 + 1] = o1 * inv;
        sOut[(ty * 8 + r) * 65 + tx * 4 + 2] = o2 * inv;
        sOut[(ty * 8 + r) * 65 + tx * 4 + 3] = o3 * inv;
    }
    __syncthreads();

    float* op = outm + ((long)b * CH + h * 64) * LPIX + qt * 128;
#pragma unroll
    for (int it = 0; it < 32; it++) {
        int f = tid + it * 256;
        int d = f >> 7;
        int i = f & 127;
        op[(long)d * LPIX + i] = sOut[i * 65 + d];
    }
}

// ---------------------------------------------------------------------------
// Depthwise 3x3 conv (+BN), accumulated into g_mid.
// ---------------------------------------------------------------------------
__global__ __launch_bounds__(1024)
void dw_kernel(const float* __restrict__ qkv, const float* __restrict__ w,
               const float* __restrict__ s, const float* __restrict__ bb,
               float* __restrict__ outm)
{
    const int c = blockIdx.x & 255;
    const int b = blockIdx.x >> 8;
    const int t = threadIdx.x;
    const int y = t >> 5, x = t & 31;
    const int h = c >> 6, d = c & 63;
    const float* vp = qkv + ((long)b * CQKV + h * 128 + 64 + d) * LPIX;

    __shared__ float tile[34][34];
    tile[y + 1][x + 1] = vp[t];
    if (t < 34) {
        tile[0][t] = 0.f; tile[33][t] = 0.f;
        tile[t][0] = 0.f; tile[t][33] = 0.f;
    }
    __syncthreads();

    float acc = 0.f;
#pragma unroll
    for (int ky = 0; ky < 3; ky++)
#pragma unroll
        for (int kx = 0; kx < 3; kx++)
            acc = fmaf(tile[y + ky][x + kx], w[c * 9 + ky * 3 + kx], acc);

    outm[((long)b * CH + c) * LPIX + t] += acc * s[c] + bb[c];
}

// ---------------------------------------------------------------------------
extern "C" void kernel_launch(void* const* d_in, const int* in_sizes, int n_in,
                              void* d_out, int out_size)
{
    const float* x     = (const float*)d_in[0];
    const float* w_qkv = (const float*)d_in[1];
    const float* s_qkv = (const float*)d_in[2];
    const float* b_qkv = (const float*)d_in[3];
    const float* w_dw  = (const float*)d_in[4];
    const float* s_dw  = (const float*)d_in[5];
    const float* b_dw  = (const float*)d_in[6];
    const float* w_pw  = (const float*)d_in[7];
    const float* s_pw  = (const float*)d_in[8];
    const float* b_pw  = (const float*)d_in[9];
    float* out = (float*)d_out;

    float *qkvbuf = nullptr, *midbuf = nullptr;
    cudaGetSymbolAddress((void**)&qkvbuf, g_qkv);
    cudaGetSymbolAddress((void**)&midbuf, g_mid);
    __nv_bfloat16 *wqh, *wql, *wph, *wpl, *xth, *xtl, *mth, *mtl;
    cudaGetSymbolAddress((void**)&wqh, g_wqh);
    cudaGetSymbolAddress((void**)&wql, g_wql);
    cudaGetSymbolAddress((void**)&wph, g_wph);
    cudaGetSymbolAddress((void**)&wpl, g_wpl);
    cudaGetSymbolAddress((void**)&xth, g_xth);
    cudaGetSymbolAddress((void**)&xtl, g_xtl);
    cudaGetSymbolAddress((void**)&mth, g_mth);
    cudaGetSymbolAddress((void**)&mtl, g_mtl);

    const int att_smem = ATT_SMEM_FLOATS * (int)sizeof(float);
    cudaFuncSetAttribute(attn_kernel, cudaFuncAttributeMaxDynamicSharedMemorySize, att_smem);
    cudaFuncSetAttribute(hmma_gemm_bn, cudaFuncAttributeMaxDynamicSharedMemorySize, HT_SMEM);

    // Prep: split weights; transpose+split x
    split_w_kernel<<<(CQKV * CH + 255) / 256, 256>>>(w_qkv, wqh, wql, CQKV * CH);
    split_w_kernel<<<(CH * CH + 255) / 256, 256>>>(w_pw, wph, wpl, CH * CH);
    split_t_kernel<<<dim3(LPIX / 64, CH / 64, BATCH), 256>>>(x, xth, xtl, CH, LPIX);

    // 1) qkv = bn(W_qkv @ x)   [tensor cores via mma.sync]
    hmma_gemm_bn<<<dim3(8, 4, 16), 256, HT_SMEM>>>(wqh, wql, xth, xtl, qkvbuf,
                                                   s_qkv, b_qkv, CQKV, LPIX, CH);
    // 2) attention -> g_mid
    attn_kernel<<<dim3(8, 4, 16), 256, att_smem>>>(qkvbuf, midbuf);
    // 3) g_mid += bn(dwconv3(v))
    dw_kernel<<<dim3(BATCH * CH), 1024>>>(qkvbuf, w_dw, s_dw, b_dw, midbuf);
    // 4) transpose+split mid, then out = bn(W_pw @ g_mid)  [tensor cores]
    split_t_kernel<<<dim3(LPIX / 64, CH / 64, BATCH), 256>>>(midbuf, mth, mtl, CH, LPIX);
    hmma_gemm_bn<<<dim3(8, 2, 16), 256, HT_SMEM>>>(wph, wpl, mth, mtl, out,
                                                   s_pw, b_pw, CH, LPIX, CH);
}

// round 8
// speedup vs baseline: 2.1373x; 1.4966x over previous
#include <cuda_runtime.h>
#include <cuda_bf16.h>
#include <math.h>

// Problem constants
#define BATCH 16
#define CH    256
#define NH    4
#define DH    64
#define LPIX  1024
#define CQKV  512
#define SCALE 0.17677669529663687f   // 32^-0.5

typedef unsigned long long u64;

__device__ __forceinline__ unsigned smem_u32(const void* p) {
    unsigned r;
    asm("{ .reg .u64 t; cvta.to.shared.u64 t, %1; cvt.u32.u64 %0, t; }" : "=r"(r) : "l"(p));
    return r;
}

// ---------------- mma.sync helpers (baseline sm_100 HMMA path) ----------------
__device__ __forceinline__ void ldm_x4(unsigned* r, unsigned addr) {
    asm volatile("ldmatrix.sync.aligned.m8n8.x4.shared.b16 {%0,%1,%2,%3}, [%4];"
                 : "=r"(r[0]), "=r"(r[1]), "=r"(r[2]), "=r"(r[3]) : "r"(addr));
}
__device__ __forceinline__ void mma_bf16(float* c, const unsigned* a, unsigned b0, unsigned b1) {
    asm volatile(
        "mma.sync.aligned.m16n8k16.row.col.f32.bf16.bf16.f32 "
        "{%0,%1,%2,%3}, {%4,%5,%6,%7}, {%8,%9}, {%0,%1,%2,%3};"
        : "+f"(c[0]), "+f"(c[1]), "+f"(c[2]), "+f"(c[3])
        : "r"(a[0]), "r"(a[1]), "r"(a[2]), "r"(a[3]), "r"(b0), "r"(b1));
}
// pack two floats -> bf16x2 (lo = first arg)
__device__ __forceinline__ unsigned bfpack(float lo, float hi) {
    unsigned r;
    asm("cvt.rn.bf16x2.f32 %0, %1, %2;" : "=r"(r) : "f"(hi), "f"(lo));
    return r;
}

// ---------------- scratch (allocation-free: __device__ globals) ----------------
__device__ float g_qkv[(long)BATCH * CQKV * LPIX];   // [b][o][l]
__device__ float g_mid[(long)BATCH * CH * LPIX];     // [b][c][l]
__device__ __nv_bfloat16 g_wqh[CQKV * CH], g_wql[CQKV * CH];
__device__ __nv_bfloat16 g_wph[CH * CH],   g_wpl[CH * CH];
__device__ __nv_bfloat16 g_xth[(long)BATCH * LPIX * CH], g_xtl[(long)BATCH * LPIX * CH];
__device__ __nv_bfloat16 g_mth[(long)BATCH * LPIX * CH], g_mtl[(long)BATCH * LPIX * CH];

// ---------------------------------------------------------------------------
// Split fp32 -> bf16 hi/lo (elementwise; layout preserved)
// ---------------------------------------------------------------------------
__global__ void split_w_kernel(const float* __restrict__ w,
                               __nv_bfloat16* __restrict__ h,
                               __nv_bfloat16* __restrict__ l, int n)
{
    int i = blockIdx.x * 256 + threadIdx.x;
    if (i < n) {
        float v = w[i];
        __nv_bfloat16 hh = __float2bfloat16(v);
        h[i] = hh;
        l[i] = __float2bfloat16(v - __bfloat162float(hh));
    }
}

// ---------------------------------------------------------------------------
// Transpose + split: X[b][k][n] fp32 -> T[b][n][k] bf16 hi/lo. 64x64 tiles.
// ---------------------------------------------------------------------------
__global__ __launch_bounds__(256)
void split_t_kernel(const float* __restrict__ X,
                    __nv_bfloat16* __restrict__ Th,
                    __nv_bfloat16* __restrict__ Tl, int K, int N)
{
    __shared__ float t[64][65];
    const int n0 = blockIdx.x * 64;
    const int k0 = blockIdx.y * 64;
    const long b = blockIdx.z;
    const float* Xb = X + b * (long)K * N;
    __nv_bfloat16* ThB = Th + b * (long)K * N;
    __nv_bfloat16* TlB = Tl + b * (long)K * N;
    const int tx = threadIdx.x & 63, ty = threadIdx.x >> 6;

#pragma unroll
    for (int i = 0; i < 16; i++)
        t[ty + i * 4][tx] = Xb[(long)(k0 + ty + i * 4) * N + n0 + tx];
    __syncthreads();

#pragma unroll
    for (int i = 0; i < 16; i++) {
        int n = ty + i * 4;
        float v = t[tx][n];
        __nv_bfloat16 hh = __float2bfloat16(v);
        ThB[(long)(n0 + n) * K + k0 + tx] = hh;
        TlB[(long)(n0 + n) * K + k0 + tx] = __float2bfloat16(v - __bfloat162float(hh));
    }
}

// ---------------------------------------------------------------------------
// HMMA bf16-split GEMM + BN (unchanged from passing round).
// ---------------------------------------------------------------------------
#define HT_PAD 72
#define HT_ASZ (128 * HT_PAD)
#define HT_SMEM (4 * HT_ASZ * 2)

__global__ __launch_bounds__(256, 2)
void hmma_gemm_bn(const __nv_bfloat16* __restrict__ Ah, const __nv_bfloat16* __restrict__ Al,
                  const __nv_bfloat16* __restrict__ Bh, const __nv_bfloat16* __restrict__ Bl,
                  float* __restrict__ Y, const float* __restrict__ scale,
                  const float* __restrict__ bias, int M, int N, int K)
{
    extern __shared__ __nv_bfloat16 hs[];
    __nv_bfloat16* sAh = hs;
    __nv_bfloat16* sAl = hs + HT_ASZ;
    __nv_bfloat16* sBh = hs + 2 * HT_ASZ;
    __nv_bfloat16* sBl = hs + 3 * HT_ASZ;

    const int tid = threadIdx.x;
    const int wid = tid >> 5, lane = tid & 31;
    const int wm = wid & 3, wn = wid >> 2;
    const int n0 = blockIdx.x * 128;
    const int m0 = blockIdx.y * 128;
    const long bz = blockIdx.z;
    const __nv_bfloat16* Bhb = Bh + bz * (long)N * K;
    const __nv_bfloat16* Blb = Bl + bz * (long)N * K;
    float* Yb = Y + bz * (long)M * N;

    float acc[2][8][4];
#pragma unroll
    for (int mi = 0; mi < 2; mi++)
#pragma unroll
        for (int ni = 0; ni < 8; ni++)
#pragma unroll
            for (int j = 0; j < 4; j++) acc[mi][ni][j] = 0.f;

    const unsigned aRow = (unsigned)(wm * 32 + (lane & 15));
    const unsigned bRow = (unsigned)(wn * 64 + (lane & 15));
    const unsigned kHalf = (unsigned)((lane >> 4) * 8);
    const unsigned aOffE = aRow * HT_PAD + kHalf;
    const unsigned sAh32 = smem_u32(sAh), sAl32 = smem_u32(sAl);
    const unsigned sBh32 = smem_u32(sBh), sBl32 = smem_u32(sBl);

    for (int kc = 0; kc < K; kc += 64) {
#pragma unroll
        for (int i = 0; i < 4; i++) {
            int f = tid + i * 256;
            int r = f >> 3, c8 = (f & 7) * 8;
            long aoff = (long)(m0 + r) * K + kc + c8;
            long boff = (long)(n0 + r) * K + kc + c8;
            *reinterpret_cast<uint4*>(&sAh[r * HT_PAD + c8]) = *reinterpret_cast<const uint4*>(Ah + aoff);
            *reinterpret_cast<uint4*>(&sAl[r * HT_PAD + c8]) = *reinterpret_cast<const uint4*>(Al + aoff);
            *reinterpret_cast<uint4*>(&sBh[r * HT_PAD + c8]) = *reinterpret_cast<const uint4*>(Bhb + boff);
            *reinterpret_cast<uint4*>(&sBl[r * HT_PAD + c8]) = *reinterpret_cast<const uint4*>(Blb + boff);
        }
        __syncthreads();

#pragma unroll
        for (int k16 = 0; k16 < 64; k16 += 16) {
            unsigned ah[2][4], al[2][4];
#pragma unroll
            for (int mi = 0; mi < 2; mi++) {
                unsigned eo = (aOffE + mi * 16 * HT_PAD + k16) * 2;
                ldm_x4(ah[mi], sAh32 + eo);
                ldm_x4(al[mi], sAl32 + eo);
            }
            unsigned bh[8][2], bl[8][2];
#pragma unroll
            for (int np = 0; np < 4; np++) {
                unsigned eo = ((bRow + np * 16) * HT_PAD + kHalf + k16) * 2;
                unsigned r4[4];
                ldm_x4(r4, sBh32 + eo);
                bh[np * 2][0] = r4[0]; bh[np * 2][1] = r4[2];
                bh[np * 2 + 1][0] = r4[1]; bh[np * 2 + 1][1] = r4[3];
                ldm_x4(r4, sBl32 + eo);
                bl[np * 2][0] = r4[0]; bl[np * 2][1] = r4[2];
                bl[np * 2 + 1][0] = r4[1]; bl[np * 2 + 1][1] = r4[3];
            }
#pragma unroll
            for (int mi = 0; mi < 2; mi++)
#pragma unroll
                for (int ni = 0; ni < 8; ni++) {
                    mma_bf16(acc[mi][ni], ah[mi], bh[ni][0], bh[ni][1]);
                    mma_bf16(acc[mi][ni], ah[mi], bl[ni][0], bl[ni][1]);
                    mma_bf16(acc[mi][ni], al[mi], bh[ni][0], bh[ni][1]);
                }
        }
        __syncthreads();
    }

#pragma unroll
    for (int mi = 0; mi < 2; mi++) {
        int r1 = m0 + wm * 32 + mi * 16 + (lane >> 2);
        int r2 = r1 + 8;
        float s1 = scale[r1], b1 = bias[r1];
        float s2 = scale[r2], b2 = bias[r2];
        float* y1 = &Yb[(long)r1 * N + n0 + wn * 64 + (lane & 3) * 2];
        float* y2 = &Yb[(long)r2 * N + n0 + wn * 64 + (lane & 3) * 2];
#pragma unroll
        for (int ni = 0; ni < 8; ni++) {
            float2 o1, o2;
            o1.x = acc[mi][ni][0] * s1 + b1;
            o1.y = acc[mi][ni][1] * s1 + b1;
            o2.x = acc[mi][ni][2] * s2 + b2;
            o2.y = acc[mi][ni][3] * s2 + b2;
            *reinterpret_cast<float2*>(y1 + ni * 8) = o1;
            *reinterpret_cast<float2*>(y2 + ni * 8) = o2;
        }
    }
}

// ---------------------------------------------------------------------------
// HMMA flash attention. CTA = (qt, h, b): 128 queries, 8 warps x 16 rows.
// Key tiles of 128, double-buffered. S = QK^T and O += P.V on tensor cores,
// 3-term bf16 splits everywhere. Softmax fully register-resident.
// smem: Qh/Ql [128][40] | K bufs x2: Kh/Kl [128][40] | V bufs x2: Vh/Vl [64][136]
// ---------------------------------------------------------------------------
#define AT_SMEM 131072

__global__ __launch_bounds__(256, 1)
void attn_hmma(const float* __restrict__ qkv, float* __restrict__ outm)
{
    extern __shared__ char smraw[];
    __nv_bfloat16* sQh = (__nv_bfloat16*)(smraw);
    __nv_bfloat16* sQl = (__nv_bfloat16*)(smraw + 10240);

    const int tid = threadIdx.x;
    const int wid = tid >> 5, lane = tid & 31;
    const int qt = blockIdx.x, h = blockIdx.y, b = blockIdx.z;

    const float* base = qkv + ((long)b * CQKV + h * 128) * LPIX;
    const float* qg = base;
    const float* kg = base + 32 * LPIX;
    const float* vg = base + 64 * LPIX;

    // Q: [32 d][128 l] -> sQ[l][d] hi/lo, pre-scaled
#pragma unroll
    for (int i = 0; i < 16; i++) {
        int f = tid + i * 256;
        int d = f >> 7, l = f & 127;
        float v = qg[(long)d * LPIX + qt * 128 + l] * SCALE;
        __nv_bfloat16 hh = __float2bfloat16(v);
        sQh[l * 40 + d] = hh;
        sQl[l * 40 + d] = __float2bfloat16(v - __bfloat162float(hh));
    }

    auto load_kv = [&](int buf, int kt) {
        __nv_bfloat16* sKh = (__nv_bfloat16*)(smraw + 20480 + buf * 20480);
        __nv_bfloat16* sKl = sKh + 5120;
        __nv_bfloat16* sVh = (__nv_bfloat16*)(smraw + 61440 + buf * 34816);
        __nv_bfloat16* sVl = sVh + 8704;
#pragma unroll
        for (int i = 0; i < 16; i++) {
            int f = tid + i * 256;
            int d = f >> 7, l = f & 127;
            float v = kg[(long)d * LPIX + kt * 128 + l];
            __nv_bfloat16 hh = __float2bfloat16(v);
            sKh[l * 40 + d] = hh;
            sKl[l * 40 + d] = __float2bfloat16(v - __bfloat162float(hh));
        }
#pragma unroll
        for (int i = 0; i < 32; i++) {
            int f = tid + i * 256;
            int d = f >> 7, j = f & 127;
            float v = vg[(long)d * LPIX + kt * 128 + j];
            __nv_bfloat16 hh = __float2bfloat16(v);
            sVh[d * 136 + j] = hh;
            sVl[d * 136 + j] = __float2bfloat16(v - __bfloat162float(hh));
        }
    };

    float oacc[8][4];
#pragma unroll
    for (int n = 0; n < 8; n++)
#pragma unroll
        for (int j = 0; j < 4; j++) oacc[n][j] = 0.f;
    float m0 = -INFINITY, m1 = -INFINITY, l0 = 0.f, l1 = 0.f;

    const unsigned sQh32 = smem_u32(sQh);
    const unsigned sQl32 = sQh32 + 10240;
    const unsigned rowA = (unsigned)(wid * 16 + (lane & 15));
    const unsigned rowB = (unsigned)(lane & 15);
    const unsigned kHalf = (unsigned)((lane >> 4) * 8);

    load_kv(0, 0);
    __syncthreads();

    for (int kt = 0; kt < 8; kt++) {
        const int buf = kt & 1;
        if (kt + 1 < 8) load_kv(1 - buf, kt + 1);

        const unsigned sKh32 = smem_u32(smraw + 20480 + buf * 20480);
        const unsigned sKl32 = sKh32 + 10240;
        const unsigned sVh32 = smem_u32(smraw + 61440 + buf * 34816);
        const unsigned sVl32 = sVh32 + 17408;

        // ---- S = Q K^T (3-term split), 16 n8-tiles per warp ----
        float sacc[16][4];
#pragma unroll
        for (int n = 0; n < 16; n++)
#pragma unroll
            for (int j = 0; j < 4; j++) sacc[n][j] = 0.f;

#pragma unroll
        for (int t = 0; t < 2; t++) {
            unsigned ah[4], al[4];
            unsigned eo = (rowA * 40 + kHalf + 16 * t) * 2;
            ldm_x4(ah, sQh32 + eo);
            ldm_x4(al, sQl32 + eo);
#pragma unroll
            for (int np = 0; np < 8; np++) {
                unsigned eo2 = ((rowB + np * 16) * 40 + kHalf + 16 * t) * 2;
                unsigned r4[4], s4[4];
                ldm_x4(r4, sKh32 + eo2);
                ldm_x4(s4, sKl32 + eo2);
                mma_bf16(sacc[2 * np],     ah, r4[0], r4[2]);
                mma_bf16(sacc[2 * np],     ah, s4[0], s4[2]);
                mma_bf16(sacc[2 * np],     al, r4[0], r4[2]);
                mma_bf16(sacc[2 * np + 1], ah, r4[1], r4[3]);
                mma_bf16(sacc[2 * np + 1], ah, s4[1], s4[3]);
                mma_bf16(sacc[2 * np + 1], al, r4[1], r4[3]);
            }
        }

        // ---- online softmax (rows r = lane>>2 and r+8) ----
        float mx0 = sacc[0][0], mx1 = sacc[0][2];
#pragma unroll
        for (int n = 0; n < 16; n++) {
            mx0 = fmaxf(mx0, fmaxf(sacc[n][0], sacc[n][1]));
            mx1 = fmaxf(mx1, fmaxf(sacc[n][2], sacc[n][3]));
        }
        mx0 = fmaxf(mx0, __shfl_xor_sync(0xffffffffu, mx0, 1));
        mx0 = fmaxf(mx0, __shfl_xor_sync(0xffffffffu, mx0, 2));
        mx1 = fmaxf(mx1, __shfl_xor_sync(0xffffffffu, mx1, 1));
        mx1 = fmaxf(mx1, __shfl_xor_sync(0xffffffffu, mx1, 2));
        float mn0 = fmaxf(m0, mx0), mn1 = fmaxf(m1, mx1);
        float c0 = __expf(m0 - mn0), c1 = __expf(m1 - mn1);
        m0 = mn0; m1 = mn1;
        l0 *= c0; l1 *= c1;
#pragma unroll
        for (int n = 0; n < 8; n++) {
            oacc[n][0] *= c0; oacc[n][1] *= c0;
            oacc[n][2] *= c1; oacc[n][3] *= c1;
        }

        // ---- P = exp(S-m) in registers -> A fragments; O += P V ----
        float sum0 = 0.f, sum1 = 0.f;
#pragma unroll
        for (int t = 0; t < 8; t++) {
            float p0 = __expf(sacc[2 * t][0] - m0);
            float p1 = __expf(sacc[2 * t][1] - m0);
            float p2 = __expf(sacc[2 * t][2] - m1);
            float p3 = __expf(sacc[2 * t][3] - m1);
            float p4 = __expf(sacc[2 * t + 1][0] - m0);
            float p5 = __expf(sacc[2 * t + 1][1] - m0);
            float p6 = __expf(sacc[2 * t + 1][2] - m1);
            float p7 = __expf(sacc[2 * t + 1][3] - m1);
            sum0 += (p0 + p1) + (p4 + p5);
            sum1 += (p2 + p3) + (p6 + p7);

            unsigned aph[4], apl[4];
            aph[0] = bfpack(p0, p1);
            aph[1] = bfpack(p2, p3);
            aph[2] = bfpack(p4, p5);
            aph[3] = bfpack(p6, p7);
            float r0 = p0 - __bfloat162float(__float2bfloat16(p0));
            float r1 = p1 - __bfloat162float(__float2bfloat16(p1));
            float r2 = p2 - __bfloat162float(__float2bfloat16(p2));
            float r3 = p3 - __bfloat162float(__float2bfloat16(p3));
            float r4f = p4 - __bfloat162float(__float2bfloat16(p4));
            float r5 = p5 - __bfloat162float(__float2bfloat16(p5));
            float r6 = p6 - __bfloat162float(__float2bfloat16(p6));
            float r7 = p7 - __bfloat162float(__float2bfloat16(p7));
            apl[0] = bfpack(r0, r1);
            apl[1] = bfpack(r2, r3);
            apl[2] = bfpack(r4f, r5);
            apl[3] = bfpack(r6, r7);

#pragma unroll
            for (int np = 0; np < 4; np++) {
                unsigned eo2 = ((rowB + np * 16) * 136 + kHalf + 16 * t) * 2;
                unsigned v4[4], w4[4];
                ldm_x4(v4, sVh32 + eo2);
                ldm_x4(w4, sVl32 + eo2);
                mma_bf16(oacc[2 * np],     aph, v4[0], v4[2]);
                mma_bf16(oacc[2 * np],     aph, w4[0], w4[2]);
                mma_bf16(oacc[2 * np],     apl, v4[0], v4[2]);
                mma_bf16(oacc[2 * np + 1], aph, v4[1], v4[3]);
                mma_bf16(oacc[2 * np + 1], aph, w4[1], w4[3]);
                mma_bf16(oacc[2 * np + 1], apl, v4[1], v4[3]);
            }
        }
        sum0 += __shfl_xor_sync(0xffffffffu, sum0, 1);
        sum0 += __shfl_xor_sync(0xffffffffu, sum0, 2);
        sum1 += __shfl_xor_sync(0xffffffffu, sum1, 1);
        sum1 += __shfl_xor_sync(0xffffffffu, sum1, 2);
        l0 += sum0; l1 += sum1;
        __syncthreads();
    }

    // ---- epilogue: normalize, stage [q][65] in smem, coalesced [d][l] write ----
    float* sOut = (float*)smraw;
    float il0 = 1.f / l0, il1 = 1.f / l1;
    int r0q = wid * 16 + (lane >> 2);
#pragma unroll
    for (int n = 0; n < 8; n++) {
        int d = n * 8 + (lane & 3) * 2;
        sOut[r0q * 65 + d]           = oacc[n][0] * il0;
        sOut[r0q * 65 + d + 1]       = oacc[n][1] * il0;
        sOut[(r0q + 8) * 65 + d]     = oacc[n][2] * il1;
        sOut[(r0q + 8) * 65 + d + 1] = oacc[n][3] * il1;
    }
    __syncthreads();

    float* op = outm + ((long)b * CH + h * 64) * LPIX + qt * 128;
#pragma unroll
    for (int it = 0; it < 32; it++) {
        int f = tid + it * 256;
        int d = f >> 7, l = f & 127;
        op[(long)d * LPIX + l] = sOut[l * 65 + d];
    }
}

// ---------------------------------------------------------------------------
// Depthwise 3x3 conv (+BN), accumulated into g_mid.
// ---------------------------------------------------------------------------
__global__ __launch_bounds__(1024)
void dw_kernel(const float* __restrict__ qkv, const float* __restrict__ w,
               const float* __restrict__ s, const float* __restrict__ bb,
               float* __restrict__ outm)
{
    const int c = blockIdx.x & 255;
    const int b = blockIdx.x >> 8;
    const int t = threadIdx.x;
    const int y = t >> 5, x = t & 31;
    const int h = c >> 6, d = c & 63;
    const float* vp = qkv + ((long)b * CQKV + h * 128 + 64 + d) * LPIX;

    __shared__ float tile[34][34];
    tile[y + 1][x + 1] = vp[t];
    if (t < 34) {
        tile[0][t] = 0.f; tile[33][t] = 0.f;
        tile[t][0] = 0.f; tile[t][33] = 0.f;
    }
    __syncthreads();

    float acc = 0.f;
#pragma unroll
    for (int ky = 0; ky < 3; ky++)
#pragma unroll
        for (int kx = 0; kx < 3; kx++)
            acc = fmaf(tile[y + ky][x + kx], w[c * 9 + ky * 3 + kx], acc);

    outm[((long)b * CH + c) * LPIX + t] += acc * s[c] + bb[c];
}

// ---------------------------------------------------------------------------
extern "C" void kernel_launch(void* const* d_in, const int* in_sizes, int n_in,
                              void* d_out, int out_size)
{
    const float* x     = (const float*)d_in[0];
    const float* w_qkv = (const float*)d_in[1];
    const float* s_qkv = (const float*)d_in[2];
    const float* b_qkv = (const float*)d_in[3];
    const float* w_dw  = (const float*)d_in[4];
    const float* s_dw  = (const float*)d_in[5];
    const float* b_dw  = (const float*)d_in[6];
    const float* w_pw  = (const float*)d_in[7];
    const float* s_pw  = (const float*)d_in[8];
    const float* b_pw  = (const float*)d_in[9];
    float* out = (float*)d_out;

    float *qkvbuf = nullptr, *midbuf = nullptr;
    cudaGetSymbolAddress((void**)&qkvbuf, g_qkv);
    cudaGetSymbolAddress((void**)&midbuf, g_mid);
    __nv_bfloat16 *wqh, *wql, *wph, *wpl, *xth, *xtl, *mth, *mtl;
    cudaGetSymbolAddress((void**)&wqh, g_wqh);
    cudaGetSymbolAddress((void**)&wql, g_wql);
    cudaGetSymbolAddress((void**)&wph, g_wph);
    cudaGetSymbolAddress((void**)&wpl, g_wpl);
    cudaGetSymbolAddress((void**)&xth, g_xth);
    cudaGetSymbolAddress((void**)&xtl, g_xtl);
    cudaGetSymbolAddress((void**)&mth, g_mth);
    cudaGetSymbolAddress((void**)&mtl, g_mtl);

    cudaFuncSetAttribute(attn_hmma, cudaFuncAttributeMaxDynamicSharedMemorySize, AT_SMEM);
    cudaFuncSetAttribute(hmma_gemm_bn, cudaFuncAttributeMaxDynamicSharedMemorySize, HT_SMEM);

    // Prep: split weights; transpose+split x
    split_w_kernel<<<(CQKV * CH + 255) / 256, 256>>>(w_qkv, wqh, wql, CQKV * CH);
    split_w_kernel<<<(CH * CH + 255) / 256, 256>>>(w_pw, wph, wpl, CH * CH);
    split_t_kernel<<<dim3(LPIX / 64, CH / 64, BATCH), 256>>>(x, xth, xtl, CH, LPIX);

    // 1) qkv = bn(W_qkv @ x)   [tensor cores]
    hmma_gemm_bn<<<dim3(8, 4, 16), 256, HT_SMEM>>>(wqh, wql, xth, xtl, qkvbuf,
                                                   s_qkv, b_qkv, CQKV, LPIX, CH);
    // 2) attention -> g_mid    [tensor cores]
    attn_hmma<<<dim3(8, 4, 16), 256, AT_SMEM>>>(qkvbuf, midbuf);
    // 3) g_mid += bn(dwconv3(v))
    dw_kernel<<<dim3(BATCH * CH), 1024>>>(qkvbuf, w_dw, s_dw, b_dw, midbuf);
    // 4) transpose+split mid, then out = bn(W_pw @ g_mid)  [tensor cores]
    split_t_kernel<<<dim3(LPIX / 64, CH / 64, BATCH), 256>>>(midbuf, mth, mtl, CH, LPIX);
    hmma_gemm_bn<<<dim3(8, 2, 16), 256, HT_SMEM>>>(wph, wpl, mth, mtl, out,
                                                   s_pw, b_pw, CH, LPIX, CH);
}

// round 10
// speedup vs baseline: 2.3959x; 1.1210x over previous
#include <cuda_runtime.h>
#include <cuda_bf16.h>
#include <math.h>

// Problem constants
#define BATCH 16
#define CH    256
#define NH    4
#define DH    64
#define LPIX  1024
#define CQKV  512
#define SCALE 0.17677669529663687f   // 32^-0.5

typedef unsigned long long u64;
typedef __nv_bfloat16 bf16;

__device__ __forceinline__ unsigned smem_u32(const void* p) {
    unsigned r;
    asm("{ .reg .u64 t; cvta.to.shared.u64 t, %1; cvt.u32.u64 %0, t; }" : "=r"(r) : "l"(p));
    return r;
}

// ---------------- mma.sync + cp.async helpers ----------------
__device__ __forceinline__ void ldm_x4(unsigned* r, unsigned addr) {
    asm volatile("ldmatrix.sync.aligned.m8n8.x4.shared.b16 {%0,%1,%2,%3}, [%4];"
                 : "=r"(r[0]), "=r"(r[1]), "=r"(r[2]), "=r"(r[3]) : "r"(addr));
}
__device__ __forceinline__ void mma_bf16(float* c, const unsigned* a, unsigned b0, unsigned b1) {
    asm volatile(
        "mma.sync.aligned.m16n8k16.row.col.f32.bf16.bf16.f32 "
        "{%0,%1,%2,%3}, {%4,%5,%6,%7}, {%8,%9}, {%0,%1,%2,%3};"
        : "+f"(c[0]), "+f"(c[1]), "+f"(c[2]), "+f"(c[3])
        : "r"(a[0]), "r"(a[1]), "r"(a[2]), "r"(a[3]), "r"(b0), "r"(b1));
}
__device__ __forceinline__ unsigned bfpack(float lo, float hi) {
    unsigned r;
    asm("cvt.rn.bf16x2.f32 %0, %1, %2;" : "=r"(r) : "f"(hi), "f"(lo));
    return r;
}
__device__ __forceinline__ void cpa16(unsigned dst, const void* src) {
    asm volatile("cp.async.ca.shared.global [%0], [%1], 16;" :: "r"(dst), "l"(src));
}
#define CP_COMMIT asm volatile("cp.async.commit_group;" ::: "memory")
#define CP_WAIT0  asm volatile("cp.async.wait_group 0;" ::: "memory")

// ---------------- scratch (allocation-free: __device__ globals) ----------------
__device__ float g_qkv[(long)BATCH * CQKV * LPIX];   // [b][o][l]
__device__ float g_mid[(long)BATCH * CH * LPIX];     // [b][c][l]
__device__ bf16 g_wqh[CQKV * CH], g_wql[CQKV * CH];
__device__ bf16 g_wph[CH * CH],   g_wpl[CH * CH];
__device__ bf16 g_xth[(long)BATCH * LPIX * CH], g_xtl[(long)BATCH * LPIX * CH];
__device__ bf16 g_mth[(long)BATCH * LPIX * CH], g_mtl[(long)BATCH * LPIX * CH];
// Pre-split attention operands: Q/K [bh][l][32], V [bh][d][1024]
__device__ bf16 g_qh[(long)64 * LPIX * 32], g_ql[(long)64 * LPIX * 32];
__device__ bf16 g_kh[(long)64 * LPIX * 32], g_kl[(long)64 * LPIX * 32];
__device__ bf16 g_vh[(long)64 * 64 * LPIX], g_vl[(long)64 * 64 * LPIX];

// ---------------------------------------------------------------------------
// Split fp32 -> bf16 hi/lo (elementwise; layout preserved)
// ---------------------------------------------------------------------------
__global__ void split_w_kernel(const float* __restrict__ w,
                               bf16* __restrict__ h, bf16* __restrict__ l, int n)
{
    int i = blockIdx.x * 256 + threadIdx.x;
    if (i < n) {
        float v = w[i];
        bf16 hh = __float2bfloat16(v);
        h[i] = hh;
        l[i] = __float2bfloat16(v - __bfloat162float(hh));
    }
}

// ---------------------------------------------------------------------------
// Transpose + split: X[b][k][n] fp32 -> T[b][n][k] bf16 hi/lo. 64x64 tiles.
// ---------------------------------------------------------------------------
__global__ __launch_bounds__(256)
void split_t_kernel(const float* __restrict__ X,
                    bf16* __restrict__ Th, bf16* __restrict__ Tl, int K, int N)
{
    __shared__ float t[64][65];
    const int n0 = blockIdx.x * 64;
    const int k0 = blockIdx.y * 64;
    const long b = blockIdx.z;
    const float* Xb = X + b * (long)K * N;
    bf16* ThB = Th + b * (long)K * N;
    bf16* TlB = Tl + b * (long)K * N;
    const int tx = threadIdx.x & 63, ty = threadIdx.x >> 6;

#pragma unroll
    for (int i = 0; i < 16; i++)
        t[ty + i * 4][tx] = Xb[(long)(k0 + ty + i * 4) * N + n0 + tx];
    __syncthreads();

#pragma unroll
    for (int i = 0; i < 16; i++) {
        int n = ty + i * 4;
        float v = t[tx][n];
        bf16 hh = __float2bfloat16(v);
        ThB[(long)(n0 + n) * K + k0 + tx] = hh;
        TlB[(long)(n0 + n) * K + k0 + tx] = __float2bfloat16(v - __bfloat162float(hh));
    }
}

// ---------------------------------------------------------------------------
// Split qkv into attention operands. Grid (8 lchunks, 4 h, 16 b), 256 thr.
// Q/K: [32 d][128 l] -> [l][32] hi/lo (Q pre-scaled). V: [64 d][128 l] split.
// ---------------------------------------------------------------------------
__global__ __launch_bounds__(256)
void split_qkv_kernel(const float* __restrict__ qkv)
{
    __shared__ float t[32][133];
    const int l0 = blockIdx.x * 128;
    const int h = blockIdx.y;
    const int b = blockIdx.z;
    const int bh = b * 4 + h;
    const int tid = threadIdx.x;
    const float* base = qkv + ((long)b * CQKV + h * 128) * LPIX;

    // ---- Q (scaled) ----
#pragma unroll
    for (int i = 0; i < 16; i++) {
        int f = tid + i * 256;
        int d = f >> 7, l = f & 127;
        t[d][l] = base[(long)d * LPIX + l0 + l] * SCALE;
    }
    __syncthreads();
#pragma unroll
    for (int i = 0; i < 16; i++) {
        int f = tid + i * 256;
        int l = f >> 5, d = f & 31;
        float v = t[d][l];
        bf16 hh = __float2bfloat16(v);
        long o = ((long)bh * LPIX + l0 + l) * 32 + d;
        g_qh[o] = hh;
        g_ql[o] = __float2bfloat16(v - __bfloat162float(hh));
    }
    __syncthreads();

    // ---- K ----
#pragma unroll
    for (int i = 0; i < 16; i++) {
        int f = tid + i * 256;
        int d = f >> 7, l = f & 127;
        t[d][l] = base[(long)(32 + d) * LPIX + l0 + l];
    }
    __syncthreads();
#pragma unroll
    for (int i = 0; i < 16; i++) {
        int f = tid + i * 256;
        int l = f >> 5, d = f & 31;
        float v = t[d][l];
        bf16 hh = __float2bfloat16(v);
        long o = ((long)bh * LPIX + l0 + l) * 32 + d;
        g_kh[o] = hh;
        g_kl[o] = __float2bfloat16(v - __bfloat162float(hh));
    }

    // ---- V (no transpose) ----
#pragma unroll
    for (int i = 0; i < 32; i++) {
        int f = tid + i * 256;
        int d = f >> 7, l = f & 127;
        float v = base[(long)(64 + d) * LPIX + l0 + l];
        bf16 hh = __float2bfloat16(v);
        long o = ((long)bh * 64 + d) * LPIX + l0 + l;
        g_vh[o] = hh;
        g_vl[o] = __float2bfloat16(v - __bfloat162float(hh));
    }
}

// ---------------------------------------------------------------------------
// HMMA bf16-split GEMM + BN, cp.async double-buffered (K chunks of 32).
// ---------------------------------------------------------------------------
#define G2_PAD   40                     // bf16 elems per row (32 + 8 pad)
#define G2_TILEB 10240                  // bytes per operand tile (128 x 80B)
#define G2_STAGE 40960                  // 4 operands
#define G2_SMEM  81920                  // 2 stages

__global__ __launch_bounds__(256, 2)
void hmma_gemm_bn(const bf16* __restrict__ Ah, const bf16* __restrict__ Al,
                  const bf16* __restrict__ Bh, const bf16* __restrict__ Bl,
                  float* __restrict__ Y, const float* __restrict__ scale,
                  const float* __restrict__ bias, int M, int N, int K)
{
    extern __shared__ char smem[];
    const unsigned sb = smem_u32(smem);
    const int tid = threadIdx.x;
    const int wid = tid >> 5, lane = tid & 31;
    const int wm = wid & 3, wn = wid >> 2;
    const int n0 = blockIdx.x * 128;
    const int m0 = blockIdx.y * 128;
    const long bz = blockIdx.z;
    const bf16* Bhb = Bh + bz * (long)N * K;
    const bf16* Blb = Bl + bz * (long)N * K;
    float* Yb = Y + bz * (long)M * N;

    float acc[2][8][4];
#pragma unroll
    for (int mi = 0; mi < 2; mi++)
#pragma unroll
        for (int ni = 0; ni < 8; ni++)
#pragma unroll
            for (int j = 0; j < 4; j++) acc[mi][ni][j] = 0.f;

    const unsigned aRow = (unsigned)(wm * 32 + (lane & 15));
    const unsigned bRow = (unsigned)(wn * 64 + (lane & 15));
    const unsigned kHalf = (unsigned)((lane >> 4) * 8);

    auto load_chunk = [&](int st, int kc) {
        unsigned db = sb + st * G2_STAGE;
#pragma unroll
        for (int i = 0; i < 2; i++) {
            int f = tid + i * 256;          // 0..511
            int r = f >> 2, c4 = f & 3;
            unsigned d0 = db + r * 80 + c4 * 16;
            cpa16(d0,                 Ah  + (long)(m0 + r) * K + kc + c4 * 8);
            cpa16(d0 + G2_TILEB,      Al  + (long)(m0 + r) * K + kc + c4 * 8);
            cpa16(d0 + 2 * G2_TILEB,  Bhb + (long)(n0 + r) * K + kc + c4 * 8);
            cpa16(d0 + 3 * G2_TILEB,  Blb + (long)(n0 + r) * K + kc + c4 * 8);
        }
    };

    const int NCH = K / 32;
    load_chunk(0, 0);
    CP_COMMIT;
    CP_WAIT0;
    __syncthreads();

    for (int c = 0; c < NCH; c++) {
        const int st = c & 1;
        if (c + 1 < NCH) { load_chunk(1 - st, (c + 1) * 32); CP_COMMIT; }

        unsigned base = sb + st * G2_STAGE;
#pragma unroll
        for (int k16 = 0; k16 < 32; k16 += 16) {
            unsigned ah[2][4], al[2][4];
#pragma unroll
            for (int mi = 0; mi < 2; mi++) {
                unsigned eo = ((aRow + mi * 16) * G2_PAD + kHalf + k16) * 2;
                ldm_x4(ah[mi], base + eo);
                ldm_x4(al[mi], base + G2_TILEB + eo);
            }
            unsigned bh[8][2], bl[8][2];
#pragma unroll
            for (int np = 0; np < 4; np++) {
                unsigned eo = ((bRow + np * 16) * G2_PAD + kHalf + k16) * 2;
                unsigned r4[4];
                ldm_x4(r4, base + 2 * G2_TILEB + eo);
                bh[np * 2][0] = r4[0]; bh[np * 2][1] = r4[2];
                bh[np * 2 + 1][0] = r4[1]; bh[np * 2 + 1][1] = r4[3];
                ldm_x4(r4, base + 3 * G2_TILEB + eo);
                bl[np * 2][0] = r4[0]; bl[np * 2][1] = r4[2];
                bl[np * 2 + 1][0] = r4[1]; bl[np * 2 + 1][1] = r4[3];
            }
#pragma unroll
            for (int mi = 0; mi < 2; mi++)
#pragma unroll
                for (int ni = 0; ni < 8; ni++) {
                    mma_bf16(acc[mi][ni], ah[mi], bh[ni][0], bh[ni][1]);
                    mma_bf16(acc[mi][ni], ah[mi], bl[ni][0], bl[ni][1]);
                    mma_bf16(acc[mi][ni], al[mi], bh[ni][0], bh[ni][1]);
                }
        }
        if (c + 1 < NCH) CP_WAIT0;
        __syncthreads();
    }

#pragma unroll
    for (int mi = 0; mi < 2; mi++) {
        int r1 = m0 + wm * 32 + mi * 16 + (lane >> 2);
        int r2 = r1 + 8;
        float s1 = scale[r1], b1 = bias[r1];
        float s2 = scale[r2], b2 = bias[r2];
        float* y1 = &Yb[(long)r1 * N + n0 + wn * 64 + (lane & 3) * 2];
        float* y2 = &Yb[(long)r2 * N + n0 + wn * 64 + (lane & 3) * 2];
#pragma unroll
        for (int ni = 0; ni < 8; ni++) {
            float2 o1, o2;
            o1.x = acc[mi][ni][0] * s1 + b1;
            o1.y = acc[mi][ni][1] * s1 + b1;
            o2.x = acc[mi][ni][2] * s2 + b2;
            o2.y = acc[mi][ni][3] * s2 + b2;
            *reinterpret_cast<float2*>(y1 + ni * 8) = o1;
            *reinterpret_cast<float2*>(y2 + ni * 8) = o2;
        }
    }
}

// ---------------------------------------------------------------------------
// HMMA flash attention v2: pre-split operands, cp.async double-buffered K/V.
// smem: Qh/Ql [128][40] @0/10240 | K stages @20480+buf*20480 (Kh,Kl 10240 each)
//       V stages @61440+buf*34816 (Vh,Vl 17408 each)   total 131072
// ---------------------------------------------------------------------------
#define AT_SMEM 131072

__global__ __launch_bounds__(256, 1)
void attn_hmma(float* __restrict__ outm)
{
    extern __shared__ char smraw[];
    const unsigned sb = smem_u32(smraw);
    const int tid = threadIdx.x;
    const int wid = tid >> 5, lane = tid & 31;
    const int qt = blockIdx.x, h = blockIdx.y, b = blockIdx.z;
    const int bh = b * 4 + h;

    const bf16* qh = g_qh + ((long)bh * LPIX + qt * 128) * 32;
    const bf16* ql = g_ql + ((long)bh * LPIX + qt * 128) * 32;
    const bf16* khp = g_kh + (long)bh * LPIX * 32;
    const bf16* klp = g_kl + (long)bh * LPIX * 32;
    const bf16* vhp = g_vh + (long)bh * 64 * LPIX;
    const bf16* vlp = g_vl + (long)bh * 64 * LPIX;

    // Q tile: 128 rows x 64B, hi+lo
#pragma unroll
    for (int i = 0; i < 2; i++) {
        int f = tid + i * 256;
        int r = f >> 2, c4 = f & 3;
        cpa16(sb + r * 80 + c4 * 16,         qh + r * 32 + c4 * 8);
        cpa16(sb + 10240 + r * 80 + c4 * 16, ql + r * 32 + c4 * 8);
    }

    auto load_kv = [&](int buf, int kt) {
        unsigned kb = sb + 20480 + buf * 20480;
        unsigned vb = sb + 61440 + buf * 34816;
        const bf16* kh = khp + (long)kt * 128 * 32;
        const bf16* kl = klp + (long)kt * 128 * 32;
#pragma unroll
        for (int i = 0; i < 2; i++) {
            int f = tid + i * 256;
            int r = f >> 2, c4 = f & 3;
            cpa16(kb + r * 80 + c4 * 16,         kh + r * 32 + c4 * 8);
            cpa16(kb + 10240 + r * 80 + c4 * 16, kl + r * 32 + c4 * 8);
        }
#pragma unroll
        for (int i = 0; i < 4; i++) {
            int f = tid + i * 256;
            int d = f >> 4, j = f & 15;
            cpa16(vb + d * 272 + j * 16,         vhp + (long)d * LPIX + kt * 128 + j * 8);
            cpa16(vb + 17408 + d * 272 + j * 16, vlp + (long)d * LPIX + kt * 128 + j * 8);
        }
    };

    load_kv(0, 0);
    CP_COMMIT;
    CP_WAIT0;
    __syncthreads();

    float oacc[8][4];
#pragma unroll
    for (int n = 0; n < 8; n++)
#pragma unroll
        for (int j = 0; j < 4; j++) oacc[n][j] = 0.f;
    float m0 = -INFINITY, m1 = -INFINITY, l0 = 0.f, l1 = 0.f;

    const unsigned rowA = (unsigned)(wid * 16 + (lane & 15));
    const unsigned rowB = (unsigned)(lane & 15);
    const unsigned kHalf = (unsigned)((lane >> 4) * 8);

    for (int kt = 0; kt < 8; kt++) {
        const int buf = kt & 1;
        if (kt + 1 < 8) { load_kv(1 - buf, kt + 1); CP_COMMIT; }

        const unsigned sKh = sb + 20480 + buf * 20480;
        const unsigned sKl = sKh + 10240;
        const unsigned sVh = sb + 61440 + buf * 34816;
        const unsigned sVl = sVh + 17408;

        // ---- S = Q K^T (3-term split) ----
        float sacc[16][4];
#pragma unroll
        for (int n = 0; n < 16; n++)
#pragma unroll
            for (int j = 0; j < 4; j++) sacc[n][j] = 0.f;

#pragma unroll
        for (int t = 0; t < 2; t++) {
            unsigned ah[4], al[4];
            unsigned eo = (rowA * 40 + kHalf + 16 * t) * 2;
            ldm_x4(ah, sb + eo);
            ldm_x4(al, sb + 10240 + eo);
#pragma unroll
            for (int np = 0; np < 8; np++) {
                unsigned eo2 = ((rowB + np * 16) * 40 + kHalf + 16 * t) * 2;
                unsigned r4[4], s4[4];
                ldm_x4(r4, sKh + eo2);
                ldm_x4(s4, sKl + eo2);
                mma_bf16(sacc[2 * np],     ah, r4[0], r4[2]);
                mma_bf16(sacc[2 * np],     ah, s4[0], s4[2]);
                mma_bf16(sacc[2 * np],     al, r4[0], r4[2]);
                mma_bf16(sacc[2 * np + 1], ah, r4[1], r4[3]);
                mma_bf16(sacc[2 * np + 1], ah, s4[1], s4[3]);
                mma_bf16(sacc[2 * np + 1], al, r4[1], r4[3]);
            }
        }

        // ---- online softmax ----
        float mx0 = sacc[0][0], mx1 = sacc[0][2];
#pragma unroll
        for (int n = 0; n < 16; n++) {
            mx0 = fmaxf(mx0, fmaxf(sacc[n][0], sacc[n][1]));
            mx1 = fmaxf(mx1, fmaxf(sacc[n][2], sacc[n][3]));
        }
        mx0 = fmaxf(mx0, __shfl_xor_sync(0xffffffffu, mx0, 1));
        mx0 = fmaxf(mx0, __shfl_xor_sync(0xffffffffu, mx0, 2));
        mx1 = fmaxf(mx1, __shfl_xor_sync(0xffffffffu, mx1, 1));
        mx1 = fmaxf(mx1, __shfl_xor_sync(0xffffffffu, mx1, 2));
        float mn0 = fmaxf(m0, mx0), mn1 = fmaxf(m1, mx1);
        float c0 = __expf(m0 - mn0), c1 = __expf(m1 - mn1);
        m0 = mn0; m1 = mn1;
        l0 *= c0; l1 *= c1;
#pragma unroll
        for (int n = 0; n < 8; n++) {
            oacc[n][0] *= c0; oacc[n][1] *= c0;
            oacc[n][2] *= c1; oacc[n][3] *= c1;
        }

        // ---- P = exp(S-m) -> A fragments; O += P V ----
        float sum0 = 0.f, sum1 = 0.f;
#pragma unroll
        for (int t = 0; t < 8; t++) {
            float p0 = __expf(sacc[2 * t][0] - m0);
            float p1 = __expf(sacc[2 * t][1] - m0);
            float p2 = __expf(sacc[2 * t][2] - m1);
            float p3 = __expf(sacc[2 * t][3] - m1);
            float p4 = __expf(sacc[2 * t + 1][0] - m0);
            float p5 = __expf(sacc[2 * t + 1][1] - m0);
            float p6 = __expf(sacc[2 * t + 1][2] - m1);
            float p7 = __expf(sacc[2 * t + 1][3] - m1);
            sum0 += (p0 + p1) + (p4 + p5);
            sum1 += (p2 + p3) + (p6 + p7);

            unsigned aph[4], apl[4];
            aph[0] = bfpack(p0, p1);
            aph[1] = bfpack(p2, p3);
            aph[2] = bfpack(p4, p5);
            aph[3] = bfpack(p6, p7);
            float r0 = p0 - __bfloat162float(__float2bfloat16(p0));
            float r1 = p1 - __bfloat162float(__float2bfloat16(p1));
            float r2 = p2 - __bfloat162float(__float2bfloat16(p2));
            float r3 = p3 - __bfloat162float(__float2bfloat16(p3));
            float r4f = p4 - __bfloat162float(__float2bfloat16(p4));
            float r5 = p5 - __bfloat162float(__float2bfloat16(p5));
            float r6 = p6 - __bfloat162float(__float2bfloat16(p6));
            float r7 = p7 - __bfloat162float(__float2bfloat16(p7));
            apl[0] = bfpack(r0, r1);
            apl[1] = bfpack(r2, r3);
            apl[2] = bfpack(r4f, r5);
            apl[3] = bfpack(r6, r7);

#pragma unroll
            for (int np = 0; np < 4; np++) {
                unsigned eo2 = ((rowB + np * 16) * 136 + kHalf + 16 * t) * 2;
                unsigned v4[4], w4[4];
                ldm_x4(v4, sVh + eo2);
                ldm_x4(w4, sVl + eo2);
                mma_bf16(oacc[2 * np],     aph, v4[0], v4[2]);
                mma_bf16(oacc[2 * np],     aph, w4[0], w4[2]);
                mma_bf16(oacc[2 * np],     apl, v4[0], v4[2]);
                mma_bf16(oacc[2 * np + 1], aph, v4[1], v4[3]);
                mma_bf16(oacc[2 * np + 1], aph, w4[1], w4[3]);
                mma_bf16(oacc[2 * np + 1], apl, v4[1], v4[3]);
            }
        }
        sum0 += __shfl_xor_sync(0xffffffffu, sum0, 1);
        sum0 += __shfl_xor_sync(0xffffffffu, sum0, 2);
        sum1 += __shfl_xor_sync(0xffffffffu, sum1, 1);
        sum1 += __shfl_xor_sync(0xffffffffu, sum1, 2);
        l0 += sum0; l1 += sum1;

        if (kt + 1 < 8) CP_WAIT0;
        __syncthreads();
    }

    // ---- epilogue ----
    float* sOut = (float*)smraw;
    float il0 = 1.f / l0, il1 = 1.f / l1;
    int r0q = wid * 16 + (lane >> 2);
#pragma unroll
    for (int n = 0; n < 8; n++) {
        int d = n * 8 + (lane & 3) * 2;
        sOut[r0q * 65 + d]           = oacc[n][0] * il0;
        sOut[r0q * 65 + d + 1]       = oacc[n][1] * il0;
        sOut[(r0q + 8) * 65 + d]     = oacc[n][2] * il1;
        sOut[(r0q + 8) * 65 + d + 1] = oacc[n][3] * il1;
    }
    __syncthreads();

    float* op = outm + ((long)b * CH + h * 64) * LPIX + qt * 128;
#pragma unroll
    for (int it = 0; it < 32; it++) {
        int f = tid + it * 256;
        int d = f >> 7, l = f & 127;
        op[(long)d * LPIX + l] = sOut[l * 65 + d];
    }
}

// ---------------------------------------------------------------------------
// Depthwise 3x3 conv (+BN), accumulated into g_mid.
// ---------------------------------------------------------------------------
__global__ __launch_bounds__(1024)
void dw_kernel(const float* __restrict__ qkv, const float* __restrict__ w,
               const float* __restrict__ s, const float* __restrict__ bb,
               float* __restrict__ outm)
{
    const int c = blockIdx.x & 255;
    const int b = blockIdx.x >> 8;
    const int t = threadIdx.x;
    const int y = t >> 5, x = t & 31;
    const int h = c >> 6, d = c & 63;
    const float* vp = qkv + ((long)b * CQKV + h * 128 + 64 + d) * LPIX;

    __shared__ float tile[34][34];
    tile[y + 1][x + 1] = vp[t];
    if (t < 34) {
        tile[0][t] = 0.f; tile[33][t] = 0.f;
        tile[t][0] = 0.f; tile[t][33] = 0.f;
    }
    __syncthreads();

    float acc = 0.f;
#pragma unroll
    for (int ky = 0; ky < 3; ky++)
#pragma unroll
        for (int kx = 0; kx < 3; kx++)
            acc = fmaf(tile[y + ky][x + kx], w[c * 9 + ky * 3 + kx], acc);

    outm[((long)b * CH + c) * LPIX + t] += acc * s[c] + bb[c];
}

// ---------------------------------------------------------------------------
extern "C" void kernel_launch(void* const* d_in, const int* in_sizes, int n_in,
                              void* d_out, int out_size)
{
    const float* x     = (const float*)d_in[0];
    const float* w_qkv = (const float*)d_in[1];
    const float* s_qkv = (const float*)d_in[2];
    const float* b_qkv = (const float*)d_in[3];
    const float* w_dw  = (const float*)d_in[4];
    const float* s_dw  = (const float*)d_in[5];
    const float* b_dw  = (const float*)d_in[6];
    const float* w_pw  = (const float*)d_in[7];
    const float* s_pw  = (const float*)d_in[8];
    const float* b_pw  = (const float*)d_in[9];
    float* out = (float*)d_out;

    float *qkvbuf = nullptr, *midbuf = nullptr;
    cudaGetSymbolAddress((void**)&qkvbuf, g_qkv);
    cudaGetSymbolAddress((void**)&midbuf, g_mid);
    bf16 *wqh, *wql, *wph, *wpl, *xth, *xtl, *mth, *mtl;
    cudaGetSymbolAddress((void**)&wqh, g_wqh);
    cudaGetSymbolAddress((void**)&wql, g_wql);
    cudaGetSymbolAddress((void**)&wph, g_wph);
    cudaGetSymbolAddress((void**)&wpl, g_wpl);
    cudaGetSymbolAddress((void**)&xth, g_xth);
    cudaGetSymbolAddress((void**)&xtl, g_xtl);
    cudaGetSymbolAddress((void**)&mth, g_mth);
    cudaGetSymbolAddress((void**)&mtl, g_mtl);

    cudaFuncSetAttribute(attn_hmma, cudaFuncAttributeMaxDynamicSharedMemorySize, AT_SMEM);
    cudaFuncSetAttribute(hmma_gemm_bn, cudaFuncAttributeMaxDynamicSharedMemorySize, G2_SMEM);

    // Prep: split weights; transpose+split x
    split_w_kernel<<<(CQKV * CH + 255) / 256, 256>>>(w_qkv, wqh, wql, CQKV * CH);
    split_w_kernel<<<(CH * CH + 255) / 256, 256>>>(w_pw, wph, wpl, CH * CH);
    split_t_kernel<<<dim3(LPIX / 64, CH / 64, BATCH), 256>>>(x, xth, xtl, CH, LPIX);

    // 1) qkv = bn(W_qkv @ x)
    hmma_gemm_bn<<<dim3(8, 4, 16), 256, G2_SMEM>>>(wqh, wql, xth, xtl, qkvbuf,
                                                   s_qkv, b_qkv, CQKV, LPIX, CH);
    // 2) pre-split attention operands
    split_qkv_kernel<<<dim3(8, 4, 16), 256>>>(qkvbuf);
    // 3) attention -> g_mid
    attn_hmma<<<dim3(8, 4, 16), 256, AT_SMEM>>>(midbuf);
    // 4) g_mid += bn(dwconv3(v))
    dw_kernel<<<dim3(BATCH * CH), 1024>>>(qkvbuf, w_dw, s_dw, b_dw, midbuf);
    // 5) transpose+split mid, then out = bn(W_pw @ g_mid)
    split_t_kernel<<<dim3(LPIX / 64, CH / 64, BATCH), 256>>>(midbuf, mth, mtl, CH, LPIX);
    hmma_gemm_bn<<<dim3(8, 2, 16), 256, G2_SMEM>>>(wph, wpl, mth, mtl, out,
                                                   s_pw, b_pw, CH, LPIX, CH);
}

// round 11
// speedup vs baseline: 2.4225x; 1.0111x over previous
#include <cuda_runtime.h>
#include <cuda_bf16.h>
#include <math.h>

// Problem constants
#define BATCH 16
#define CH    256
#define NH    4
#define DH    64
#define LPIX  1024
#define CQKV  512
#define SCALE 0.17677669529663687f   // 32^-0.5

typedef unsigned long long u64;
typedef __nv_bfloat16 bf16;

__device__ __forceinline__ unsigned smem_u32(const void* p) {
    unsigned r;
    asm("{ .reg .u64 t; cvta.to.shared.u64 t, %1; cvt.u32.u64 %0, t; }" : "=r"(r) : "l"(p));
    return r;
}

// ---------------- mma.sync + cp.async helpers ----------------
__device__ __forceinline__ void ldm_x4(unsigned* r, unsigned addr) {
    asm volatile("ldmatrix.sync.aligned.m8n8.x4.shared.b16 {%0,%1,%2,%3}, [%4];"
                 : "=r"(r[0]), "=r"(r[1]), "=r"(r[2]), "=r"(r[3]) : "r"(addr));
}
__device__ __forceinline__ void mma_bf16(float* c, const unsigned* a, unsigned b0, unsigned b1) {
    asm volatile(
        "mma.sync.aligned.m16n8k16.row.col.f32.bf16.bf16.f32 "
        "{%0,%1,%2,%3}, {%4,%5,%6,%7}, {%8,%9}, {%0,%1,%2,%3};"
        : "+f"(c[0]), "+f"(c[1]), "+f"(c[2]), "+f"(c[3])
        : "r"(a[0]), "r"(a[1]), "r"(a[2]), "r"(a[3]), "r"(b0), "r"(b1));
}
__device__ __forceinline__ unsigned bfpack(float lo, float hi) {
    unsigned r;
    asm("cvt.rn.bf16x2.f32 %0, %1, %2;" : "=r"(r) : "f"(hi), "f"(lo));
    return r;
}
__device__ __forceinline__ void cpa16(unsigned dst, const void* src) {
    asm volatile("cp.async.ca.shared.global [%0], [%1], 16;" :: "r"(dst), "l"(src));
}
#define CP_COMMIT asm volatile("cp.async.commit_group;" ::: "memory")
#define CP_WAIT0  asm volatile("cp.async.wait_group 0;" ::: "memory")

// ---------------- scratch (allocation-free: __device__ globals) ----------------
__device__ float g_qkv[(long)BATCH * CQKV * LPIX];   // [b][o][l]
__device__ float g_mid[(long)BATCH * CH * LPIX];     // [b][c][l]
__device__ bf16 g_wqh[CQKV * CH], g_wql[CQKV * CH];
__device__ bf16 g_wph[CH * CH],   g_wpl[CH * CH];
__device__ bf16 g_xth[(long)BATCH * LPIX * CH], g_xtl[(long)BATCH * LPIX * CH];
__device__ bf16 g_mth[(long)BATCH * LPIX * CH], g_mtl[(long)BATCH * LPIX * CH];
// Pre-split attention operands: Q/K [bh][l][32], V [bh][d][1024]
__device__ bf16 g_qh[(long)64 * LPIX * 32], g_ql[(long)64 * LPIX * 32];
__device__ bf16 g_kh[(long)64 * LPIX * 32], g_kl[(long)64 * LPIX * 32];
__device__ bf16 g_vh[(long)64 * 64 * LPIX], g_vl[(long)64 * 64 * LPIX];

// ---------------------------------------------------------------------------
// Split fp32 -> bf16 hi/lo (elementwise; layout preserved)
// ---------------------------------------------------------------------------
__global__ void split_w_kernel(const float* __restrict__ w,
                               bf16* __restrict__ h, bf16* __restrict__ l, int n)
{
    int i = blockIdx.x * 256 + threadIdx.x;
    if (i < n) {
        float v = w[i];
        bf16 hh = __float2bfloat16(v);
        h[i] = hh;
        l[i] = __float2bfloat16(v - __bfloat162float(hh));
    }
}

// ---------------------------------------------------------------------------
// Transpose + split: X[b][k][n] fp32 -> T[b][n][k] bf16 hi/lo. 64x64 tiles.
// ---------------------------------------------------------------------------
__global__ __launch_bounds__(256)
void split_t_kernel(const float* __restrict__ X,
                    bf16* __restrict__ Th, bf16* __restrict__ Tl, int K, int N)
{
    __shared__ float t[64][65];
    const int n0 = blockIdx.x * 64;
    const int k0 = blockIdx.y * 64;
    const long b = blockIdx.z;
    const float* Xb = X + b * (long)K * N;
    bf16* ThB = Th + b * (long)K * N;
    bf16* TlB = Tl + b * (long)K * N;
    const int tx = threadIdx.x & 63, ty = threadIdx.x >> 6;

#pragma unroll
    for (int i = 0; i < 16; i++)
        t[ty + i * 4][tx] = Xb[(long)(k0 + ty + i * 4) * N + n0 + tx];
    __syncthreads();

#pragma unroll
    for (int i = 0; i < 16; i++) {
        int n = ty + i * 4;
        float v = t[tx][n];
        bf16 hh = __float2bfloat16(v);
        ThB[(long)(n0 + n) * K + k0 + tx] = hh;
        TlB[(long)(n0 + n) * K + k0 + tx] = __float2bfloat16(v - __bfloat162float(hh));
    }
}

// ---------------------------------------------------------------------------
// Split qkv into attention operands. Grid (8 lchunks, 4 h, 16 b), 256 thr.
// ---------------------------------------------------------------------------
__global__ __launch_bounds__(256)
void split_qkv_kernel(const float* __restrict__ qkv)
{
    __shared__ float t[32][133];
    const int l0 = blockIdx.x * 128;
    const int h = blockIdx.y;
    const int b = blockIdx.z;
    const int bh = b * 4 + h;
    const int tid = threadIdx.x;
    const float* base = qkv + ((long)b * CQKV + h * 128) * LPIX;

    // ---- Q (scaled) ----
#pragma unroll
    for (int i = 0; i < 16; i++) {
        int f = tid + i * 256;
        int d = f >> 7, l = f & 127;
        t[d][l] = base[(long)d * LPIX + l0 + l] * SCALE;
    }
    __syncthreads();
#pragma unroll
    for (int i = 0; i < 16; i++) {
        int f = tid + i * 256;
        int l = f >> 5, d = f & 31;
        float v = t[d][l];
        bf16 hh = __float2bfloat16(v);
        long o = ((long)bh * LPIX + l0 + l) * 32 + d;
        g_qh[o] = hh;
        g_ql[o] = __float2bfloat16(v - __bfloat162float(hh));
    }
    __syncthreads();

    // ---- K ----
#pragma unroll
    for (int i = 0; i < 16; i++) {
        int f = tid + i * 256;
        int d = f >> 7, l = f & 127;
        t[d][l] = base[(long)(32 + d) * LPIX + l0 + l];
    }
    __syncthreads();
#pragma unroll
    for (int i = 0; i < 16; i++) {
        int f = tid + i * 256;
        int l = f >> 5, d = f & 31;
        float v = t[d][l];
        bf16 hh = __float2bfloat16(v);
        long o = ((long)bh * LPIX + l0 + l) * 32 + d;
        g_kh[o] = hh;
        g_kl[o] = __float2bfloat16(v - __bfloat162float(hh));
    }

    // ---- V (no transpose) ----
#pragma unroll
    for (int i = 0; i < 32; i++) {
        int f = tid + i * 256;
        int d = f >> 7, l = f & 127;
        float v = base[(long)(64 + d) * LPIX + l0 + l];
        bf16 hh = __float2bfloat16(v);
        long o = ((long)bh * 64 + d) * LPIX + l0 + l;
        g_vh[o] = hh;
        g_vl[o] = __float2bfloat16(v - __bfloat162float(hh));
    }
}

// ---------------------------------------------------------------------------
// HMMA bf16-split GEMM + BN, cp.async double-buffered, term-major MMA order.
// ---------------------------------------------------------------------------
#define G2_PAD   40
#define G2_TILEB 10240
#define G2_STAGE 40960
#define G2_SMEM  81920

__global__ __launch_bounds__(256, 2)
void hmma_gemm_bn(const bf16* __restrict__ Ah, const bf16* __restrict__ Al,
                  const bf16* __restrict__ Bh, const bf16* __restrict__ Bl,
                  float* __restrict__ Y, const float* __restrict__ scale,
                  const float* __restrict__ bias, int M, int N, int K)
{
    extern __shared__ char smem[];
    const unsigned sb = smem_u32(smem);
    const int tid = threadIdx.x;
    const int wid = tid >> 5, lane = tid & 31;
    const int wm = wid & 3, wn = wid >> 2;
    const int n0 = blockIdx.x * 128;
    const int m0 = blockIdx.y * 128;
    const long bz = blockIdx.z;
    const bf16* Bhb = Bh + bz * (long)N * K;
    const bf16* Blb = Bl + bz * (long)N * K;
    float* Yb = Y + bz * (long)M * N;

    float acc[2][8][4];
#pragma unroll
    for (int mi = 0; mi < 2; mi++)
#pragma unroll
        for (int ni = 0; ni < 8; ni++)
#pragma unroll
            for (int j = 0; j < 4; j++) acc[mi][ni][j] = 0.f;

    const unsigned aRow = (unsigned)(wm * 32 + (lane & 15));
    const unsigned bRow = (unsigned)(wn * 64 + (lane & 15));
    const unsigned kHalf = (unsigned)((lane >> 4) * 8);

    auto load_chunk = [&](int st, int kc) {
        unsigned db = sb + st * G2_STAGE;
#pragma unroll
        for (int i = 0; i < 2; i++) {
            int f = tid + i * 256;
            int r = f >> 2, c4 = f & 3;
            unsigned d0 = db + r * 80 + c4 * 16;
            cpa16(d0,                 Ah  + (long)(m0 + r) * K + kc + c4 * 8);
            cpa16(d0 + G2_TILEB,      Al  + (long)(m0 + r) * K + kc + c4 * 8);
            cpa16(d0 + 2 * G2_TILEB,  Bhb + (long)(n0 + r) * K + kc + c4 * 8);
            cpa16(d0 + 3 * G2_TILEB,  Blb + (long)(n0 + r) * K + kc + c4 * 8);
        }
    };

    const int NCH = K / 32;
    load_chunk(0, 0);
    CP_COMMIT;
    CP_WAIT0;
    __syncthreads();

    for (int c = 0; c < NCH; c++) {
        const int st = c & 1;
        if (c + 1 < NCH) { load_chunk(1 - st, (c + 1) * 32); CP_COMMIT; }

        unsigned base = sb + st * G2_STAGE;
#pragma unroll
        for (int k16 = 0; k16 < 32; k16 += 16) {
            unsigned ah[2][4], al[2][4];
#pragma unroll
            for (int mi = 0; mi < 2; mi++) {
                unsigned eo = ((aRow + mi * 16) * G2_PAD + kHalf + k16) * 2;
                ldm_x4(ah[mi], base + eo);
                ldm_x4(al[mi], base + G2_TILEB + eo);
            }
            unsigned bh[8][2], bl[8][2];
#pragma unroll
            for (int np = 0; np < 4; np++) {
                unsigned eo = ((bRow + np * 16) * G2_PAD + kHalf + k16) * 2;
                unsigned r4[4];
                ldm_x4(r4, base + 2 * G2_TILEB + eo);
                bh[np * 2][0] = r4[0]; bh[np * 2][1] = r4[2];
                bh[np * 2 + 1][0] = r4[1]; bh[np * 2 + 1][1] = r4[3];
                ldm_x4(r4, base + 3 * G2_TILEB + eo);
                bl[np * 2][0] = r4[0]; bl[np * 2][1] = r4[2];
                bl[np * 2 + 1][0] = r4[1]; bl[np * 2 + 1][1] = r4[3];
            }
            // term-major: RAW distance = 16 MMAs
#pragma unroll
            for (int mi = 0; mi < 2; mi++)
#pragma unroll
                for (int ni = 0; ni < 8; ni++)
                    mma_bf16(acc[mi][ni], ah[mi], bh[ni][0], bh[ni][1]);
#pragma unroll
            for (int mi = 0; mi < 2; mi++)
#pragma unroll
                for (int ni = 0; ni < 8; ni++)
                    mma_bf16(acc[mi][ni], ah[mi], bl[ni][0], bl[ni][1]);
#pragma unroll
            for (int mi = 0; mi < 2; mi++)
#pragma unroll
                for (int ni = 0; ni < 8; ni++)
                    mma_bf16(acc[mi][ni], al[mi], bh[ni][0], bh[ni][1]);
        }
        if (c + 1 < NCH) CP_WAIT0;
        __syncthreads();
    }

#pragma unroll
    for (int mi = 0; mi < 2; mi++) {
        int r1 = m0 + wm * 32 + mi * 16 + (lane >> 2);
        int r2 = r1 + 8;
        float s1 = scale[r1], b1 = bias[r1];
        float s2 = scale[r2], b2 = bias[r2];
        float* y1 = &Yb[(long)r1 * N + n0 + wn * 64 + (lane & 3) * 2];
        float* y2 = &Yb[(long)r2 * N + n0 + wn * 64 + (lane & 3) * 2];
#pragma unroll
        for (int ni = 0; ni < 8; ni++) {
            float2 o1, o2;
            o1.x = acc[mi][ni][0] * s1 + b1;
            o1.y = acc[mi][ni][1] * s1 + b1;
            o2.x = acc[mi][ni][2] * s2 + b2;
            o2.y = acc[mi][ni][3] * s2 + b2;
            *reinterpret_cast<float2*>(y1 + ni * 8) = o1;
            *reinterpret_cast<float2*>(y2 + ni * 8) = o2;
        }
    }
}

// ---------------------------------------------------------------------------
// HMMA flash attention v3: KT=64 key tiles -> 77.8KB smem -> occupancy 2.
// Term-major MMA ordering. cp.async double-buffered K/V; pre-split operands.
// smem: Qh@0 Ql@10240 (128x80B each) | K stages @20480+st*10240 (Kh 5120, Kl 5120)
//       V stages @40960+st*18432 (Vh 9216 = 64x144B, Vl 9216).  total 77824
// ---------------------------------------------------------------------------
#define AT_SMEM 77824

__global__ __launch_bounds__(256, 2)
void attn_hmma(float* __restrict__ outm)
{
    extern __shared__ char smraw[];
    const unsigned sb = smem_u32(smraw);
    const int tid = threadIdx.x;
    const int wid = tid >> 5, lane = tid & 31;
    const int qt = blockIdx.x, h = blockIdx.y, b = blockIdx.z;
    const int bh = b * 4 + h;

    const bf16* qh = g_qh + ((long)bh * LPIX + qt * 128) * 32;
    const bf16* ql = g_ql + ((long)bh * LPIX + qt * 128) * 32;
    const bf16* khp = g_kh + (long)bh * LPIX * 32;
    const bf16* klp = g_kl + (long)bh * LPIX * 32;
    const bf16* vhp = g_vh + (long)bh * 64 * LPIX;
    const bf16* vlp = g_vl + (long)bh * 64 * LPIX;

    // Q tile: 128 rows x 64B, hi+lo
#pragma unroll
    for (int i = 0; i < 2; i++) {
        int f = tid + i * 256;
        int r = f >> 2, c4 = f & 3;
        cpa16(sb + r * 80 + c4 * 16,         qh + r * 32 + c4 * 8);
        cpa16(sb + 10240 + r * 80 + c4 * 16, ql + r * 32 + c4 * 8);
    }

    auto load_kv = [&](int st, int kt) {
        unsigned kb = sb + 20480 + st * 10240;
        unsigned vb = sb + 40960 + st * 18432;
        {   // K: 64 rows x 64B each, hi+lo  (256 cpa per operand)
            int r = tid >> 2, c4 = tid & 3;
            cpa16(kb + r * 80 + c4 * 16,        khp + (long)(kt * 64 + r) * 32 + c4 * 8);
            cpa16(kb + 5120 + r * 80 + c4 * 16, klp + (long)(kt * 64 + r) * 32 + c4 * 8);
        }
#pragma unroll
        for (int i = 0; i < 2; i++) {   // V: 64 d-rows x 128B, hi+lo
            int f = tid + i * 256;
            int d = f >> 3, j8 = f & 7;
            cpa16(vb + d * 144 + j8 * 16,        vhp + (long)d * LPIX + kt * 64 + j8 * 8);
            cpa16(vb + 9216 + d * 144 + j8 * 16, vlp + (long)d * LPIX + kt * 64 + j8 * 8);
        }
    };

    load_kv(0, 0);
    CP_COMMIT;
    CP_WAIT0;
    __syncthreads();

    float oacc[8][4];
#pragma unroll
    for (int n = 0; n < 8; n++)
#pragma unroll
        for (int j = 0; j < 4; j++) oacc[n][j] = 0.f;
    float m0 = -INFINITY, m1 = -INFINITY, l0 = 0.f, l1 = 0.f;

    const unsigned rowA = (unsigned)(wid * 16 + (lane & 15));
    const unsigned rowB = (unsigned)(lane & 15);
    const unsigned kHalf = (unsigned)((lane >> 4) * 8);

    for (int kt = 0; kt < 16; kt++) {
        const int st = kt & 1;
        if (kt + 1 < 16) { load_kv(1 - st, kt + 1); CP_COMMIT; }

        const unsigned sKh = sb + 20480 + st * 10240;
        const unsigned sKl = sKh + 5120;
        const unsigned sVh = sb + 40960 + st * 18432;
        const unsigned sVl = sVh + 9216;

        // ---- S = Q K^T (3-term split, 64 keys -> 8 n8 tiles) ----
        float sacc[8][4];
#pragma unroll
        for (int n = 0; n < 8; n++)
#pragma unroll
            for (int j = 0; j < 4; j++) sacc[n][j] = 0.f;

#pragma unroll
        for (int t = 0; t < 2; t++) {
            unsigned ah[4], al[4];
            unsigned eo = (rowA * 40 + kHalf + 16 * t) * 2;
            ldm_x4(ah, sb + eo);
            ldm_x4(al, sb + 10240 + eo);
            unsigned bh[8][2], bl[8][2];
#pragma unroll
            for (int np = 0; np < 4; np++) {
                unsigned eo2 = ((rowB + np * 16) * 40 + kHalf + 16 * t) * 2;
                unsigned r4[4];
                ldm_x4(r4, sKh + eo2);
                bh[np * 2][0] = r4[0]; bh[np * 2][1] = r4[2];
                bh[np * 2 + 1][0] = r4[1]; bh[np * 2 + 1][1] = r4[3];
                ldm_x4(r4, sKl + eo2);
                bl[np * 2][0] = r4[0]; bl[np * 2][1] = r4[2];
                bl[np * 2 + 1][0] = r4[1]; bl[np * 2 + 1][1] = r4[3];
            }
#pragma unroll
            for (int n = 0; n < 8; n++)
                mma_bf16(sacc[n], ah, bh[n][0], bh[n][1]);
#pragma unroll
            for (int n = 0; n < 8; n++)
                mma_bf16(sacc[n], ah, bl[n][0], bl[n][1]);
#pragma unroll
            for (int n = 0; n < 8; n++)
                mma_bf16(sacc[n], al, bh[n][0], bh[n][1]);
        }

        // ---- online softmax ----
        float mx0 = sacc[0][0], mx1 = sacc[0][2];
#pragma unroll
        for (int n = 0; n < 8; n++) {
            mx0 = fmaxf(mx0, fmaxf(sacc[n][0], sacc[n][1]));
            mx1 = fmaxf(mx1, fmaxf(sacc[n][2], sacc[n][3]));
        }
        mx0 = fmaxf(mx0, __shfl_xor_sync(0xffffffffu, mx0, 1));
        mx0 = fmaxf(mx0, __shfl_xor_sync(0xffffffffu, mx0, 2));
        mx1 = fmaxf(mx1, __shfl_xor_sync(0xffffffffu, mx1, 1));
        mx1 = fmaxf(mx1, __shfl_xor_sync(0xffffffffu, mx1, 2));
        float mn0 = fmaxf(m0, mx0), mn1 = fmaxf(m1, mx1);
        float c0 = __expf(m0 - mn0), c1 = __expf(m1 - mn1);
        m0 = mn0; m1 = mn1;
        l0 *= c0; l1 *= c1;
#pragma unroll
        for (int n = 0; n < 8; n++) {
            oacc[n][0] *= c0; oacc[n][1] *= c0;
            oacc[n][2] *= c1; oacc[n][3] *= c1;
        }

        // ---- P = exp(S-m) -> A fragments; O += P V (4 k16 chunks) ----
        float sum0 = 0.f, sum1 = 0.f;
#pragma unroll
        for (int t = 0; t < 4; t++) {
            float p0 = __expf(sacc[2 * t][0] - m0);
            float p1 = __expf(sacc[2 * t][1] - m0);
            float p2 = __expf(sacc[2 * t][2] - m1);
            float p3 = __expf(sacc[2 * t][3] - m1);
            float p4 = __expf(sacc[2 * t + 1][0] - m0);
            float p5 = __expf(sacc[2 * t + 1][1] - m0);
            float p6 = __expf(sacc[2 * t + 1][2] - m1);
            float p7 = __expf(sacc[2 * t + 1][3] - m1);
            sum0 += (p0 + p1) + (p4 + p5);
            sum1 += (p2 + p3) + (p6 + p7);

            unsigned aph[4], apl[4];
            aph[0] = bfpack(p0, p1);
            aph[1] = bfpack(p2, p3);
            aph[2] = bfpack(p4, p5);
            aph[3] = bfpack(p6, p7);
            float r0 = p0 - __bfloat162float(__float2bfloat16(p0));
            float r1 = p1 - __bfloat162float(__float2bfloat16(p1));
            float r2 = p2 - __bfloat162float(__float2bfloat16(p2));
            float r3 = p3 - __bfloat162float(__float2bfloat16(p3));
            float r4f = p4 - __bfloat162float(__float2bfloat16(p4));
            float r5 = p5 - __bfloat162float(__float2bfloat16(p5));
            float r6 = p6 - __bfloat162float(__float2bfloat16(p6));
            float r7 = p7 - __bfloat162float(__float2bfloat16(p7));
            apl[0] = bfpack(r0, r1);
            apl[1] = bfpack(r2, r3);
            apl[2] = bfpack(r4f, r5);
            apl[3] = bfpack(r6, r7);

            unsigned vh[8][2], vl[8][2];
#pragma unroll
            for (int np = 0; np < 4; np++) {
                unsigned eo2 = ((rowB + np * 16) * 72 + kHalf + 16 * t) * 2;
                unsigned v4[4];
                ldm_x4(v4, sVh + eo2);
                vh[np * 2][0] = v4[0]; vh[np * 2][1] = v4[2];
                vh[np * 2 + 1][0] = v4[1]; vh[np * 2 + 1][1] = v4[3];
                ldm_x4(v4, sVl + eo2);
                vl[np * 2][0] = v4[0]; vl[np * 2][1] = v4[2];
                vl[np * 2 + 1][0] = v4[1]; vl[np * 2 + 1][1] = v4[3];
            }
#pragma unroll
            for (int n = 0; n < 8; n++)
                mma_bf16(oacc[n], aph, vh[n][0], vh[n][1]);
#pragma unroll
            for (int n = 0; n < 8; n++)
                mma_bf16(oacc[n], aph, vl[n][0], vl[n][1]);
#pragma unroll
            for (int n = 0; n < 8; n++)
                mma_bf16(oacc[n], apl, vh[n][0], vh[n][1]);
        }
        sum0 += __shfl_xor_sync(0xffffffffu, sum0, 1);
        sum0 += __shfl_xor_sync(0xffffffffu, sum0, 2);
        sum1 += __shfl_xor_sync(0xffffffffu, sum1, 1);
        sum1 += __shfl_xor_sync(0xffffffffu, sum1, 2);
        l0 += sum0; l1 += sum1;

        if (kt + 1 < 16) CP_WAIT0;
        __syncthreads();
    }

    // ---- epilogue: normalize, stage [q][65], coalesced [d][l] write ----
    float* sOut = (float*)smraw;
    float il0 = 1.f / l0, il1 = 1.f / l1;
    int r0q = wid * 16 + (lane >> 2);
#pragma unroll
    for (int n = 0; n < 8; n++) {
        int d = n * 8 + (lane & 3) * 2;
        sOut[r0q * 65 + d]           = oacc[n][0] * il0;
        sOut[r0q * 65 + d + 1]       = oacc[n][1] * il0;
        sOut[(r0q + 8) * 65 + d]     = oacc[n][2] * il1;
        sOut[(r0q + 8) * 65 + d + 1] = oacc[n][3] * il1;
    }
    __syncthreads();

    float* op = outm + ((long)b * CH + h * 64) * LPIX + qt * 128;
#pragma unroll
    for (int it = 0; it < 32; it++) {
        int f = tid + it * 256;
        int d = f >> 7, l = f & 127;
        op[(long)d * LPIX + l] = sOut[l * 65 + d];
    }
}

// ---------------------------------------------------------------------------
// Depthwise 3x3 conv (+BN), accumulated into g_mid.
// ---------------------------------------------------------------------------
__global__ __launch_bounds__(1024)
void dw_kernel(const float* __restrict__ qkv, const float* __restrict__ w,
               const float* __restrict__ s, const float* __restrict__ bb,
               float* __restrict__ outm)
{
    const int c = blockIdx.x & 255;
    const int b = blockIdx.x >> 8;
    const int t = threadIdx.x;
    const int y = t >> 5, x = t & 31;
    const int h = c >> 6, d = c & 63;
    const float* vp = qkv + ((long)b * CQKV + h * 128 + 64 + d) * LPIX;

    __shared__ float tile[34][34];
    tile[y + 1][x + 1] = vp[t];
    if (t < 34) {
        tile[0][t] = 0.f; tile[33][t] = 0.f;
        tile[t][0] = 0.f; tile[t][33] = 0.f;
    }
    __syncthreads();

    float acc = 0.f;
#pragma unroll
    for (int ky = 0; ky < 3; ky++)
#pragma unroll
        for (int kx = 0; kx < 3; kx++)
            acc = fmaf(tile[y + ky][x + kx], w[c * 9 + ky * 3 + kx], acc);

    outm[((long)b * CH + c) * LPIX + t] += acc * s[c] + bb[c];
}

// ---------------------------------------------------------------------------
extern "C" void kernel_launch(void* const* d_in, const int* in_sizes, int n_in,
                              void* d_out, int out_size)
{
    const float* x     = (const float*)d_in[0];
    const float* w_qkv = (const float*)d_in[1];
    const float* s_qkv = (const float*)d_in[2];
    const float* b_qkv = (const float*)d_in[3];
    const float* w_dw  = (const float*)d_in[4];
    const float* s_dw  = (const float*)d_in[5];
    const float* b_dw  = (const float*)d_in[6];
    const float* w_pw  = (const float*)d_in[7];
    const float* s_pw  = (const float*)d_in[8];
    const float* b_pw  = (const float*)d_in[9];
    float* out = (float*)d_out;

    float *qkvbuf = nullptr, *midbuf = nullptr;
    cudaGetSymbolAddress((void**)&qkvbuf, g_qkv);
    cudaGetSymbolAddress((void**)&midbuf, g_mid);
    bf16 *wqh, *wql, *wph, *wpl, *xth, *xtl, *mth, *mtl;
    cudaGetSymbolAddress((void**)&wqh, g_wqh);
    cudaGetSymbolAddress((void**)&wql, g_wql);
    cudaGetSymbolAddress((void**)&wph, g_wph);
    cudaGetSymbolAddress((void**)&wpl, g_wpl);
    cudaGetSymbolAddress((void**)&xth, g_xth);
    cudaGetSymbolAddress((void**)&xtl, g_xtl);
    cudaGetSymbolAddress((void**)&mth, g_mth);
    cudaGetSymbolAddress((void**)&mtl, g_mtl);

    cudaFuncSetAttribute(attn_hmma, cudaFuncAttributeMaxDynamicSharedMemorySize, AT_SMEM);
    cudaFuncSetAttribute(hmma_gemm_bn, cudaFuncAttributeMaxDynamicSharedMemorySize, G2_SMEM);

    // Prep: split weights; transpose+split x
    split_w_kernel<<<(CQKV * CH + 255) / 256, 256>>>(w_qkv, wqh, wql, CQKV * CH);
    split_w_kernel<<<(CH * CH + 255) / 256, 256>>>(w_pw, wph, wpl, CH * CH);
    split_t_kernel<<<dim3(LPIX / 64, CH / 64, BATCH), 256>>>(x, xth, xtl, CH, LPIX);

    // 1) qkv = bn(W_qkv @ x)
    hmma_gemm_bn<<<dim3(8, 4, 16), 256, G2_SMEM>>>(wqh, wql, xth, xtl, qkvbuf,
                                                   s_qkv, b_qkv, CQKV, LPIX, CH);
    // 2) pre-split attention operands
    split_qkv_kernel<<<dim3(8, 4, 16), 256>>>(qkvbuf);
    // 3) attention -> g_mid
    attn_hmma<<<dim3(8, 4, 16), 256, AT_SMEM>>>(midbuf);
    // 4) g_mid += bn(dwconv3(v))
    dw_kernel<<<dim3(BATCH * CH), 1024>>>(qkvbuf, w_dw, s_dw, b_dw, midbuf);
    // 5) transpose+split mid, then out = bn(W_pw @ g_mid)
    split_t_kernel<<<dim3(LPIX / 64, CH / 64, BATCH), 256>>>(midbuf, mth, mtl, CH, LPIX);
    hmma_gemm_bn<<<dim3(8, 2, 16), 256, G2_SMEM>>>(wph, wpl, mth, mtl, out,
                                                   s_pw, b_pw, CH, LPIX, CH);
}

// round 12
// speedup vs baseline: 2.5547x; 1.0546x over previous
#include <cuda_runtime.h>
#include <cuda_bf16.h>
#include <math.h>

// Problem constants
#define BATCH 16
#define CH    256
#define NH    4
#define DH    64
#define LPIX  1024
#define CQKV  512
#define SCALE 0.17677669529663687f   // 32^-0.5

typedef unsigned long long u64;
typedef __nv_bfloat16 bf16;

__device__ __forceinline__ unsigned smem_u32(const void* p) {
    unsigned r;
    asm("{ .reg .u64 t; cvta.to.shared.u64 t, %1; cvt.u32.u64 %0, t; }" : "=r"(r) : "l"(p));
    return r;
}

// ---------------- mma.sync + cp.async helpers ----------------
__device__ __forceinline__ void ldm_x4(unsigned* r, unsigned addr) {
    asm volatile("ldmatrix.sync.aligned.m8n8.x4.shared.b16 {%0,%1,%2,%3}, [%4];"
                 : "=r"(r[0]), "=r"(r[1]), "=r"(r[2]), "=r"(r[3]) : "r"(addr));
}
__device__ __forceinline__ void mma_bf16(float* c, const unsigned* a, unsigned b0, unsigned b1) {
    asm volatile(
        "mma.sync.aligned.m16n8k16.row.col.f32.bf16.bf16.f32 "
        "{%0,%1,%2,%3}, {%4,%5,%6,%7}, {%8,%9}, {%0,%1,%2,%3};"
        : "+f"(c[0]), "+f"(c[1]), "+f"(c[2]), "+f"(c[3])
        : "r"(a[0]), "r"(a[1]), "r"(a[2]), "r"(a[3]), "r"(b0), "r"(b1));
}
__device__ __forceinline__ unsigned bfpack(float lo, float hi) {
    unsigned r;
    asm("cvt.rn.bf16x2.f32 %0, %1, %2;" : "=r"(r) : "f"(hi), "f"(lo));
    return r;
}
__device__ __forceinline__ void cpa16(unsigned dst, const void* src) {
    asm volatile("cp.async.ca.shared.global [%0], [%1], 16;" :: "r"(dst), "l"(src));
}
#define CP_COMMIT asm volatile("cp.async.commit_group;" ::: "memory")
#define CP_WAIT0  asm volatile("cp.async.wait_group 0;" ::: "memory")

// ---------------- scratch (allocation-free: __device__ globals) ----------------
__device__ float g_mid[(long)BATCH * CH * LPIX];     // [b][c][l]  (dw output)
__device__ bf16 g_wqh[CQKV * CH], g_wql[CQKV * CH];
__device__ bf16 g_wph[CH * CH],   g_wpl[CH * CH];
__device__ bf16 g_xth[(long)BATCH * LPIX * CH], g_xtl[(long)BATCH * LPIX * CH];
__device__ bf16 g_mth[(long)BATCH * LPIX * CH], g_mtl[(long)BATCH * LPIX * CH];
// Pre-split attention operands: Q/K [bh][l][32], V [bh][d][1024]
__device__ bf16 g_qh[(long)64 * LPIX * 32], g_ql[(long)64 * LPIX * 32];
__device__ bf16 g_kh[(long)64 * LPIX * 32], g_kl[(long)64 * LPIX * 32];
__device__ bf16 g_vh[(long)64 * 64 * LPIX], g_vl[(long)64 * 64 * LPIX];

// ---------------------------------------------------------------------------
// Split fp32 -> bf16 hi/lo (elementwise; layout preserved)
// ---------------------------------------------------------------------------
__global__ void split_w_kernel(const float* __restrict__ w,
                               bf16* __restrict__ h, bf16* __restrict__ l, int n)
{
    int i = blockIdx.x * 256 + threadIdx.x;
    if (i < n) {
        float v = w[i];
        bf16 hh = __float2bfloat16(v);
        h[i] = hh;
        l[i] = __float2bfloat16(v - __bfloat162float(hh));
    }
}

// ---------------------------------------------------------------------------
// Transpose + split: X[b][k][n] fp32 -> T[b][n][k] bf16 hi/lo. 64x64 tiles.
// ---------------------------------------------------------------------------
__global__ __launch_bounds__(256)
void split_t_kernel(const float* __restrict__ X,
                    bf16* __restrict__ Th, bf16* __restrict__ Tl, int K, int N)
{
    __shared__ float t[64][65];
    const int n0 = blockIdx.x * 64;
    const int k0 = blockIdx.y * 64;
    const long b = blockIdx.z;
    const float* Xb = X + b * (long)K * N;
    bf16* ThB = Th + b * (long)K * N;
    bf16* TlB = Tl + b * (long)K * N;
    const int tx = threadIdx.x & 63, ty = threadIdx.x >> 6;

#pragma unroll
    for (int i = 0; i < 16; i++)
        t[ty + i * 4][tx] = Xb[(long)(k0 + ty + i * 4) * N + n0 + tx];
    __syncthreads();

#pragma unroll
    for (int i = 0; i < 16; i++) {
        int n = ty + i * 4;
        float v = t[tx][n];
        bf16 hh = __float2bfloat16(v);
        ThB[(long)(n0 + n) * K + k0 + tx] = hh;
        TlB[(long)(n0 + n) * K + k0 + tx] = __float2bfloat16(v - __bfloat162float(hh));
    }
}

// ---------------------------------------------------------------------------
// HMMA bf16-split GEMM mainloop macro-shared pieces (identical to best round).
// ---------------------------------------------------------------------------
#define G2_PAD   40
#define G2_TILEB 10240
#define G2_STAGE 40960
#define G2_SMEM  81920

// Generic GEMM + BN -> fp32 out (used for pw projection).
__global__ __launch_bounds__(256, 2)
void hmma_gemm_bn(const bf16* __restrict__ Ah, const bf16* __restrict__ Al,
                  const bf16* __restrict__ Bh, const bf16* __restrict__ Bl,
                  float* __restrict__ Y, const float* __restrict__ scale,
                  const float* __restrict__ bias, int M, int N, int K)
{
    extern __shared__ char smem[];
    const unsigned sb = smem_u32(smem);
    const int tid = threadIdx.x;
    const int wid = tid >> 5, lane = tid & 31;
    const int wm = wid & 3, wn = wid >> 2;
    const int n0 = blockIdx.x * 128;
    const int m0 = blockIdx.y * 128;
    const long bz = blockIdx.z;
    const bf16* Bhb = Bh + bz * (long)N * K;
    const bf16* Blb = Bl + bz * (long)N * K;
    float* Yb = Y + bz * (long)M * N;

    float acc[2][8][4];
#pragma unroll
    for (int mi = 0; mi < 2; mi++)
#pragma unroll
        for (int ni = 0; ni < 8; ni++)
#pragma unroll
            for (int j = 0; j < 4; j++) acc[mi][ni][j] = 0.f;

    const unsigned aRow = (unsigned)(wm * 32 + (lane & 15));
    const unsigned bRow = (unsigned)(wn * 64 + (lane & 15));
    const unsigned kHalf = (unsigned)((lane >> 4) * 8);

    auto load_chunk = [&](int st, int kc) {
        unsigned db = sb + st * G2_STAGE;
#pragma unroll
        for (int i = 0; i < 2; i++) {
            int f = tid + i * 256;
            int r = f >> 2, c4 = f & 3;
            unsigned d0 = db + r * 80 + c4 * 16;
            cpa16(d0,                 Ah  + (long)(m0 + r) * K + kc + c4 * 8);
            cpa16(d0 + G2_TILEB,      Al  + (long)(m0 + r) * K + kc + c4 * 8);
            cpa16(d0 + 2 * G2_TILEB,  Bhb + (long)(n0 + r) * K + kc + c4 * 8);
            cpa16(d0 + 3 * G2_TILEB,  Blb + (long)(n0 + r) * K + kc + c4 * 8);
        }
    };

    const int NCH = K / 32;
    load_chunk(0, 0);
    CP_COMMIT;
    CP_WAIT0;
    __syncthreads();

    for (int c = 0; c < NCH; c++) {
        const int st = c & 1;
        if (c + 1 < NCH) { load_chunk(1 - st, (c + 1) * 32); CP_COMMIT; }

        unsigned base = sb + st * G2_STAGE;
#pragma unroll
        for (int k16 = 0; k16 < 32; k16 += 16) {
            unsigned ah[2][4], al[2][4];
#pragma unroll
            for (int mi = 0; mi < 2; mi++) {
                unsigned eo = ((aRow + mi * 16) * G2_PAD + kHalf + k16) * 2;
                ldm_x4(ah[mi], base + eo);
                ldm_x4(al[mi], base + G2_TILEB + eo);
            }
            unsigned bh[8][2], bl[8][2];
#pragma unroll
            for (int np = 0; np < 4; np++) {
                unsigned eo = ((bRow + np * 16) * G2_PAD + kHalf + k16) * 2;
                unsigned r4[4];
                ldm_x4(r4, base + 2 * G2_TILEB + eo);
                bh[np * 2][0] = r4[0]; bh[np * 2][1] = r4[2];
                bh[np * 2 + 1][0] = r4[1]; bh[np * 2 + 1][1] = r4[3];
                ldm_x4(r4, base + 3 * G2_TILEB + eo);
                bl[np * 2][0] = r4[0]; bl[np * 2][1] = r4[2];
                bl[np * 2 + 1][0] = r4[1]; bl[np * 2 + 1][1] = r4[3];
            }
#pragma unroll
            for (int mi = 0; mi < 2; mi++)
#pragma unroll
                for (int ni = 0; ni < 8; ni++)
                    mma_bf16(acc[mi][ni], ah[mi], bh[ni][0], bh[ni][1]);
#pragma unroll
            for (int mi = 0; mi < 2; mi++)
#pragma unroll
                for (int ni = 0; ni < 8; ni++)
                    mma_bf16(acc[mi][ni], ah[mi], bl[ni][0], bl[ni][1]);
#pragma unroll
            for (int mi = 0; mi < 2; mi++)
#pragma unroll
                for (int ni = 0; ni < 8; ni++)
                    mma_bf16(acc[mi][ni], al[mi], bh[ni][0], bh[ni][1]);
        }
        if (c + 1 < NCH) CP_WAIT0;
        __syncthreads();
    }

#pragma unroll
    for (int mi = 0; mi < 2; mi++) {
        int r1 = m0 + wm * 32 + mi * 16 + (lane >> 2);
        int r2 = r1 + 8;
        float s1 = scale[r1], b1 = bias[r1];
        float s2 = scale[r2], b2 = bias[r2];
        float* y1 = &Yb[(long)r1 * N + n0 + wn * 64 + (lane & 3) * 2];
        float* y2 = &Yb[(long)r2 * N + n0 + wn * 64 + (lane & 3) * 2];
#pragma unroll
        for (int ni = 0; ni < 8; ni++) {
            float2 o1, o2;
            o1.x = acc[mi][ni][0] * s1 + b1;
            o1.y = acc[mi][ni][1] * s1 + b1;
            o2.x = acc[mi][ni][2] * s2 + b2;
            o2.y = acc[mi][ni][3] * s2 + b2;
            *reinterpret_cast<float2*>(y1 + ni * 8) = o1;
            *reinterpret_cast<float2*>(y2 + ni * 8) = o2;
        }
    }
}

// ---------------------------------------------------------------------------
// qkv GEMM with FUSED split epilogue: writes Q/K [l][32] hi/lo (Q pre-scaled)
// and V [d][l] hi/lo directly. blockIdx.y = head. Mainloop identical.
// ---------------------------------------------------------------------------
__global__ __launch_bounds__(256, 2)
void hmma_qkv(const bf16* __restrict__ Ah, const bf16* __restrict__ Al,
              const bf16* __restrict__ Bh, const bf16* __restrict__ Bl,
              const float* __restrict__ scale, const float* __restrict__ bias)
{
    extern __shared__ char smem[];
    const unsigned sb = smem_u32(smem);
    const int tid = threadIdx.x;
    const int wid = tid >> 5, lane = tid & 31;
    const int wm = wid & 3, wn = wid >> 2;
    const int n0 = blockIdx.x * 128;
    const int m0 = blockIdx.y * 128;     // head h = blockIdx.y
    const long bz = blockIdx.z;
    const int K = CH, N = LPIX;
    const bf16* Bhb = Bh + bz * (long)N * K;
    const bf16* Blb = Bl + bz * (long)N * K;

    float acc[2][8][4];
#pragma unroll
    for (int mi = 0; mi < 2; mi++)
#pragma unroll
        for (int ni = 0; ni < 8; ni++)
#pragma unroll
            for (int j = 0; j < 4; j++) acc[mi][ni][j] = 0.f;

    const unsigned aRow = (unsigned)(wm * 32 + (lane & 15));
    const unsigned bRow = (unsigned)(wn * 64 + (lane & 15));
    const unsigned kHalf = (unsigned)((lane >> 4) * 8);

    auto load_chunk = [&](int st, int kc) {
        unsigned db = sb + st * G2_STAGE;
#pragma unroll
        for (int i = 0; i < 2; i++) {
            int f = tid + i * 256;
            int r = f >> 2, c4 = f & 3;
            unsigned d0 = db + r * 80 + c4 * 16;
            cpa16(d0,                 Ah  + (long)(m0 + r) * K + kc + c4 * 8);
            cpa16(d0 + G2_TILEB,      Al  + (long)(m0 + r) * K + kc + c4 * 8);
            cpa16(d0 + 2 * G2_TILEB,  Bhb + (long)(n0 + r) * K + kc + c4 * 8);
            cpa16(d0 + 3 * G2_TILEB,  Blb + (long)(n0 + r) * K + kc + c4 * 8);
        }
    };

    const int NCH = K / 32;
    load_chunk(0, 0);
    CP_COMMIT;
    CP_WAIT0;
    __syncthreads();

    for (int c = 0; c < NCH; c++) {
        const int st = c & 1;
        if (c + 1 < NCH) { load_chunk(1 - st, (c + 1) * 32); CP_COMMIT; }

        unsigned base = sb + st * G2_STAGE;
#pragma unroll
        for (int k16 = 0; k16 < 32; k16 += 16) {
            unsigned ah[2][4], al[2][4];
#pragma unroll
            for (int mi = 0; mi < 2; mi++) {
                unsigned eo = ((aRow + mi * 16) * G2_PAD + kHalf + k16) * 2;
                ldm_x4(ah[mi], base + eo);
                ldm_x4(al[mi], base + G2_TILEB + eo);
            }
            unsigned bh[8][2], bl[8][2];
#pragma unroll
            for (int np = 0; np < 4; np++) {
                unsigned eo = ((bRow + np * 16) * G2_PAD + kHalf + k16) * 2;
                unsigned r4[4];
                ldm_x4(r4, base + 2 * G2_TILEB + eo);
                bh[np * 2][0] = r4[0]; bh[np * 2][1] = r4[2];
                bh[np * 2 + 1][0] = r4[1]; bh[np * 2 + 1][1] = r4[3];
                ldm_x4(r4, base + 3 * G2_TILEB + eo);
                bl[np * 2][0] = r4[0]; bl[np * 2][1] = r4[2];
                bl[np * 2 + 1][0] = r4[1]; bl[np * 2 + 1][1] = r4[3];
            }
#pragma unroll
            for (int mi = 0; mi < 2; mi++)
#pragma unroll
                for (int ni = 0; ni < 8; ni++)
                    mma_bf16(acc[mi][ni], ah[mi], bh[ni][0], bh[ni][1]);
#pragma unroll
            for (int mi = 0; mi < 2; mi++)
#pragma unroll
                for (int ni = 0; ni < 8; ni++)
                    mma_bf16(acc[mi][ni], ah[mi], bl[ni][0], bl[ni][1]);
#pragma unroll
            for (int mi = 0; mi < 2; mi++)
#pragma unroll
                for (int ni = 0; ni < 8; ni++)
                    mma_bf16(acc[mi][ni], al[mi], bh[ni][0], bh[ni][1]);
        }
        if (c + 1 < NCH) CP_WAIT0;
        __syncthreads();
    }

    // ---- fused epilogue: stage BN'd tile [128][133] then split-write ----
    float* st = (float*)smem;
#pragma unroll
    for (int mi = 0; mi < 2; mi++) {
        int rl1 = wm * 32 + mi * 16 + (lane >> 2);
        int rl2 = rl1 + 8;
        float s1 = scale[m0 + rl1], b1 = bias[m0 + rl1];
        float s2 = scale[m0 + rl2], b2 = bias[m0 + rl2];
#pragma unroll
        for (int ni = 0; ni < 8; ni++) {
            int cj = wn * 64 + ni * 8 + (lane & 3) * 2;
            st[rl1 * 133 + cj]     = acc[mi][ni][0] * s1 + b1;
            st[rl1 * 133 + cj + 1] = acc[mi][ni][1] * s1 + b1;
            st[rl2 * 133 + cj]     = acc[mi][ni][2] * s2 + b2;
            st[rl2 * 133 + cj + 1] = acc[mi][ni][3] * s2 + b2;
        }
    }
    __syncthreads();

    const int bh_ = (int)bz * 4 + blockIdx.y;
    // Q rows 0..31 -> [l][32], pre-scaled
#pragma unroll
    for (int i = 0; i < 16; i++) {
        int f = tid + i * 256;
        int j = f >> 5, d = f & 31;
        float v = st[d * 133 + j] * SCALE;
        bf16 hv = __float2bfloat16(v);
        long o = ((long)bh_ * LPIX + n0 + j) * 32 + d;
        g_qh[o] = hv;
        g_ql[o] = __float2bfloat16(v - __bfloat162float(hv));
    }
    // K rows 32..63 -> [l][32]
#pragma unroll
    for (int i = 0; i < 16; i++) {
        int f = tid + i * 256;
        int j = f >> 5, d = f & 31;
        float v = st[(32 + d) * 133 + j];
        bf16 hv = __float2bfloat16(v);
        long o = ((long)bh_ * LPIX + n0 + j) * 32 + d;
        g_kh[o] = hv;
        g_kl[o] = __float2bfloat16(v - __bfloat162float(hv));
    }
    // V rows 64..127 -> [d][l]
#pragma unroll
    for (int i = 0; i < 32; i++) {
        int f = tid + i * 256;
        int d = f >> 7, j = f & 127;
        float v = st[(64 + d) * 133 + j];
        bf16 hv = __float2bfloat16(v);
        long o = ((long)bh_ * 64 + d) * LPIX + n0 + j;
        g_vh[o] = hv;
        g_vl[o] = __float2bfloat16(v - __bfloat162float(hv));
    }
}

// ---------------------------------------------------------------------------
// HMMA flash attention (mainloop identical to best round). Epilogue fuses
// mid-add and transposed split write to g_mth/g_mtl.
// ---------------------------------------------------------------------------
#define AT_SMEM 77824

__global__ __launch_bounds__(256, 2)
void attn_hmma(const float* __restrict__ midp)
{
    extern __shared__ char smraw[];
    const unsigned sb = smem_u32(smraw);
    const int tid = threadIdx.x;
    const int wid = tid >> 5, lane = tid & 31;
    const int qt = blockIdx.x, h = blockIdx.y, b = blockIdx.z;
    const int bh = b * 4 + h;

    const bf16* qh = g_qh + ((long)bh * LPIX + qt * 128) * 32;
    const bf16* ql = g_ql + ((long)bh * LPIX + qt * 128) * 32;
    const bf16* khp = g_kh + (long)bh * LPIX * 32;
    const bf16* klp = g_kl + (long)bh * LPIX * 32;
    const bf16* vhp = g_vh + (long)bh * 64 * LPIX;
    const bf16* vlp = g_vl + (long)bh * 64 * LPIX;

#pragma unroll
    for (int i = 0; i < 2; i++) {
        int f = tid + i * 256;
        int r = f >> 2, c4 = f & 3;
        cpa16(sb + r * 80 + c4 * 16,         qh + r * 32 + c4 * 8);
        cpa16(sb + 10240 + r * 80 + c4 * 16, ql + r * 32 + c4 * 8);
    }

    auto load_kv = [&](int st, int kt) {
        unsigned kb = sb + 20480 + st * 10240;
        unsigned vb = sb + 40960 + st * 18432;
        {
            int r = tid >> 2, c4 = tid & 3;
            cpa16(kb + r * 80 + c4 * 16,        khp + (long)(kt * 64 + r) * 32 + c4 * 8);
            cpa16(kb + 5120 + r * 80 + c4 * 16, klp + (long)(kt * 64 + r) * 32 + c4 * 8);
        }
#pragma unroll
        for (int i = 0; i < 2; i++) {
            int f = tid + i * 256;
            int d = f >> 3, j8 = f & 7;
            cpa16(vb + d * 144 + j8 * 16,        vhp + (long)d * LPIX + kt * 64 + j8 * 8);
            cpa16(vb + 9216 + d * 144 + j8 * 16, vlp + (long)d * LPIX + kt * 64 + j8 * 8);
        }
    };

    load_kv(0, 0);
    CP_COMMIT;
    CP_WAIT0;
    __syncthreads();

    float oacc[8][4];
#pragma unroll
    for (int n = 0; n < 8; n++)
#pragma unroll
        for (int j = 0; j < 4; j++) oacc[n][j] = 0.f;
    float m0 = -INFINITY, m1 = -INFINITY, l0 = 0.f, l1 = 0.f;

    const unsigned rowA = (unsigned)(wid * 16 + (lane & 15));
    const unsigned rowB = (unsigned)(lane & 15);
    const unsigned kHalf = (unsigned)((lane >> 4) * 8);

    for (int kt = 0; kt < 16; kt++) {
        const int st = kt & 1;
        if (kt + 1 < 16) { load_kv(1 - st, kt + 1); CP_COMMIT; }

        const unsigned sKh = sb + 20480 + st * 10240;
        const unsigned sKl = sKh + 5120;
        const unsigned sVh = sb + 40960 + st * 18432;
        const unsigned sVl = sVh + 9216;

        float sacc[8][4];
#pragma unroll
        for (int n = 0; n < 8; n++)
#pragma unroll
            for (int j = 0; j < 4; j++) sacc[n][j] = 0.f;

#pragma unroll
        for (int t = 0; t < 2; t++) {
            unsigned ah[4], al[4];
            unsigned eo = (rowA * 40 + kHalf + 16 * t) * 2;
            ldm_x4(ah, sb + eo);
            ldm_x4(al, sb + 10240 + eo);
            unsigned bh2[8][2], bl2[8][2];
#pragma unroll
            for (int np = 0; np < 4; np++) {
                unsigned eo2 = ((rowB + np * 16) * 40 + kHalf + 16 * t) * 2;
                unsigned r4[4];
                ldm_x4(r4, sKh + eo2);
                bh2[np * 2][0] = r4[0]; bh2[np * 2][1] = r4[2];
                bh2[np * 2 + 1][0] = r4[1]; bh2[np * 2 + 1][1] = r4[3];
                ldm_x4(r4, sKl + eo2);
                bl2[np * 2][0] = r4[0]; bl2[np * 2][1] = r4[2];
                bl2[np * 2 + 1][0] = r4[1]; bl2[np * 2 + 1][1] = r4[3];
            }
#pragma unroll
            for (int n = 0; n < 8; n++)
                mma_bf16(sacc[n], ah, bh2[n][0], bh2[n][1]);
#pragma unroll
            for (int n = 0; n < 8; n++)
                mma_bf16(sacc[n], ah, bl2[n][0], bl2[n][1]);
#pragma unroll
            for (int n = 0; n < 8; n++)
                mma_bf16(sacc[n], al, bh2[n][0], bh2[n][1]);
        }

        float mx0 = sacc[0][0], mx1 = sacc[0][2];
#pragma unroll
        for (int n = 0; n < 8; n++) {
            mx0 = fmaxf(mx0, fmaxf(sacc[n][0], sacc[n][1]));
            mx1 = fmaxf(mx1, fmaxf(sacc[n][2], sacc[n][3]));
        }
        mx0 = fmaxf(mx0, __shfl_xor_sync(0xffffffffu, mx0, 1));
        mx0 = fmaxf(mx0, __shfl_xor_sync(0xffffffffu, mx0, 2));
        mx1 = fmaxf(mx1, __shfl_xor_sync(0xffffffffu, mx1, 1));
        mx1 = fmaxf(mx1, __shfl_xor_sync(0xffffffffu, mx1, 2));
        float mn0 = fmaxf(m0, mx0), mn1 = fmaxf(m1, mx1);
        float c0 = __expf(m0 - mn0), c1 = __expf(m1 - mn1);
        m0 = mn0; m1 = mn1;
        l0 *= c0; l1 *= c1;
#pragma unroll
        for (int n = 0; n < 8; n++) {
            oacc[n][0] *= c0; oacc[n][1] *= c0;
            oacc[n][2] *= c1; oacc[n][3] *= c1;
        }

        float sum0 = 0.f, sum1 = 0.f;
#pragma unroll
        for (int t = 0; t < 4; t++) {
            float p0 = __expf(sacc[2 * t][0] - m0);
            float p1 = __expf(sacc[2 * t][1] - m0);
            float p2 = __expf(sacc[2 * t][2] - m1);
            float p3 = __expf(sacc[2 * t][3] - m1);
            float p4 = __expf(sacc[2 * t + 1][0] - m0);
            float p5 = __expf(sacc[2 * t + 1][1] - m0);
            float p6 = __expf(sacc[2 * t + 1][2] - m1);
            float p7 = __expf(sacc[2 * t + 1][3] - m1);
            sum0 += (p0 + p1) + (p4 + p5);
            sum1 += (p2 + p3) + (p6 + p7);

            unsigned aph[4], apl[4];
            aph[0] = bfpack(p0, p1);
            aph[1] = bfpack(p2, p3);
            aph[2] = bfpack(p4, p5);
            aph[3] = bfpack(p6, p7);
            float r0 = p0 - __bfloat162float(__float2bfloat16(p0));
            float r1 = p1 - __bfloat162float(__float2bfloat16(p1));
            float r2 = p2 - __bfloat162float(__float2bfloat16(p2));
            float r3 = p3 - __bfloat162float(__float2bfloat16(p3));
            float r4f = p4 - __bfloat162float(__float2bfloat16(p4));
            float r5 = p5 - __bfloat162float(__float2bfloat16(p5));
            float r6 = p6 - __bfloat162float(__float2bfloat16(p6));
            float r7 = p7 - __bfloat162float(__float2bfloat16(p7));
            apl[0] = bfpack(r0, r1);
            apl[1] = bfpack(r2, r3);
            apl[2] = bfpack(r4f, r5);
            apl[3] = bfpack(r6, r7);

            unsigned vh2[8][2], vl2[8][2];
#pragma unroll
            for (int np = 0; np < 4; np++) {
                unsigned eo2 = ((rowB + np * 16) * 72 + kHalf + 16 * t) * 2;
                unsigned v4[4];
                ldm_x4(v4, sVh + eo2);
                vh2[np * 2][0] = v4[0]; vh2[np * 2][1] = v4[2];
                vh2[np * 2 + 1][0] = v4[1]; vh2[np * 2 + 1][1] = v4[3];
                ldm_x4(v4, sVl + eo2);
                vl2[np * 2][0] = v4[0]; vl2[np * 2][1] = v4[2];
                vl2[np * 2 + 1][0] = v4[1]; vl2[np * 2 + 1][1] = v4[3];
            }
#pragma unroll
            for (int n = 0; n < 8; n++)
                mma_bf16(oacc[n], aph, vh2[n][0], vh2[n][1]);
#pragma unroll
            for (int n = 0; n < 8; n++)
                mma_bf16(oacc[n], aph, vl2[n][0], vl2[n][1]);
#pragma unroll
            for (int n = 0; n < 8; n++)
                mma_bf16(oacc[n], apl, vh2[n][0], vh2[n][1]);
        }
        sum0 += __shfl_xor_sync(0xffffffffu, sum0, 1);
        sum0 += __shfl_xor_sync(0xffffffffu, sum0, 2);
        sum1 += __shfl_xor_sync(0xffffffffu, sum1, 1);
        sum1 += __shfl_xor_sync(0xffffffffu, sum1, 2);
        l0 += sum0; l1 += sum1;

        if (kt + 1 < 16) CP_WAIT0;
        __syncthreads();
    }

    // ---- epilogue: normalize -> sOut[l][65]; += mid; write mth/mtl split ----
    float* sOut = (float*)smraw;
    float il0 = 1.f / l0, il1 = 1.f / l1;
    int r0q = wid * 16 + (lane >> 2);
#pragma unroll
    for (int n = 0; n < 8; n++) {
        int d = n * 8 + (lane & 3) * 2;
        sOut[r0q * 65 + d]           = oacc[n][0] * il0;
        sOut[r0q * 65 + d + 1]       = oacc[n][1] * il0;
        sOut[(r0q + 8) * 65 + d]     = oacc[n][2] * il1;
        sOut[(r0q + 8) * 65 + d + 1] = oacc[n][3] * il1;
    }
    __syncthreads();

    const float* mp = midp + ((long)b * CH + h * 64) * LPIX + qt * 128;
#pragma unroll
    for (int it = 0; it < 32; it++) {
        int f = tid + it * 256;
        int d = f >> 7, l = f & 127;
        sOut[l * 65 + d] += mp[(long)d * LPIX + l];
    }
    __syncthreads();

    bf16* th = g_mth + ((long)b * LPIX + qt * 128) * CH + h * 64;
    bf16* tl = g_mtl + ((long)b * LPIX + qt * 128) * CH + h * 64;
#pragma unroll
    for (int it = 0; it < 32; it++) {
        int f = tid + it * 256;
        int l = f >> 6, d = f & 63;
        float v = sOut[l * 65 + d];
        bf16 hv = __float2bfloat16(v);
        th[(long)l * CH + d] = hv;
        tl[(long)l * CH + d] = __float2bfloat16(v - __bfloat162float(hv));
    }
}

// ---------------------------------------------------------------------------
// Depthwise 3x3 conv (+BN) from split V -> writes g_mid (first writer).
// ---------------------------------------------------------------------------
__global__ __launch_bounds__(1024)
void dw_kernel(const float* __restrict__ w,
               const float* __restrict__ s, const float* __restrict__ bb,
               float* __restrict__ outm)
{
    const int c = blockIdx.x & 255;
    const int b = blockIdx.x >> 8;
    const int t = threadIdx.x;
    const int y = t >> 5, x = t & 31;
    const int h = c >> 6, d = c & 63;
    const long vo = ((long)(b * 4 + h) * 64 + d) * LPIX;

    __shared__ float tile[34][34];
    tile[y + 1][x + 1] = __bfloat162float(g_vh[vo + t]) + __bfloat162float(g_vl[vo + t]);
    if (t < 34) {
        tile[0][t] = 0.f; tile[33][t] = 0.f;
        tile[t][0] = 0.f; tile[t][33] = 0.f;
    }
    __syncthreads();

    float acc = 0.f;
#pragma unroll
    for (int ky = 0; ky < 3; ky++)
#pragma unroll
        for (int kx = 0; kx < 3; kx++)
            acc = fmaf(tile[y + ky][x + kx], w[c * 9 + ky * 3 + kx], acc);

    outm[((long)b * CH + c) * LPIX + t] = acc * s[c] + bb[c];
}

// ---------------------------------------------------------------------------
extern "C" void kernel_launch(void* const* d_in, const int* in_sizes, int n_in,
                              void* d_out, int out_size)
{
    const float* x     = (const float*)d_in[0];
    const float* w_qkv = (const float*)d_in[1];
    const float* s_qkv = (const float*)d_in[2];
    const float* b_qkv = (const float*)d_in[3];
    const float* w_dw  = (const float*)d_in[4];
    const float* s_dw  = (const float*)d_in[5];
    const float* b_dw  = (const float*)d_in[6];
    const float* w_pw  = (const float*)d_in[7];
    const float* s_pw  = (const float*)d_in[8];
    const float* b_pw  = (const float*)d_in[9];
    float* out = (float*)d_out;

    float* midbuf = nullptr;
    cudaGetSymbolAddress((void**)&midbuf, g_mid);
    bf16 *wqh, *wql, *wph, *wpl, *xth, *xtl, *mth, *mtl;
    cudaGetSymbolAddress((void**)&wqh, g_wqh);
    cudaGetSymbolAddress((void**)&wql, g_wql);
    cudaGetSymbolAddress((void**)&wph, g_wph);
    cudaGetSymbolAddress((void**)&wpl, g_wpl);
    cudaGetSymbolAddress((void**)&xth, g_xth);
    cudaGetSymbolAddress((void**)&xtl, g_xtl);
    cudaGetSymbolAddress((void**)&mth, g_mth);
    cudaGetSymbolAddress((void**)&mtl, g_mtl);

    cudaFuncSetAttribute(attn_hmma, cudaFuncAttributeMaxDynamicSharedMemorySize, AT_SMEM);
    cudaFuncSetAttribute(hmma_gemm_bn, cudaFuncAttributeMaxDynamicSharedMemorySize, G2_SMEM);
    cudaFuncSetAttribute(hmma_qkv, cudaFuncAttributeMaxDynamicSharedMemorySize, G2_SMEM);

    // Prep: split weights; transpose+split x
    split_w_kernel<<<(CQKV * CH + 255) / 256, 256>>>(w_qkv, wqh, wql, CQKV * CH);
    split_w_kernel<<<(CH * CH + 255) / 256, 256>>>(w_pw, wph, wpl, CH * CH);
    split_t_kernel<<<dim3(LPIX / 64, CH / 64, BATCH), 256>>>(x, xth, xtl, CH, LPIX);

    // 1) qkv GEMM with fused split epilogue -> g_qh/ql/kh/kl/vh/vl
    hmma_qkv<<<dim3(8, 4, 16), 256, G2_SMEM>>>(wqh, wql, xth, xtl, s_qkv, b_qkv);
    // 2) mid = bn(dwconv3(v))  (from split V)
    dw_kernel<<<dim3(BATCH * CH), 1024>>>(w_dw, s_dw, b_dw, midbuf);
    // 3) attention; epilogue adds mid and writes transposed split mth/mtl
    attn_hmma<<<dim3(8, 4, 16), 256, AT_SMEM>>>(midbuf);
    // 4) out = bn(W_pw @ mid_total)
    hmma_gemm_bn<<<dim3(8, 2, 16), 256, G2_SMEM>>>(wph, wpl, mth, mtl, out,
                                                   s_pw, b_pw, CH, LPIX, CH);
}

// round 14
// speedup vs baseline: 2.6535x; 1.0387x over previous
#include <cuda_runtime.h>
#include <cuda_bf16.h>
#include <math.h>

// Problem constants
#define BATCH 16
#define CH    256
#define NH    4
#define DH    64
#define LPIX  1024
#define CQKV  512
#define SCALE 0.17677669529663687f   // 32^-0.5

typedef unsigned long long u64;
typedef __nv_bfloat16 bf16;

__device__ __forceinline__ unsigned smem_u32(const void* p) {
    unsigned r;
    asm("{ .reg .u64 t; cvta.to.shared.u64 t, %1; cvt.u32.u64 %0, t; }" : "=r"(r) : "l"(p));
    return r;
}

// ---------------- mma.sync + cp.async helpers ----------------
__device__ __forceinline__ void ldm_x4(unsigned* r, unsigned addr) {
    asm volatile("ldmatrix.sync.aligned.m8n8.x4.shared.b16 {%0,%1,%2,%3}, [%4];"
                 : "=r"(r[0]), "=r"(r[1]), "=r"(r[2]), "=r"(r[3]) : "r"(addr));
}
__device__ __forceinline__ void mma_bf16(float* c, const unsigned* a, unsigned b0, unsigned b1) {
    asm volatile(
        "mma.sync.aligned.m16n8k16.row.col.f32.bf16.bf16.f32 "
        "{%0,%1,%2,%3}, {%4,%5,%6,%7}, {%8,%9}, {%0,%1,%2,%3};"
        : "+f"(c[0]), "+f"(c[1]), "+f"(c[2]), "+f"(c[3])
        : "r"(a[0]), "r"(a[1]), "r"(a[2]), "r"(a[3]), "r"(b0), "r"(b1));
}
__device__ __forceinline__ unsigned bfpack(float lo, float hi) {
    unsigned r;
    asm("cvt.rn.bf16x2.f32 %0, %1, %2;" : "=r"(r) : "f"(hi), "f"(lo));
    return r;
}
__device__ __forceinline__ void cpa16(unsigned dst, const void* src) {
    asm volatile("cp.async.ca.shared.global [%0], [%1], 16;" :: "r"(dst), "l"(src));
}
#define CP_COMMIT asm volatile("cp.async.commit_group;" ::: "memory")
#define CP_WAIT0  asm volatile("cp.async.wait_group 0;" ::: "memory")

// ---------------- scratch (allocation-free: __device__ globals) ----------------
__device__ bf16 g_wqh[CQKV * CH], g_wql[CQKV * CH];
__device__ bf16 g_wph[CH * CH],   g_wpl[CH * CH];
__device__ bf16 g_xth[(long)BATCH * LPIX * CH], g_xtl[(long)BATCH * LPIX * CH];
__device__ bf16 g_mth[(long)BATCH * LPIX * CH], g_mtl[(long)BATCH * LPIX * CH];
// Pre-split attention operands: Q/K [bh][l][32], V [bh][d][1024]
__device__ bf16 g_qh[(long)64 * LPIX * 32], g_ql[(long)64 * LPIX * 32];
__device__ bf16 g_kh[(long)64 * LPIX * 32], g_kl[(long)64 * LPIX * 32];
__device__ bf16 g_vh[(long)64 * 64 * LPIX], g_vl[(long)64 * 64 * LPIX];

// ---------------------------------------------------------------------------
// Split fp32 -> bf16 hi/lo (elementwise; layout preserved)
// ---------------------------------------------------------------------------
__global__ void split_w_kernel(const float* __restrict__ w,
                               bf16* __restrict__ h, bf16* __restrict__ l, int n)
{
    int i = blockIdx.x * 256 + threadIdx.x;
    if (i < n) {
        float v = w[i];
        bf16 hh = __float2bfloat16(v);
        h[i] = hh;
        l[i] = __float2bfloat16(v - __bfloat162float(hh));
    }
}

// ---------------------------------------------------------------------------
// Transpose + split: X[b][k][n] fp32 -> T[b][n][k] bf16 hi/lo. 64x64 tiles.
// ---------------------------------------------------------------------------
__global__ __launch_bounds__(256)
void split_t_kernel(const float* __restrict__ X,
                    bf16* __restrict__ Th, bf16* __restrict__ Tl, int K, int N)
{
    __shared__ float t[64][65];
    const int n0 = blockIdx.x * 64;
    const int k0 = blockIdx.y * 64;
    const long b = blockIdx.z;
    const float* Xb = X + b * (long)K * N;
    bf16* ThB = Th + b * (long)K * N;
    bf16* TlB = Tl + b * (long)K * N;
    const int tx = threadIdx.x & 63, ty = threadIdx.x >> 6;

#pragma unroll
    for (int i = 0; i < 16; i++)
        t[ty + i * 4][tx] = Xb[(long)(k0 + ty + i * 4) * N + n0 + tx];
    __syncthreads();

#pragma unroll
    for (int i = 0; i < 16; i++) {
        int n = ty + i * 4;
        float v = t[tx][n];
        bf16 hh = __float2bfloat16(v);
        ThB[(long)(n0 + n) * K + k0 + tx] = hh;
        TlB[(long)(n0 + n) * K + k0 + tx] = __float2bfloat16(v - __bfloat162float(hh));
    }
}

// ---------------------------------------------------------------------------
// HMMA bf16-split GEMM shared tile constants.
// ---------------------------------------------------------------------------
#define G2_PAD   40
#define G2_TILEB 10240
#define G2_STAGE 40960
#define G2_SMEM  81920

// Generic GEMM + BN -> fp32 out (used for pw projection).
__global__ __launch_bounds__(256, 2)
void hmma_gemm_bn(const bf16* __restrict__ Ah, const bf16* __restrict__ Al,
                  const bf16* __restrict__ Bh, const bf16* __restrict__ Bl,
                  float* __restrict__ Y, const float* __restrict__ scale,
                  const float* __restrict__ bias, int M, int N, int K)
{
    extern __shared__ char smem[];
    const unsigned sb = smem_u32(smem);
    const int tid = threadIdx.x;
    const int wid = tid >> 5, lane = tid & 31;
    const int wm = wid & 3, wn = wid >> 2;
    const int n0 = blockIdx.x * 128;
    const int m0 = blockIdx.y * 128;
    const long bz = blockIdx.z;
    const bf16* Bhb = Bh + bz * (long)N * K;
    const bf16* Blb = Bl + bz * (long)N * K;
    float* Yb = Y + bz * (long)M * N;

    float acc[2][8][4];
#pragma unroll
    for (int mi = 0; mi < 2; mi++)
#pragma unroll
        for (int ni = 0; ni < 8; ni++)
#pragma unroll
            for (int j = 0; j < 4; j++) acc[mi][ni][j] = 0.f;

    const unsigned aRow = (unsigned)(wm * 32 + (lane & 15));
    const unsigned bRow = (unsigned)(wn * 64 + (lane & 15));
    const unsigned kHalf = (unsigned)((lane >> 4) * 8);

    auto load_chunk = [&](int st, int kc) {
        unsigned db = sb + st * G2_STAGE;
#pragma unroll
        for (int i = 0; i < 2; i++) {
            int f = tid + i * 256;
            int r = f >> 2, c4 = f & 3;
            unsigned d0 = db + r * 80 + c4 * 16;
            cpa16(d0,                 Ah  + (long)(m0 + r) * K + kc + c4 * 8);
            cpa16(d0 + G2_TILEB,      Al  + (long)(m0 + r) * K + kc + c4 * 8);
            cpa16(d0 + 2 * G2_TILEB,  Bhb + (long)(n0 + r) * K + kc + c4 * 8);
            cpa16(d0 + 3 * G2_TILEB,  Blb + (long)(n0 + r) * K + kc + c4 * 8);
        }
    };

    const int NCH = K / 32;
    load_chunk(0, 0);
    CP_COMMIT;
    CP_WAIT0;
    __syncthreads();

    for (int c = 0; c < NCH; c++) {
        const int st = c & 1;
        if (c + 1 < NCH) { load_chunk(1 - st, (c + 1) * 32); CP_COMMIT; }

        unsigned base = sb + st * G2_STAGE;
#pragma unroll
        for (int k16 = 0; k16 < 32; k16 += 16) {
            unsigned ah[2][4], al[2][4];
#pragma unroll
            for (int mi = 0; mi < 2; mi++) {
                unsigned eo = ((aRow + mi * 16) * G2_PAD + kHalf + k16) * 2;
                ldm_x4(ah[mi], base + eo);
                ldm_x4(al[mi], base + G2_TILEB + eo);
            }
            unsigned bh[8][2], bl[8][2];
#pragma unroll
            for (int np = 0; np < 4; np++) {
                unsigned eo = ((bRow + np * 16) * G2_PAD + kHalf + k16) * 2;
                unsigned r4[4];
                ldm_x4(r4, base + 2 * G2_TILEB + eo);
                bh[np * 2][0] = r4[0]; bh[np * 2][1] = r4[2];
                bh[np * 2 + 1][0] = r4[1]; bh[np * 2 + 1][1] = r4[3];
                ldm_x4(r4, base + 3 * G2_TILEB + eo);
                bl[np * 2][0] = r4[0]; bl[np * 2][1] = r4[2];
                bl[np * 2 + 1][0] = r4[1]; bl[np * 2 + 1][1] = r4[3];
            }
#pragma unroll
            for (int mi = 0; mi < 2; mi++)
#pragma unroll
                for (int ni = 0; ni < 8; ni++)
                    mma_bf16(acc[mi][ni], ah[mi], bh[ni][0], bh[ni][1]);
#pragma unroll
            for (int mi = 0; mi < 2; mi++)
#pragma unroll
                for (int ni = 0; ni < 8; ni++)
                    mma_bf16(acc[mi][ni], ah[mi], bl[ni][0], bl[ni][1]);
#pragma unroll
            for (int mi = 0; mi < 2; mi++)
#pragma unroll
                for (int ni = 0; ni < 8; ni++)
                    mma_bf16(acc[mi][ni], al[mi], bh[ni][0], bh[ni][1]);
        }
        if (c + 1 < NCH) CP_WAIT0;
        __syncthreads();
    }

#pragma unroll
    for (int mi = 0; mi < 2; mi++) {
        int r1 = m0 + wm * 32 + mi * 16 + (lane >> 2);
        int r2 = r1 + 8;
        float s1 = scale[r1], b1 = bias[r1];
        float s2 = scale[r2], b2 = bias[r2];
        float* y1 = &Yb[(long)r1 * N + n0 + wn * 64 + (lane & 3) * 2];
        float* y2 = &Yb[(long)r2 * N + n0 + wn * 64 + (lane & 3) * 2];
#pragma unroll
        for (int ni = 0; ni < 8; ni++) {
            float2 o1, o2;
            o1.x = acc[mi][ni][0] * s1 + b1;
            o1.y = acc[mi][ni][1] * s1 + b1;
            o2.x = acc[mi][ni][2] * s2 + b2;
            o2.y = acc[mi][ni][3] * s2 + b2;
            *reinterpret_cast<float2*>(y1 + ni * 8) = o1;
            *reinterpret_cast<float2*>(y2 + ni * 8) = o2;
        }
    }
}

// ---------------------------------------------------------------------------
// qkv GEMM with FUSED split epilogue (unchanged from passing round).
// ---------------------------------------------------------------------------
__global__ __launch_bounds__(256, 2)
void hmma_qkv(const bf16* __restrict__ Ah, const bf16* __restrict__ Al,
              const bf16* __restrict__ Bh, const bf16* __restrict__ Bl,
              const float* __restrict__ scale, const float* __restrict__ bias)
{
    extern __shared__ char smem[];
    const unsigned sb = smem_u32(smem);
    const int tid = threadIdx.x;
    const int wid = tid >> 5, lane = tid & 31;
    const int wm = wid & 3, wn = wid >> 2;
    const int n0 = blockIdx.x * 128;
    const int m0 = blockIdx.y * 128;     // head h = blockIdx.y
    const long bz = blockIdx.z;
    const int K = CH, N = LPIX;
    const bf16* Bhb = Bh + bz * (long)N * K;
    const bf16* Blb = Bl + bz * (long)N * K;

    float acc[2][8][4];
#pragma unroll
    for (int mi = 0; mi < 2; mi++)
#pragma unroll
        for (int ni = 0; ni < 8; ni++)
#pragma unroll
            for (int j = 0; j < 4; j++) acc[mi][ni][j] = 0.f;

    const unsigned aRow = (unsigned)(wm * 32 + (lane & 15));
    const unsigned bRow = (unsigned)(wn * 64 + (lane & 15));
    const unsigned kHalf = (unsigned)((lane >> 4) * 8);

    auto load_chunk = [&](int st, int kc) {
        unsigned db = sb + st * G2_STAGE;
#pragma unroll
        for (int i = 0; i < 2; i++) {
            int f = tid + i * 256;
            int r = f >> 2, c4 = f & 3;
            unsigned d0 = db + r * 80 + c4 * 16;
            cpa16(d0,                 Ah  + (long)(m0 + r) * K + kc + c4 * 8);
            cpa16(d0 + G2_TILEB,      Al  + (long)(m0 + r) * K + kc + c4 * 8);
            cpa16(d0 + 2 * G2_TILEB,  Bhb + (long)(n0 + r) * K + kc + c4 * 8);
            cpa16(d0 + 3 * G2_TILEB,  Blb + (long)(n0 + r) * K + kc + c4 * 8);
        }
    };

    const int NCH = K / 32;
    load_chunk(0, 0);
    CP_COMMIT;
    CP_WAIT0;
    __syncthreads();

    for (int c = 0; c < NCH; c++) {
        const int st = c & 1;
        if (c + 1 < NCH) { load_chunk(1 - st, (c + 1) * 32); CP_COMMIT; }

        unsigned base = sb + st * G2_STAGE;
#pragma unroll
        for (int k16 = 0; k16 < 32; k16 += 16) {
            unsigned ah[2][4], al[2][4];
#pragma unroll
            for (int mi = 0; mi < 2; mi++) {
                unsigned eo = ((aRow + mi * 16) * G2_PAD + kHalf + k16) * 2;
                ldm_x4(ah[mi], base + eo);
                ldm_x4(al[mi], base + G2_TILEB + eo);
            }
            unsigned bh[8][2], bl[8][2];
#pragma unroll
            for (int np = 0; np < 4; np++) {
                unsigned eo = ((bRow + np * 16) * G2_PAD + kHalf + k16) * 2;
                unsigned r4[4];
                ldm_x4(r4, base + 2 * G2_TILEB + eo);
                bh[np * 2][0] = r4[0]; bh[np * 2][1] = r4[2];
                bh[np * 2 + 1][0] = r4[1]; bh[np * 2 + 1][1] = r4[3];
                ldm_x4(r4, base + 3 * G2_TILEB + eo);
                bl[np * 2][0] = r4[0]; bl[np * 2][1] = r4[2];
                bl[np * 2 + 1][0] = r4[1]; bl[np * 2 + 1][1] = r4[3];
            }
#pragma unroll
            for (int mi = 0; mi < 2; mi++)
#pragma unroll
                for (int ni = 0; ni < 8; ni++)
                    mma_bf16(acc[mi][ni], ah[mi], bh[ni][0], bh[ni][1]);
#pragma unroll
            for (int mi = 0; mi < 2; mi++)
#pragma unroll
                for (int ni = 0; ni < 8; ni++)
                    mma_bf16(acc[mi][ni], ah[mi], bl[ni][0], bl[ni][1]);
#pragma unroll
            for (int mi = 0; mi < 2; mi++)
#pragma unroll
                for (int ni = 0; ni < 8; ni++)
                    mma_bf16(acc[mi][ni], al[mi], bh[ni][0], bh[ni][1]);
        }
        if (c + 1 < NCH) CP_WAIT0;
        __syncthreads();
    }

    // ---- fused epilogue: stage BN'd tile [128][133] then split-write ----
    float* st = (float*)smem;
#pragma unroll
    for (int mi = 0; mi < 2; mi++) {
        int rl1 = wm * 32 + mi * 16 + (lane >> 2);
        int rl2 = rl1 + 8;
        float s1 = scale[m0 + rl1], b1 = bias[m0 + rl1];
        float s2 = scale[m0 + rl2], b2 = bias[m0 + rl2];
#pragma unroll
        for (int ni = 0; ni < 8; ni++) {
            int cj = wn * 64 + ni * 8 + (lane & 3) * 2;
            st[rl1 * 133 + cj]     = acc[mi][ni][0] * s1 + b1;
            st[rl1 * 133 + cj + 1] = acc[mi][ni][1] * s1 + b1;
            st[rl2 * 133 + cj]     = acc[mi][ni][2] * s2 + b2;
            st[rl2 * 133 + cj + 1] = acc[mi][ni][3] * s2 + b2;
        }
    }
    __syncthreads();

    const int bh_ = (int)bz * 4 + blockIdx.y;
#pragma unroll
    for (int i = 0; i < 16; i++) {
        int f = tid + i * 256;
        int j = f >> 5, d = f & 31;
        float v = st[d * 133 + j] * SCALE;
        bf16 hv = __float2bfloat16(v);
        long o = ((long)bh_ * LPIX + n0 + j) * 32 + d;
        g_qh[o] = hv;
        g_ql[o] = __float2bfloat16(v - __bfloat162float(hv));
    }
#pragma unroll
    for (int i = 0; i < 16; i++) {
        int f = tid + i * 256;
        int j = f >> 5, d = f & 31;
        float v = st[(32 + d) * 133 + j];
        bf16 hv = __float2bfloat16(v);
        long o = ((long)bh_ * LPIX + n0 + j) * 32 + d;
        g_kh[o] = hv;
        g_kl[o] = __float2bfloat16(v - __bfloat162float(hv));
    }
#pragma unroll
    for (int i = 0; i < 32; i++) {
        int f = tid + i * 256;
        int d = f >> 7, j = f & 127;
        float v = st[(64 + d) * 133 + j];
        bf16 hv = __float2bfloat16(v);
        long o = ((long)bh_ * 64 + d) * LPIX + n0 + j;
        g_vh[o] = hv;
        g_vl[o] = __float2bfloat16(v - __bfloat162float(hv));
    }
}

// ---------------------------------------------------------------------------
// HMMA flash attention. Mainloop identical to passing round. Epilogue now
// computes the depthwise 3x3 conv (+BN) inline from split V, adds it, and
// writes the transposed split mth/mtl.
// smem after mainloop: sOut[128][65] @0 | wsm[576] @33280 | vsm[192][68] @35584
// ---------------------------------------------------------------------------
#define AT_SMEM 88064

__global__ __launch_bounds__(256, 2)
void attn_hmma(const float* __restrict__ w_dw, const float* __restrict__ s_dw,
               const float* __restrict__ b_dw)
{
    extern __shared__ char smraw[];
    const unsigned sb = smem_u32(smraw);
    const int tid = threadIdx.x;
    const int wid = tid >> 5, lane = tid & 31;
    const int qt = blockIdx.x, h = blockIdx.y, b = blockIdx.z;
    const int bh = b * 4 + h;

    const bf16* qh = g_qh + ((long)bh * LPIX + qt * 128) * 32;
    const bf16* ql = g_ql + ((long)bh * LPIX + qt * 128) * 32;
    const bf16* khp = g_kh + (long)bh * LPIX * 32;
    const bf16* klp = g_kl + (long)bh * LPIX * 32;
    const bf16* vhp = g_vh + (long)bh * 64 * LPIX;
    const bf16* vlp = g_vl + (long)bh * 64 * LPIX;

#pragma unroll
    for (int i = 0; i < 2; i++) {
        int f = tid + i * 256;
        int r = f >> 2, c4 = f & 3;
        cpa16(sb + r * 80 + c4 * 16,         qh + r * 32 + c4 * 8);
        cpa16(sb + 10240 + r * 80 + c4 * 16, ql + r * 32 + c4 * 8);
    }

    auto load_kv = [&](int st, int kt) {
        unsigned kb = sb + 20480 + st * 10240;
        unsigned vb = sb + 40960 + st * 18432;
        {
            int r = tid >> 2, c4 = tid & 3;
            cpa16(kb + r * 80 + c4 * 16,        khp + (long)(kt * 64 + r) * 32 + c4 * 8);
            cpa16(kb + 5120 + r * 80 + c4 * 16, klp + (long)(kt * 64 + r) * 32 + c4 * 8);
        }
#pragma unroll
        for (int i = 0; i < 2; i++) {
            int f = tid + i * 256;
            int d = f >> 3, j8 = f & 7;
            cpa16(vb + d * 144 + j8 * 16,        vhp + (long)d * LPIX + kt * 64 + j8 * 8);
            cpa16(vb + 9216 + d * 144 + j8 * 16, vlp + (long)d * LPIX + kt * 64 + j8 * 8);
        }
    };

    load_kv(0, 0);
    CP_COMMIT;
    CP_WAIT0;
    __syncthreads();

    float oacc[8][4];
#pragma unroll
    for (int n = 0; n < 8; n++)
#pragma unroll
        for (int j = 0; j < 4; j++) oacc[n][j] = 0.f;
    float m0 = -INFINITY, m1 = -INFINITY, l0 = 0.f, l1 = 0.f;

    const unsigned rowA = (unsigned)(wid * 16 + (lane & 15));
    const unsigned rowB = (unsigned)(lane & 15);
    const unsigned kHalf = (unsigned)((lane >> 4) * 8);

    for (int kt = 0; kt < 16; kt++) {
        const int st = kt & 1;
        if (kt + 1 < 16) { load_kv(1 - st, kt + 1); CP_COMMIT; }

        const unsigned sKh = sb + 20480 + st * 10240;
        const unsigned sKl = sKh + 5120;
        const unsigned sVh = sb + 40960 + st * 18432;
        const unsigned sVl = sVh + 9216;

        float sacc[8][4];
#pragma unroll
        for (int n = 0; n < 8; n++)
#pragma unroll
            for (int j = 0; j < 4; j++) sacc[n][j] = 0.f;

#pragma unroll
        for (int t = 0; t < 2; t++) {
            unsigned ah[4], al[4];
            unsigned eo = (rowA * 40 + kHalf + 16 * t) * 2;
            ldm_x4(ah, sb + eo);
            ldm_x4(al, sb + 10240 + eo);
            unsigned bh2[8][2], bl2[8][2];
#pragma unroll
            for (int np = 0; np < 4; np++) {
                unsigned eo2 = ((rowB + np * 16) * 40 + kHalf + 16 * t) * 2;
                unsigned r4[4];
                ldm_x4(r4, sKh + eo2);
                bh2[np * 2][0] = r4[0]; bh2[np * 2][1] = r4[2];
                bh2[np * 2 + 1][0] = r4[1]; bh2[np * 2 + 1][1] = r4[3];
                ldm_x4(r4, sKl + eo2);
                bl2[np * 2][0] = r4[0]; bl2[np * 2][1] = r4[2];
                bl2[np * 2 + 1][0] = r4[1]; bl2[np * 2 + 1][1] = r4[3];
            }
#pragma unroll
            for (int n = 0; n < 8; n++)
                mma_bf16(sacc[n], ah, bh2[n][0], bh2[n][1]);
#pragma unroll
            for (int n = 0; n < 8; n++)
                mma_bf16(sacc[n], ah, bl2[n][0], bl2[n][1]);
#pragma unroll
            for (int n = 0; n < 8; n++)
                mma_bf16(sacc[n], al, bh2[n][0], bh2[n][1]);
        }

        float mx0 = sacc[0][0], mx1 = sacc[0][2];
#pragma unroll
        for (int n = 0; n < 8; n++) {
            mx0 = fmaxf(mx0, fmaxf(sacc[n][0], sacc[n][1]));
            mx1 = fmaxf(mx1, fmaxf(sacc[n][2], sacc[n][3]));
        }
        mx0 = fmaxf(mx0, __shfl_xor_sync(0xffffffffu, mx0, 1));
        mx0 = fmaxf(mx0, __shfl_xor_sync(0xffffffffu, mx0, 2));
        mx1 = fmaxf(mx1, __shfl_xor_sync(0xffffffffu, mx1, 1));
        mx1 = fmaxf(mx1, __shfl_xor_sync(0xffffffffu, mx1, 2));
        float mn0 = fmaxf(m0, mx0), mn1 = fmaxf(m1, mx1);
        float c0 = __expf(m0 - mn0), c1 = __expf(m1 - mn1);
        m0 = mn0; m1 = mn1;
        l0 *= c0; l1 *= c1;
#pragma unroll
        for (int n = 0; n < 8; n++) {
            oacc[n][0] *= c0; oacc[n][1] *= c0;
            oacc[n][2] *= c1; oacc[n][3] *= c1;
        }

        float sum0 = 0.f, sum1 = 0.f;
#pragma unroll
        for (int t = 0; t < 4; t++) {
            float p0 = __expf(sacc[2 * t][0] - m0);
            float p1 = __expf(sacc[2 * t][1] - m0);
            float p2 = __expf(sacc[2 * t][2] - m1);
            float p3 = __expf(sacc[2 * t][3] - m1);
            float p4 = __expf(sacc[2 * t + 1][0] - m0);
            float p5 = __expf(sacc[2 * t + 1][1] - m0);
            float p6 = __expf(sacc[2 * t + 1][2] - m1);
            float p7 = __expf(sacc[2 * t + 1][3] - m1);
            sum0 += (p0 + p1) + (p4 + p5);
            sum1 += (p2 + p3) + (p6 + p7);

            unsigned aph[4], apl[4];
            aph[0] = bfpack(p0, p1);
            aph[1] = bfpack(p2, p3);
            aph[2] = bfpack(p4, p5);
            aph[3] = bfpack(p6, p7);
            float r0 = p0 - __bfloat162float(__float2bfloat16(p0));
            float r1 = p1 - __bfloat162float(__float2bfloat16(p1));
            float r2 = p2 - __bfloat162float(__float2bfloat16(p2));
            float r3 = p3 - __bfloat162float(__float2bfloat16(p3));
            float r4f = p4 - __bfloat162float(__float2bfloat16(p4));
            float r5 = p5 - __bfloat162float(__float2bfloat16(p5));
            float r6 = p6 - __bfloat162float(__float2bfloat16(p6));
            float r7 = p7 - __bfloat162float(__float2bfloat16(p7));
            apl[0] = bfpack(r0, r1);
            apl[1] = bfpack(r2, r3);
            apl[2] = bfpack(r4f, r5);
            apl[3] = bfpack(r6, r7);

            unsigned vh2[8][2], vl2[8][2];
#pragma unroll
            for (int np = 0; np < 4; np++) {
                unsigned eo2 = ((rowB + np * 16) * 72 + kHalf + 16 * t) * 2;
                unsigned v4[4];
                ldm_x4(v4, sVh + eo2);
                vh2[np * 2][0] = v4[0]; vh2[np * 2][1] = v4[2];
                vh2[np * 2 + 1][0] = v4[1]; vh2[np * 2 + 1][1] = v4[3];
                ldm_x4(v4, sVl + eo2);
                vl2[np * 2][0] = v4[0]; vl2[np * 2][1] = v4[2];
                vl2[np * 2 + 1][0] = v4[1]; vl2[np * 2 + 1][1] = v4[3];
            }
#pragma unroll
            for (int n = 0; n < 8; n++)
                mma_bf16(oacc[n], aph, vh2[n][0], vh2[n][1]);
#pragma unroll
            for (int n = 0; n < 8; n++)
                mma_bf16(oacc[n], aph, vl2[n][0], vl2[n][1]);
#pragma unroll
            for (int n = 0; n < 8; n++)
                mma_bf16(oacc[n], apl, vh2[n][0], vh2[n][1]);
        }
        sum0 += __shfl_xor_sync(0xffffffffu, sum0, 1);
        sum0 += __shfl_xor_sync(0xffffffffu, sum0, 2);
        sum1 += __shfl_xor_sync(0xffffffffu, sum1, 1);
        sum1 += __shfl_xor_sync(0xffffffffu, sum1, 2);
        l0 += sum0; l1 += sum1;

        if (kt + 1 < 16) CP_WAIT0;
        __syncthreads();
    }

    // ---- epilogue part 1: normalize attn -> sOut[l][65] ----
    float* sOut = (float*)smraw;
    float* wsm  = (float*)(smraw + 33280);   // 576 floats (dw weights of this head)
    float* vsm  = (float*)(smraw + 35584);   // [192 px][68] V slice (6 rows x 32 cols)
    float il0 = 1.f / l0, il1 = 1.f / l1;
    int r0q = wid * 16 + (lane >> 2);
#pragma unroll
    for (int n = 0; n < 8; n++) {
        int d = n * 8 + (lane & 3) * 2;
        sOut[r0q * 65 + d]           = oacc[n][0] * il0;
        sOut[r0q * 65 + d + 1]       = oacc[n][1] * il0;
        sOut[(r0q + 8) * 65 + d]     = oacc[n][2] * il1;
        sOut[(r0q + 8) * 65 + d + 1] = oacc[n][3] * il1;
    }

    // ---- epilogue part 2: load dw weights + V halo slice ----
    for (int i = tid; i < 576; i += 256)
        wsm[i] = w_dw[h * 64 * 9 + i];
#pragma unroll
    for (int i = 0; i < 48; i++) {
        int f = tid + i * 256;        // 0..12287 = d(64) * r(6) * x(32)
        int d = f / 192;
        int rx = f - d * 192;         // r*32 + x
        int y = qt * 4 - 1 + (rx >> 5);
        float v = 0.f;
        if (y >= 0 && y < 32) {
            long vo = (long)d * LPIX + y * 32 + (rx & 31);
            v = __bfloat162float(vhp[vo]) + __bfloat162float(vlp[vo]);
        }
        vsm[rx * 68 + d] = v;
    }
    __syncthreads();

    // ---- epilogue part 3: dw conv + BN, add into sOut ----
    {
        int d = tid & 63, ly = tid >> 6;    // ly in 0..3 (local image row)
        float wv[9];
#pragma unroll
        for (int t = 0; t < 9; t++) wv[t] = wsm[d * 9 + t];
        float sdw = s_dw[h * 64 + d], bdw = b_dw[h * 64 + d];
#pragma unroll 4
        for (int lx = 0; lx < 32; lx++) {
            float acc = 0.f;
#pragma unroll
            for (int ky = 0; ky < 3; ky++) {
#pragma unroll
                for (int kx = 0; kx < 3; kx++) {
                    int xx = lx + kx - 1;
                    if (xx >= 0 && xx < 32)
                        acc = fmaf(vsm[((ly + ky) * 32 + xx) * 68 + d],
                                   wv[ky * 3 + kx], acc);
                }
            }
            sOut[(ly * 32 + lx) * 65 + d] += acc * sdw + bdw;
        }
    }
    __syncthreads();

    // ---- epilogue part 4: split-write transposed mid -> g_mth/g_mtl ----
    bf16* th = g_mth + ((long)b * LPIX + qt * 128) * CH + h * 64;
    bf16* tl = g_mtl + ((long)b * LPIX + qt * 128) * CH + h * 64;
#pragma unroll
    for (int it = 0; it < 32; it++) {
        int f = tid + it * 256;
        int l = f >> 6, d = f & 63;
        float v = sOut[l * 65 + d];
        bf16 hv = __float2bfloat16(v);
        th[(long)l * CH + d] = hv;
        tl[(long)l * CH + d] = __float2bfloat16(v - __bfloat162float(hv));
    }
}

// ---------------------------------------------------------------------------
extern "C" void kernel_launch(void* const* d_in, const int* in_sizes, int n_in,
                              void* d_out, int out_size)
{
    const float* x     = (const float*)d_in[0];
    const float* w_qkv = (const float*)d_in[1];
    const float* s_qkv = (const float*)d_in[2];
    const float* b_qkv = (const float*)d_in[3];
    const float* w_dw  = (const float*)d_in[4];
    const float* s_dw  = (const float*)d_in[5];
    const float* b_dw  = (const float*)d_in[6];
    const float* w_pw  = (const float*)d_in[7];
    const float* s_pw  = (const float*)d_in[8];
    const float* b_pw  = (const float*)d_in[9];
    float* out = (float*)d_out;

    bf16 *wqh, *wql, *wph, *wpl, *xth, *xtl, *mth, *mtl;
    cudaGetSymbolAddress((void**)&wqh, g_wqh);
    cudaGetSymbolAddress((void**)&wql, g_wql);
    cudaGetSymbolAddress((void**)&wph, g_wph);
    cudaGetSymbolAddress((void**)&wpl, g_wpl);
    cudaGetSymbolAddress((void**)&xth, g_xth);
    cudaGetSymbolAddress((void**)&xtl, g_xtl);
    cudaGetSymbolAddress((void**)&mth, g_mth);
    cudaGetSymbolAddress((void**)&mtl, g_mtl);

    cudaFuncSetAttribute(attn_hmma, cudaFuncAttributeMaxDynamicSharedMemorySize, AT_SMEM);
    cudaFuncSetAttribute(hmma_gemm_bn, cudaFuncAttributeMaxDynamicSharedMemorySize, G2_SMEM);
    cudaFuncSetAttribute(hmma_qkv, cudaFuncAttributeMaxDynamicSharedMemorySize, G2_SMEM);

    // Prep: split weights; transpose+split x
    split_w_kernel<<<(CQKV * CH + 255) / 256, 256>>>(w_qkv, wqh, wql, CQKV * CH);
    split_w_kernel<<<(CH * CH + 255) / 256, 256>>>(w_pw, wph, wpl, CH * CH);
    split_t_kernel<<<dim3(LPIX / 64, CH / 64, BATCH), 256>>>(x, xth, xtl, CH, LPIX);

    // 1) qkv GEMM with fused split epilogue -> g_qh/ql/kh/kl/vh/vl
    hmma_qkv<<<dim3(8, 4, 16), 256, G2_SMEM>>>(wqh, wql, xth, xtl, s_qkv, b_qkv);
    // 2) attention; epilogue computes dwconv inline, adds, writes split mth/mtl
    attn_hmma<<<dim3(8, 4, 16), 256, AT_SMEM>>>(w_dw, s_dw, b_dw);
    // 3) out = bn(W_pw @ (attn + dwconv))
    hmma_gemm_bn<<<dim3(8, 2, 16), 256, G2_SMEM>>>(wph, wpl, mth, mtl, out,
                                                   s_pw, b_pw, CH, LPIX, CH);
}

// round 16
// speedup vs baseline: 2.8716x; 1.0822x over previous
#include <cuda_runtime.h>
#include <cuda_bf16.h>
#include <cuda_fp16.h>
#include <math.h>

// Problem constants
#define BATCH 16
#define CH    256
#define NH    4
#define DH    64
#define LPIX  1024
#define CQKV  512
#define SCALE 0.17677669529663687f   // 32^-0.5

typedef unsigned long long u64;
typedef __nv_bfloat16 bf16;

__device__ __forceinline__ unsigned smem_u32(const void* p) {
    unsigned r;
    asm("{ .reg .u64 t; cvta.to.shared.u64 t, %1; cvt.u32.u64 %0, t; }" : "=r"(r) : "l"(p));
    return r;
}

// ---------------- mma.sync + cp.async helpers ----------------
__device__ __forceinline__ void ldm_x4(unsigned* r, unsigned addr) {
    asm volatile("ldmatrix.sync.aligned.m8n8.x4.shared.b16 {%0,%1,%2,%3}, [%4];"
                 : "=r"(r[0]), "=r"(r[1]), "=r"(r[2]), "=r"(r[3]) : "r"(addr));
}
__device__ __forceinline__ void mma_bf16(float* c, const unsigned* a, unsigned b0, unsigned b1) {
    asm volatile(
        "mma.sync.aligned.m16n8k16.row.col.f32.bf16.bf16.f32 "
        "{%0,%1,%2,%3}, {%4,%5,%6,%7}, {%8,%9}, {%0,%1,%2,%3};"
        : "+f"(c[0]), "+f"(c[1]), "+f"(c[2]), "+f"(c[3])
        : "r"(a[0]), "r"(a[1]), "r"(a[2]), "r"(a[3]), "r"(b0), "r"(b1));
}
__device__ __forceinline__ void mma_f16(float* c, const unsigned* a, unsigned b0, unsigned b1) {
    asm volatile(
        "mma.sync.aligned.m16n8k16.row.col.f32.f16.f16.f32 "
        "{%0,%1,%2,%3}, {%4,%5,%6,%7}, {%8,%9}, {%0,%1,%2,%3};"
        : "+f"(c[0]), "+f"(c[1]), "+f"(c[2]), "+f"(c[3])
        : "r"(a[0]), "r"(a[1]), "r"(a[2]), "r"(a[3]), "r"(b0), "r"(b1));
}
__device__ __forceinline__ unsigned bfpack(float lo, float hi) {
    unsigned r;
    asm("cvt.rn.bf16x2.f32 %0, %1, %2;" : "=r"(r) : "f"(hi), "f"(lo));
    return r;
}
__device__ __forceinline__ unsigned hfpack(float lo, float hi) {
    unsigned r;
    asm("cvt.rn.f16x2.f32 %0, %1, %2;" : "=r"(r) : "f"(hi), "f"(lo));
    return r;
}
__device__ __forceinline__ float2 hunpack(unsigned v) {
    __half2 h = *reinterpret_cast<__half2*>(&v);
    return __half22float2(h);
}
__device__ __forceinline__ void cpa16(unsigned dst, const void* src) {
    asm volatile("cp.async.ca.shared.global [%0], [%1], 16;" :: "r"(dst), "l"(src));
}
#define CP_COMMIT asm volatile("cp.async.commit_group;" ::: "memory")
#define CP_WAIT0  asm volatile("cp.async.wait_group 0;" ::: "memory")

// ---------------- scratch (allocation-free: __device__ globals) ----------------
__device__ bf16 g_wqh[CQKV * CH], g_wql[CQKV * CH];
__device__ bf16 g_wph[CH * CH],   g_wpl[CH * CH];
__device__ bf16 g_xth[(long)BATCH * LPIX * CH], g_xtl[(long)BATCH * LPIX * CH];
__device__ bf16 g_mth[(long)BATCH * LPIX * CH], g_mtl[(long)BATCH * LPIX * CH];
// Pre-split attention operands: Q/K [bh][l][32] (bf16), V [bh][d][1024] (fp16 pair)
__device__ bf16 g_qh[(long)64 * LPIX * 32], g_ql[(long)64 * LPIX * 32];
__device__ bf16 g_kh[(long)64 * LPIX * 32], g_kl[(long)64 * LPIX * 32];
__device__ __half g_vh[(long)64 * 64 * LPIX], g_vl[(long)64 * 64 * LPIX];

// ---------------------------------------------------------------------------
// Split fp32 -> bf16 hi/lo (elementwise; layout preserved)
// ---------------------------------------------------------------------------
__global__ void split_w_kernel(const float* __restrict__ w,
                               bf16* __restrict__ h, bf16* __restrict__ l, int n)
{
    int i = blockIdx.x * 256 + threadIdx.x;
    if (i < n) {
        float v = w[i];
        bf16 hh = __float2bfloat16(v);
        h[i] = hh;
        l[i] = __float2bfloat16(v - __bfloat162float(hh));
    }
}

// ---------------------------------------------------------------------------
// Transpose + split: X[b][k][n] fp32 -> T[b][n][k] bf16 hi/lo. 64x64 tiles.
// ---------------------------------------------------------------------------
__global__ __launch_bounds__(256)
void split_t_kernel(const float* __restrict__ X,
                    bf16* __restrict__ Th, bf16* __restrict__ Tl, int K, int N)
{
    __shared__ float t[64][65];
    const int n0 = blockIdx.x * 64;
    const int k0 = blockIdx.y * 64;
    const long b = blockIdx.z;
    const float* Xb = X + b * (long)K * N;
    bf16* ThB = Th + b * (long)K * N;
    bf16* TlB = Tl + b * (long)K * N;
    const int tx = threadIdx.x & 63, ty = threadIdx.x >> 6;

#pragma unroll
    for (int i = 0; i < 16; i++)
        t[ty + i * 4][tx] = Xb[(long)(k0 + ty + i * 4) * N + n0 + tx];
    __syncthreads();

#pragma unroll
    for (int i = 0; i < 16; i++) {
        int n = ty + i * 4;
        float v = t[tx][n];
        bf16 hh = __float2bfloat16(v);
        ThB[(long)(n0 + n) * K + k0 + tx] = hh;
        TlB[(long)(n0 + n) * K + k0 + tx] = __float2bfloat16(v - __bfloat162float(hh));
    }
}

// ---------------------------------------------------------------------------
// HMMA bf16-split GEMM shared tile constants.
// ---------------------------------------------------------------------------
#define G2_PAD   40
#define G2_TILEB 10240
#define G2_STAGE 40960
#define G2_SMEM  81920

// Generic GEMM + BN -> fp32 out (used for pw projection).
__global__ __launch_bounds__(256, 2)
void hmma_gemm_bn(const bf16* __restrict__ Ah, const bf16* __restrict__ Al,
                  const bf16* __restrict__ Bh, const bf16* __restrict__ Bl,
                  float* __restrict__ Y, const float* __restrict__ scale,
                  const float* __restrict__ bias, int M, int N, int K)
{
    extern __shared__ char smem[];
    const unsigned sb = smem_u32(smem);
    const int tid = threadIdx.x;
    const int wid = tid >> 5, lane = tid & 31;
    const int wm = wid & 3, wn = wid >> 2;
    const int n0 = blockIdx.x * 128;
    const int m0 = blockIdx.y * 128;
    const long bz = blockIdx.z;
    const bf16* Bhb = Bh + bz * (long)N * K;
    const bf16* Blb = Bl + bz * (long)N * K;
    float* Yb = Y + bz * (long)M * N;

    float acc[2][8][4];
#pragma unroll
    for (int mi = 0; mi < 2; mi++)
#pragma unroll
        for (int ni = 0; ni < 8; ni++)
#pragma unroll
            for (int j = 0; j < 4; j++) acc[mi][ni][j] = 0.f;

    const unsigned aRow = (unsigned)(wm * 32 + (lane & 15));
    const unsigned bRow = (unsigned)(wn * 64 + (lane & 15));
    const unsigned kHalf = (unsigned)((lane >> 4) * 8);

    auto load_chunk = [&](int st, int kc) {
        unsigned db = sb + st * G2_STAGE;
#pragma unroll
        for (int i = 0; i < 2; i++) {
            int f = tid + i * 256;
            int r = f >> 2, c4 = f & 3;
            unsigned d0 = db + r * 80 + c4 * 16;
            cpa16(d0,                 Ah  + (long)(m0 + r) * K + kc + c4 * 8);
            cpa16(d0 + G2_TILEB,      Al  + (long)(m0 + r) * K + kc + c4 * 8);
            cpa16(d0 + 2 * G2_TILEB,  Bhb + (long)(n0 + r) * K + kc + c4 * 8);
            cpa16(d0 + 3 * G2_TILEB,  Blb + (long)(n0 + r) * K + kc + c4 * 8);
        }
    };

    const int NCH = K / 32;
    load_chunk(0, 0);
    CP_COMMIT;
    CP_WAIT0;
    __syncthreads();

    for (int c = 0; c < NCH; c++) {
        const int st = c & 1;
        if (c + 1 < NCH) { load_chunk(1 - st, (c + 1) * 32); CP_COMMIT; }

        unsigned base = sb + st * G2_STAGE;
#pragma unroll
        for (int k16 = 0; k16 < 32; k16 += 16) {
            unsigned ah[2][4], al[2][4];
#pragma unroll
            for (int mi = 0; mi < 2; mi++) {
                unsigned eo = ((aRow + mi * 16) * G2_PAD + kHalf + k16) * 2;
                ldm_x4(ah[mi], base + eo);
                ldm_x4(al[mi], base + G2_TILEB + eo);
            }
            unsigned bh[8][2], bl[8][2];
#pragma unroll
            for (int np = 0; np < 4; np++) {
                unsigned eo = ((bRow + np * 16) * G2_PAD + kHalf + k16) * 2;
                unsigned r4[4];
                ldm_x4(r4, base + 2 * G2_TILEB + eo);
                bh[np * 2][0] = r4[0]; bh[np * 2][1] = r4[2];
                bh[np * 2 + 1][0] = r4[1]; bh[np * 2 + 1][1] = r4[3];
                ldm_x4(r4, base + 3 * G2_TILEB + eo);
                bl[np * 2][0] = r4[0]; bl[np * 2][1] = r4[2];
                bl[np * 2 + 1][0] = r4[1]; bl[np * 2 + 1][1] = r4[3];
            }
#pragma unroll
            for (int mi = 0; mi < 2; mi++)
#pragma unroll
                for (int ni = 0; ni < 8; ni++)
                    mma_bf16(acc[mi][ni], ah[mi], bh[ni][0], bh[ni][1]);
#pragma unroll
            for (int mi = 0; mi < 2; mi++)
#pragma unroll
                for (int ni = 0; ni < 8; ni++)
                    mma_bf16(acc[mi][ni], ah[mi], bl[ni][0], bl[ni][1]);
#pragma unroll
            for (int mi = 0; mi < 2; mi++)
#pragma unroll
                for (int ni = 0; ni < 8; ni++)
                    mma_bf16(acc[mi][ni], al[mi], bh[ni][0], bh[ni][1]);
        }
        if (c + 1 < NCH) CP_WAIT0;
        __syncthreads();
    }

#pragma unroll
    for (int mi = 0; mi < 2; mi++) {
        int r1 = m0 + wm * 32 + mi * 16 + (lane >> 2);
        int r2 = r1 + 8;
        float s1 = scale[r1], b1 = bias[r1];
        float s2 = scale[r2], b2 = bias[r2];
        float* y1 = &Yb[(long)r1 * N + n0 + wn * 64 + (lane & 3) * 2];
        float* y2 = &Yb[(long)r2 * N + n0 + wn * 64 + (lane & 3) * 2];
#pragma unroll
        for (int ni = 0; ni < 8; ni++) {
            float2 o1, o2;
            o1.x = acc[mi][ni][0] * s1 + b1;
            o1.y = acc[mi][ni][1] * s1 + b1;
            o2.x = acc[mi][ni][2] * s2 + b2;
            o2.y = acc[mi][ni][3] * s2 + b2;
            *reinterpret_cast<float2*>(y1 + ni * 8) = o1;
            *reinterpret_cast<float2*>(y2 + ni * 8) = o2;
        }
    }
}

// ---------------------------------------------------------------------------
// qkv GEMM with FUSED split epilogue: Q/K bf16 pairs, V fp16 pairs.
// ---------------------------------------------------------------------------
__global__ __launch_bounds__(256, 2)
void hmma_qkv(const bf16* __restrict__ Ah, const bf16* __restrict__ Al,
              const bf16* __restrict__ Bh, const bf16* __restrict__ Bl,
              const float* __restrict__ scale, const float* __restrict__ bias)
{
    extern __shared__ char smem[];
    const unsigned sb = smem_u32(smem);
    const int tid = threadIdx.x;
    const int wid = tid >> 5, lane = tid & 31;
    const int wm = wid & 3, wn = wid >> 2;
    const int n0 = blockIdx.x * 128;
    const int m0 = blockIdx.y * 128;     // head h = blockIdx.y
    const long bz = blockIdx.z;
    const int K = CH, N = LPIX;
    const bf16* Bhb = Bh + bz * (long)N * K;
    const bf16* Blb = Bl + bz * (long)N * K;

    float acc[2][8][4];
#pragma unroll
    for (int mi = 0; mi < 2; mi++)
#pragma unroll
        for (int ni = 0; ni < 8; ni++)
#pragma unroll
            for (int j = 0; j < 4; j++) acc[mi][ni][j] = 0.f;

    const unsigned aRow = (unsigned)(wm * 32 + (lane & 15));
    const unsigned bRow = (unsigned)(wn * 64 + (lane & 15));
    const unsigned kHalf = (unsigned)((lane >> 4) * 8);

    auto load_chunk = [&](int st, int kc) {
        unsigned db = sb + st * G2_STAGE;
#pragma unroll
        for (int i = 0; i < 2; i++) {
            int f = tid + i * 256;
            int r = f >> 2, c4 = f & 3;
            unsigned d0 = db + r * 80 + c4 * 16;
            cpa16(d0,                 Ah  + (long)(m0 + r) * K + kc + c4 * 8);
            cpa16(d0 + G2_TILEB,      Al  + (long)(m0 + r) * K + kc + c4 * 8);
            cpa16(d0 + 2 * G2_TILEB,  Bhb + (long)(n0 + r) * K + kc + c4 * 8);
            cpa16(d0 + 3 * G2_TILEB,  Blb + (long)(n0 + r) * K + kc + c4 * 8);
        }
    };

    const int NCH = K / 32;
    load_chunk(0, 0);
    CP_COMMIT;
    CP_WAIT0;
    __syncthreads();

    for (int c = 0; c < NCH; c++) {
        const int st = c & 1;
        if (c + 1 < NCH) { load_chunk(1 - st, (c + 1) * 32); CP_COMMIT; }

        unsigned base = sb + st * G2_STAGE;
#pragma unroll
        for (int k16 = 0; k16 < 32; k16 += 16) {
            unsigned ah[2][4], al[2][4];
#pragma unroll
            for (int mi = 0; mi < 2; mi++) {
                unsigned eo = ((aRow + mi * 16) * G2_PAD + kHalf + k16) * 2;
                ldm_x4(ah[mi], base + eo);
                ldm_x4(al[mi], base + G2_TILEB + eo);
            }
            unsigned bh[8][2], bl[8][2];
#pragma unroll
            for (int np = 0; np < 4; np++) {
                unsigned eo = ((bRow + np * 16) * G2_PAD + kHalf + k16) * 2;
                unsigned r4[4];
                ldm_x4(r4, base + 2 * G2_TILEB + eo);
                bh[np * 2][0] = r4[0]; bh[np * 2][1] = r4[2];
                bh[np * 2 + 1][0] = r4[1]; bh[np * 2 + 1][1] = r4[3];
                ldm_x4(r4, base + 3 * G2_TILEB + eo);
                bl[np * 2][0] = r4[0]; bl[np * 2][1] = r4[2];
                bl[np * 2 + 1][0] = r4[1]; bl[np * 2 + 1][1] = r4[3];
            }
#pragma unroll
            for (int mi = 0; mi < 2; mi++)
#pragma unroll
                for (int ni = 0; ni < 8; ni++)
                    mma_bf16(acc[mi][ni], ah[mi], bh[ni][0], bh[ni][1]);
#pragma unroll
            for (int mi = 0; mi < 2; mi++)
#pragma unroll
                for (int ni = 0; ni < 8; ni++)
                    mma_bf16(acc[mi][ni], ah[mi], bl[ni][0], bl[ni][1]);
#pragma unroll
            for (int mi = 0; mi < 2; mi++)
#pragma unroll
                for (int ni = 0; ni < 8; ni++)
                    mma_bf16(acc[mi][ni], al[mi], bh[ni][0], bh[ni][1]);
        }
        if (c + 1 < NCH) CP_WAIT0;
        __syncthreads();
    }

    // ---- fused epilogue: stage BN'd tile [128][133] then split-write ----
    float* st = (float*)smem;
#pragma unroll
    for (int mi = 0; mi < 2; mi++) {
        int rl1 = wm * 32 + mi * 16 + (lane >> 2);
        int rl2 = rl1 + 8;
        float s1 = scale[m0 + rl1], b1 = bias[m0 + rl1];
        float s2 = scale[m0 + rl2], b2 = bias[m0 + rl2];
#pragma unroll
        for (int ni = 0; ni < 8; ni++) {
            int cj = wn * 64 + ni * 8 + (lane & 3) * 2;
            st[rl1 * 133 + cj]     = acc[mi][ni][0] * s1 + b1;
            st[rl1 * 133 + cj + 1] = acc[mi][ni][1] * s1 + b1;
            st[rl2 * 133 + cj]     = acc[mi][ni][2] * s2 + b2;
            st[rl2 * 133 + cj + 1] = acc[mi][ni][3] * s2 + b2;
        }
    }
    __syncthreads();

    const int bh_ = (int)bz * 4 + blockIdx.y;
#pragma unroll
    for (int i = 0; i < 16; i++) {
        int f = tid + i * 256;
        int j = f >> 5, d = f & 31;
        float v = st[d * 133 + j] * SCALE;
        bf16 hv = __float2bfloat16(v);
        long o = ((long)bh_ * LPIX + n0 + j) * 32 + d;
        g_qh[o] = hv;
        g_ql[o] = __float2bfloat16(v - __bfloat162float(hv));
    }
#pragma unroll
    for (int i = 0; i < 16; i++) {
        int f = tid + i * 256;
        int j = f >> 5, d = f & 31;
        float v = st[(32 + d) * 133 + j];
        bf16 hv = __float2bfloat16(v);
        long o = ((long)bh_ * LPIX + n0 + j) * 32 + d;
        g_kh[o] = hv;
        g_kl[o] = __float2bfloat16(v - __bfloat162float(hv));
    }
#pragma unroll
    for (int i = 0; i < 32; i++) {
        int f = tid + i * 256;
        int d = f >> 7, j = f & 127;
        float v = st[(64 + d) * 133 + j];
        __half hv = __float2half(v);
        long o = ((long)bh_ * 64 + d) * LPIX + n0 + j;
        g_vh[o] = hv;
        g_vl[o] = __float2half(v - __half2float(hv));
    }
}

// ---------------------------------------------------------------------------
// HMMA flash attention. S = QK^T bf16 3-term (unchanged). PV: P single fp16,
// V fp16 hi/lo -> 2 MMAs per tile. Normalizer uses quantized P. Epilogue:
// inline dw conv + BN + add, split-write mth/mtl.
// ---------------------------------------------------------------------------
#define AT_SMEM 88064

__global__ __launch_bounds__(256, 2)
void attn_hmma(const float* __restrict__ w_dw, const float* __restrict__ s_dw,
               const float* __restrict__ b_dw)
{
    extern __shared__ char smraw[];
    const unsigned sb = smem_u32(smraw);
    const int tid = threadIdx.x;
    const int wid = tid >> 5, lane = tid & 31;
    const int qt = blockIdx.x, h = blockIdx.y, b = blockIdx.z;
    const int bh = b * 4 + h;

    const bf16* qh = g_qh + ((long)bh * LPIX + qt * 128) * 32;
    const bf16* ql = g_ql + ((long)bh * LPIX + qt * 128) * 32;
    const bf16* khp = g_kh + (long)bh * LPIX * 32;
    const bf16* klp = g_kl + (long)bh * LPIX * 32;
    const __half* vhp = g_vh + (long)bh * 64 * LPIX;
    const __half* vlp = g_vl + (long)bh * 64 * LPIX;

#pragma unroll
    for (int i = 0; i < 2; i++) {
        int f = tid + i * 256;
        int r = f >> 2, c4 = f & 3;
        cpa16(sb + r * 80 + c4 * 16,         qh + r * 32 + c4 * 8);
        cpa16(sb + 10240 + r * 80 + c4 * 16, ql + r * 32 + c4 * 8);
    }

    auto load_kv = [&](int st, int kt) {
        unsigned kb = sb + 20480 + st * 10240;
        unsigned vb = sb + 40960 + st * 18432;
        {
            int r = tid >> 2, c4 = tid & 3;
            cpa16(kb + r * 80 + c4 * 16,        khp + (long)(kt * 64 + r) * 32 + c4 * 8);
            cpa16(kb + 5120 + r * 80 + c4 * 16, klp + (long)(kt * 64 + r) * 32 + c4 * 8);
        }
#pragma unroll
        for (int i = 0; i < 2; i++) {
            int f = tid + i * 256;
            int d = f >> 3, j8 = f & 7;
            cpa16(vb + d * 144 + j8 * 16,        vhp + (long)d * LPIX + kt * 64 + j8 * 8);
            cpa16(vb + 9216 + d * 144 + j8 * 16, vlp + (long)d * LPIX + kt * 64 + j8 * 8);
        }
    };

    load_kv(0, 0);
    CP_COMMIT;
    CP_WAIT0;
    __syncthreads();

    float oacc[8][4];
#pragma unroll
    for (int n = 0; n < 8; n++)
#pragma unroll
        for (int j = 0; j < 4; j++) oacc[n][j] = 0.f;
    float m0 = -INFINITY, m1 = -INFINITY, l0 = 0.f, l1 = 0.f;

    const unsigned rowA = (unsigned)(wid * 16 + (lane & 15));
    const unsigned rowB = (unsigned)(lane & 15);
    const unsigned kHalf = (unsigned)((lane >> 4) * 8);

    for (int kt = 0; kt < 16; kt++) {
        const int st = kt & 1;
        if (kt + 1 < 16) { load_kv(1 - st, kt + 1); CP_COMMIT; }

        const unsigned sKh = sb + 20480 + st * 10240;
        const unsigned sKl = sKh + 5120;
        const unsigned sVh = sb + 40960 + st * 18432;
        const unsigned sVl = sVh + 9216;

        float sacc[8][4];
#pragma unroll
        for (int n = 0; n < 8; n++)
#pragma unroll
            for (int j = 0; j < 4; j++) sacc[n][j] = 0.f;

#pragma unroll
        for (int t = 0; t < 2; t++) {
            unsigned ah[4], al[4];
            unsigned eo = (rowA * 40 + kHalf + 16 * t) * 2;
            ldm_x4(ah, sb + eo);
            ldm_x4(al, sb + 10240 + eo);
            unsigned bh2[8][2], bl2[8][2];
#pragma unroll
            for (int np = 0; np < 4; np++) {
                unsigned eo2 = ((rowB + np * 16) * 40 + kHalf + 16 * t) * 2;
                unsigned r4[4];
                ldm_x4(r4, sKh + eo2);
                bh2[np * 2][0] = r4[0]; bh2[np * 2][1] = r4[2];
                bh2[np * 2 + 1][0] = r4[1]; bh2[np * 2 + 1][1] = r4[3];
                ldm_x4(r4, sKl + eo2);
                bl2[np * 2][0] = r4[0]; bl2[np * 2][1] = r4[2];
                bl2[np * 2 + 1][0] = r4[1]; bl2[np * 2 + 1][1] = r4[3];
            }
#pragma unroll
            for (int n = 0; n < 8; n++)
                mma_bf16(sacc[n], ah, bh2[n][0], bh2[n][1]);
#pragma unroll
            for (int n = 0; n < 8; n++)
                mma_bf16(sacc[n], ah, bl2[n][0], bl2[n][1]);
#pragma unroll
            for (int n = 0; n < 8; n++)
                mma_bf16(sacc[n], al, bh2[n][0], bh2[n][1]);
        }

        float mx0 = sacc[0][0], mx1 = sacc[0][2];
#pragma unroll
        for (int n = 0; n < 8; n++) {
            mx0 = fmaxf(mx0, fmaxf(sacc[n][0], sacc[n][1]));
            mx1 = fmaxf(mx1, fmaxf(sacc[n][2], sacc[n][3]));
        }
        mx0 = fmaxf(mx0, __shfl_xor_sync(0xffffffffu, mx0, 1));
        mx0 = fmaxf(mx0, __shfl_xor_sync(0xffffffffu, mx0, 2));
        mx1 = fmaxf(mx1, __shfl_xor_sync(0xffffffffu, mx1, 1));
        mx1 = fmaxf(mx1, __shfl_xor_sync(0xffffffffu, mx1, 2));
        float mn0 = fmaxf(m0, mx0), mn1 = fmaxf(m1, mx1);
        float c0 = __expf(m0 - mn0), c1 = __expf(m1 - mn1);
        m0 = mn0; m1 = mn1;
        l0 *= c0; l1 *= c1;
#pragma unroll
        for (int n = 0; n < 8; n++) {
            oacc[n][0] *= c0; oacc[n][1] *= c0;
            oacc[n][2] *= c1; oacc[n][3] *= c1;
        }

        float sum0 = 0.f, sum1 = 0.f;
#pragma unroll
        for (int t = 0; t < 4; t++) {
            float p0 = __expf(sacc[2 * t][0] - m0);
            float p1 = __expf(sacc[2 * t][1] - m0);
            float p2 = __expf(sacc[2 * t][2] - m1);
            float p3 = __expf(sacc[2 * t][3] - m1);
            float p4 = __expf(sacc[2 * t + 1][0] - m0);
            float p5 = __expf(sacc[2 * t + 1][1] - m0);
            float p6 = __expf(sacc[2 * t + 1][2] - m1);
            float p7 = __expf(sacc[2 * t + 1][3] - m1);

            unsigned aph[4];
            aph[0] = hfpack(p0, p1);
            aph[1] = hfpack(p2, p3);
            aph[2] = hfpack(p4, p5);
            aph[3] = hfpack(p6, p7);
            // normalizer from the QUANTIZED weights (keeps O/l consistent)
            float2 q0 = hunpack(aph[0]);
            float2 q1 = hunpack(aph[1]);
            float2 q2 = hunpack(aph[2]);
            float2 q3 = hunpack(aph[3]);
            sum0 += (q0.x + q0.y) + (q2.x + q2.y);
            sum1 += (q1.x + q1.y) + (q3.x + q3.y);

            unsigned vh2[8][2], vl2[8][2];
#pragma unroll
            for (int np = 0; np < 4; np++) {
                unsigned eo2 = ((rowB + np * 16) * 72 + kHalf + 16 * t) * 2;
                unsigned v4[4];
                ldm_x4(v4, sVh + eo2);
                vh2[np * 2][0] = v4[0]; vh2[np * 2][1] = v4[2];
                vh2[np * 2 + 1][0] = v4[1]; vh2[np * 2 + 1][1] = v4[3];
                ldm_x4(v4, sVl + eo2);
                vl2[np * 2][0] = v4[0]; vl2[np * 2][1] = v4[2];
                vl2[np * 2 + 1][0] = v4[1]; vl2[np * 2 + 1][1] = v4[3];
            }
#pragma unroll
            for (int n = 0; n < 8; n++)
                mma_f16(oacc[n], aph, vh2[n][0], vh2[n][1]);
#pragma unroll
            for (int n = 0; n < 8; n++)
                mma_f16(oacc[n], aph, vl2[n][0], vl2[n][1]);
        }
        sum0 += __shfl_xor_sync(0xffffffffu, sum0, 1);
        sum0 += __shfl_xor_sync(0xffffffffu, sum0, 2);
        sum1 += __shfl_xor_sync(0xffffffffu, sum1, 1);
        sum1 += __shfl_xor_sync(0xffffffffu, sum1, 2);
        l0 += sum0; l1 += sum1;

        if (kt + 1 < 16) CP_WAIT0;
        __syncthreads();
    }

    // ---- epilogue part 1: normalize attn -> sOut[l][65] ----
    float* sOut = (float*)smraw;
    float* wsm  = (float*)(smraw + 33280);
    float* vsm  = (float*)(smraw + 35584);
    float il0 = 1.f / l0, il1 = 1.f / l1;
    int r0q = wid * 16 + (lane >> 2);
#pragma unroll
    for (int n = 0; n < 8; n++) {
        int d = n * 8 + (lane & 3) * 2;
        sOut[r0q * 65 + d]           = oacc[n][0] * il0;
        sOut[r0q * 65 + d + 1]       = oacc[n][1] * il0;
        sOut[(r0q + 8) * 65 + d]     = oacc[n][2] * il1;
        sOut[(r0q + 8) * 65 + d + 1] = oacc[n][3] * il1;
    }

    // ---- epilogue part 2: load dw weights + V halo slice ----
    for (int i = tid; i < 576; i += 256)
        wsm[i] = w_dw[h * 64 * 9 + i];
#pragma unroll
    for (int i = 0; i < 48; i++) {
        int f = tid + i * 256;
        int d = f / 192;
        int rx = f - d * 192;
        int y = qt * 4 - 1 + (rx >> 5);
        float v = 0.f;
        if (y >= 0 && y < 32) {
            long vo = (long)d * LPIX + y * 32 + (rx & 31);
            v = __half2float(vhp[vo]) + __half2float(vlp[vo]);
        }
        vsm[rx * 68 + d] = v;
    }
    __syncthreads();

    // ---- epilogue part 3: dw conv + BN, add into sOut ----
    {
        int d = tid & 63, ly = tid >> 6;
        float wv[9];
#pragma unroll
        for (int t = 0; t < 9; t++) wv[t] = wsm[d * 9 + t];
        float sdw = s_dw[h * 64 + d], bdw = b_dw[h * 64 + d];
#pragma unroll 4
        for (int lx = 0; lx < 32; lx++) {
            float acc = 0.f;
#pragma unroll
            for (int ky = 0; ky < 3; ky++) {
#pragma unroll
                for (int kx = 0; kx < 3; kx++) {
                    int xx = lx + kx - 1;
                    if (xx >= 0 && xx < 32)
                        acc = fmaf(vsm[((ly + ky) * 32 + xx) * 68 + d],
                                   wv[ky * 3 + kx], acc);
                }
            }
            sOut[(ly * 32 + lx) * 65 + d] += acc * sdw + bdw;
        }
    }
    __syncthreads();

    // ---- epilogue part 4: split-write transposed mid -> g_mth/g_mtl ----
    bf16* th = g_mth + ((long)b * LPIX + qt * 128) * CH + h * 64;
    bf16* tl = g_mtl + ((long)b * LPIX + qt * 128) * CH + h * 64;
#pragma unroll
    for (int it = 0; it < 32; it++) {
        int f = tid + it * 256;
        int l = f >> 6, d = f & 63;
        float v = sOut[l * 65 + d];
        bf16 hv = __float2bfloat16(v);
        th[(long)l * CH + d] = hv;
        tl[(long)l * CH + d] = __float2bfloat16(v - __bfloat162float(hv));
    }
}

// ---------------------------------------------------------------------------
extern "C" void kernel_launch(void* const* d_in, const int* in_sizes, int n_in,
                              void* d_out, int out_size)
{
    const float* x     = (const float*)d_in[0];
    const float* w_qkv = (const float*)d_in[1];
    const float* s_qkv = (const float*)d_in[2];
    const float* b_qkv = (const float*)d_in[3];
    const float* w_dw  = (const float*)d_in[4];
    const float* s_dw  = (const float*)d_in[5];
    const float* b_dw  = (const float*)d_in[6];
    const float* w_pw  = (const float*)d_in[7];
    const float* s_pw  = (const float*)d_in[8];
    const float* b_pw  = (const float*)d_in[9];
    float* out = (float*)d_out;

    bf16 *wqh, *wql, *wph, *wpl, *xth, *xtl, *mth, *mtl;
    cudaGetSymbolAddress((void**)&wqh, g_wqh);
    cudaGetSymbolAddress((void**)&wql, g_wql);
    cudaGetSymbolAddress((void**)&wph, g_wph);
    cudaGetSymbolAddress((void**)&wpl, g_wpl);
    cudaGetSymbolAddress((void**)&xth, g_xth);
    cudaGetSymbolAddress((void**)&xtl, g_xtl);
    cudaGetSymbolAddress((void**)&mth, g_mth);
    cudaGetSymbolAddress((void**)&mtl, g_mtl);

    cudaFuncSetAttribute(attn_hmma, cudaFuncAttributeMaxDynamicSharedMemorySize, AT_SMEM);
    cudaFuncSetAttribute(hmma_gemm_bn, cudaFuncAttributeMaxDynamicSharedMemorySize, G2_SMEM);
    cudaFuncSetAttribute(hmma_qkv, cudaFuncAttributeMaxDynamicSharedMemorySize, G2_SMEM);

    // Prep: split weights; transpose+split x
    split_w_kernel<<<(CQKV * CH + 255) / 256, 256>>>(w_qkv, wqh, wql, CQKV * CH);
    split_w_kernel<<<(CH * CH + 255) / 256, 256>>>(w_pw, wph, wpl, CH * CH);
    split_t_kernel<<<dim3(LPIX / 64, CH / 64, BATCH), 256>>>(x, xth, xtl, CH, LPIX);

    // 1) qkv GEMM with fused split epilogue -> g_qh/ql/kh/kl/vh/vl
    hmma_qkv<<<dim3(8, 4, 16), 256, G2_SMEM>>>(wqh, wql, xth, xtl, s_qkv, b_qkv);
    // 2) attention; epilogue computes dwconv inline, adds, writes split mth/mtl
    attn_hmma<<<dim3(8, 4, 16), 256, AT_SMEM>>>(w_dw, s_dw, b_dw);
    // 3) out = bn(W_pw @ (attn + dwconv))
    hmma_gemm_bn<<<dim3(8, 2, 16), 256, G2_SMEM>>>(wph, wpl, mth, mtl, out,
                                                   s_pw, b_pw, CH, LPIX, CH);
}

// round 17
// speedup vs baseline: 3.2381x; 1.1276x over previous
#include <cuda_runtime.h>
#include <cuda_bf16.h>
#include <cuda_fp16.h>
#include <math.h>

// Problem constants
#define BATCH 16
#define CH    256
#define NH    4
#define DH    64
#define LPIX  1024
#define CQKV  512
#define SCALE 0.17677669529663687f   // 32^-0.5

typedef unsigned long long u64;
typedef __nv_bfloat16 bf16;

__device__ __forceinline__ unsigned smem_u32(const void* p) {
    unsigned r;
    asm("{ .reg .u64 t; cvta.to.shared.u64 t, %1; cvt.u32.u64 %0, t; }" : "=r"(r) : "l"(p));
    return r;
}

// ---------------- mma.sync + cp.async helpers ----------------
__device__ __forceinline__ void ldm_x4(unsigned* r, unsigned addr) {
    asm volatile("ldmatrix.sync.aligned.m8n8.x4.shared.b16 {%0,%1,%2,%3}, [%4];"
                 : "=r"(r[0]), "=r"(r[1]), "=r"(r[2]), "=r"(r[3]) : "r"(addr));
}
__device__ __forceinline__ void mma_bf16(float* c, const unsigned* a, unsigned b0, unsigned b1) {
    asm volatile(
        "mma.sync.aligned.m16n8k16.row.col.f32.bf16.bf16.f32 "
        "{%0,%1,%2,%3}, {%4,%5,%6,%7}, {%8,%9}, {%0,%1,%2,%3};"
        : "+f"(c[0]), "+f"(c[1]), "+f"(c[2]), "+f"(c[3])
        : "r"(a[0]), "r"(a[1]), "r"(a[2]), "r"(a[3]), "r"(b0), "r"(b1));
}
__device__ __forceinline__ void mma_f16(float* c, const unsigned* a, unsigned b0, unsigned b1) {
    asm volatile(
        "mma.sync.aligned.m16n8k16.row.col.f32.f16.f16.f32 "
        "{%0,%1,%2,%3}, {%4,%5,%6,%7}, {%8,%9}, {%0,%1,%2,%3};"
        : "+f"(c[0]), "+f"(c[1]), "+f"(c[2]), "+f"(c[3])
        : "r"(a[0]), "r"(a[1]), "r"(a[2]), "r"(a[3]), "r"(b0), "r"(b1));
}
__device__ __forceinline__ unsigned hfpack(float lo, float hi) {
    unsigned r;
    asm("cvt.rn.f16x2.f32 %0, %1, %2;" : "=r"(r) : "f"(hi), "f"(lo));
    return r;
}
__device__ __forceinline__ float2 hunpack(unsigned v) {
    __half2 h = *reinterpret_cast<__half2*>(&v);
    return __half22float2(h);
}
__device__ __forceinline__ void cpa16(unsigned dst, const void* src) {
    asm volatile("cp.async.ca.shared.global [%0], [%1], 16;" :: "r"(dst), "l"(src));
}
#define CP_COMMIT asm volatile("cp.async.commit_group;" ::: "memory")
#define CP_WAIT0  asm volatile("cp.async.wait_group 0;" ::: "memory")

// ---------------- scratch (allocation-free: __device__ globals) ----------------
__device__ bf16 g_wqh[CQKV * CH], g_wql[CQKV * CH];
__device__ bf16 g_wph[CH * CH],   g_wpl[CH * CH];
__device__ bf16 g_xth[(long)BATCH * LPIX * CH], g_xtl[(long)BATCH * LPIX * CH];
__device__ bf16 g_mth[(long)BATCH * LPIX * CH], g_mtl[(long)BATCH * LPIX * CH];
// Attention operands: Q/K single fp16 [bh][l][32], V fp16 pair [bh][d][1024]
__device__ __half g_q[(long)64 * LPIX * 32], g_k[(long)64 * LPIX * 32];
__device__ __half g_vh[(long)64 * 64 * LPIX], g_vl[(long)64 * 64 * LPIX];

// ---------------------------------------------------------------------------
// Split fp32 -> bf16 hi/lo (elementwise; layout preserved)
// ---------------------------------------------------------------------------
__global__ void split_w_kernel(const float* __restrict__ w,
                               bf16* __restrict__ h, bf16* __restrict__ l, int n)
{
    int i = blockIdx.x * 256 + threadIdx.x;
    if (i < n) {
        float v = w[i];
        bf16 hh = __float2bfloat16(v);
        h[i] = hh;
        l[i] = __float2bfloat16(v - __bfloat162float(hh));
    }
}

// ---------------------------------------------------------------------------
// Transpose + split: X[b][k][n] fp32 -> T[b][n][k] bf16 hi/lo. 64x64 tiles.
// ---------------------------------------------------------------------------
__global__ __launch_bounds__(256)
void split_t_kernel(const float* __restrict__ X,
                    bf16* __restrict__ Th, bf16* __restrict__ Tl, int K, int N)
{
    __shared__ float t[64][65];
    const int n0 = blockIdx.x * 64;
    const int k0 = blockIdx.y * 64;
    const long b = blockIdx.z;
    const float* Xb = X + b * (long)K * N;
    bf16* ThB = Th + b * (long)K * N;
    bf16* TlB = Tl + b * (long)K * N;
    const int tx = threadIdx.x & 63, ty = threadIdx.x >> 6;

#pragma unroll
    for (int i = 0; i < 16; i++)
        t[ty + i * 4][tx] = Xb[(long)(k0 + ty + i * 4) * N + n0 + tx];
    __syncthreads();

#pragma unroll
    for (int i = 0; i < 16; i++) {
        int n = ty + i * 4;
        float v = t[tx][n];
        bf16 hh = __float2bfloat16(v);
        ThB[(long)(n0 + n) * K + k0 + tx] = hh;
        TlB[(long)(n0 + n) * K + k0 + tx] = __float2bfloat16(v - __bfloat162float(hh));
    }
}

// ---------------------------------------------------------------------------
// HMMA bf16-split GEMM shared tile constants.
// ---------------------------------------------------------------------------
#define G2_PAD   40
#define G2_TILEB 10240
#define G2_STAGE 40960
#define G2_SMEM  81920

// Generic GEMM + BN -> fp32 out (used for pw projection).
__global__ __launch_bounds__(256, 2)
void hmma_gemm_bn(const bf16* __restrict__ Ah, const bf16* __restrict__ Al,
                  const bf16* __restrict__ Bh, const bf16* __restrict__ Bl,
                  float* __restrict__ Y, const float* __restrict__ scale,
                  const float* __restrict__ bias, int M, int N, int K)
{
    extern __shared__ char smem[];
    const unsigned sb = smem_u32(smem);
    const int tid = threadIdx.x;
    const int wid = tid >> 5, lane = tid & 31;
    const int wm = wid & 3, wn = wid >> 2;
    const int n0 = blockIdx.x * 128;
    const int m0 = blockIdx.y * 128;
    const long bz = blockIdx.z;
    const bf16* Bhb = Bh + bz * (long)N * K;
    const bf16* Blb = Bl + bz * (long)N * K;
    float* Yb = Y + bz * (long)M * N;

    float acc[2][8][4];
#pragma unroll
    for (int mi = 0; mi < 2; mi++)
#pragma unroll
        for (int ni = 0; ni < 8; ni++)
#pragma unroll
            for (int j = 0; j < 4; j++) acc[mi][ni][j] = 0.f;

    const unsigned aRow = (unsigned)(wm * 32 + (lane & 15));
    const unsigned bRow = (unsigned)(wn * 64 + (lane & 15));
    const unsigned kHalf = (unsigned)((lane >> 4) * 8);

    auto load_chunk = [&](int st, int kc) {
        unsigned db = sb + st * G2_STAGE;
#pragma unroll
        for (int i = 0; i < 2; i++) {
            int f = tid + i * 256;
            int r = f >> 2, c4 = f & 3;
            unsigned d0 = db + r * 80 + c4 * 16;
            cpa16(d0,                 Ah  + (long)(m0 + r) * K + kc + c4 * 8);
            cpa16(d0 + G2_TILEB,      Al  + (long)(m0 + r) * K + kc + c4 * 8);
            cpa16(d0 + 2 * G2_TILEB,  Bhb + (long)(n0 + r) * K + kc + c4 * 8);
            cpa16(d0 + 3 * G2_TILEB,  Blb + (long)(n0 + r) * K + kc + c4 * 8);
        }
    };

    const int NCH = K / 32;
    load_chunk(0, 0);
    CP_COMMIT;
    CP_WAIT0;
    __syncthreads();

    for (int c = 0; c < NCH; c++) {
        const int st = c & 1;
        if (c + 1 < NCH) { load_chunk(1 - st, (c + 1) * 32); CP_COMMIT; }

        unsigned base = sb + st * G2_STAGE;
#pragma unroll
        for (int k16 = 0; k16 < 32; k16 += 16) {
            unsigned ah[2][4], al[2][4];
#pragma unroll
            for (int mi = 0; mi < 2; mi++) {
                unsigned eo = ((aRow + mi * 16) * G2_PAD + kHalf + k16) * 2;
                ldm_x4(ah[mi], base + eo);
                ldm_x4(al[mi], base + G2_TILEB + eo);
            }
            unsigned bh[8][2], bl[8][2];
#pragma unroll
            for (int np = 0; np < 4; np++) {
                unsigned eo = ((bRow + np * 16) * G2_PAD + kHalf + k16) * 2;
                unsigned r4[4];
                ldm_x4(r4, base + 2 * G2_TILEB + eo);
                bh[np * 2][0] = r4[0]; bh[np * 2][1] = r4[2];
                bh[np * 2 + 1][0] = r4[1]; bh[np * 2 + 1][1] = r4[3];
                ldm_x4(r4, base + 3 * G2_TILEB + eo);
                bl[np * 2][0] = r4[0]; bl[np * 2][1] = r4[2];
                bl[np * 2 + 1][0] = r4[1]; bl[np * 2 + 1][1] = r4[3];
            }
#pragma unroll
            for (int mi = 0; mi < 2; mi++)
#pragma unroll
                for (int ni = 0; ni < 8; ni++)
                    mma_bf16(acc[mi][ni], ah[mi], bh[ni][0], bh[ni][1]);
#pragma unroll
            for (int mi = 0; mi < 2; mi++)
#pragma unroll
                for (int ni = 0; ni < 8; ni++)
                    mma_bf16(acc[mi][ni], ah[mi], bl[ni][0], bl[ni][1]);
#pragma unroll
            for (int mi = 0; mi < 2; mi++)
#pragma unroll
                for (int ni = 0; ni < 8; ni++)
                    mma_bf16(acc[mi][ni], al[mi], bh[ni][0], bh[ni][1]);
        }
        if (c + 1 < NCH) CP_WAIT0;
        __syncthreads();
    }

#pragma unroll
    for (int mi = 0; mi < 2; mi++) {
        int r1 = m0 + wm * 32 + mi * 16 + (lane >> 2);
        int r2 = r1 + 8;
        float s1 = scale[r1], b1 = bias[r1];
        float s2 = scale[r2], b2 = bias[r2];
        float* y1 = &Yb[(long)r1 * N + n0 + wn * 64 + (lane & 3) * 2];
        float* y2 = &Yb[(long)r2 * N + n0 + wn * 64 + (lane & 3) * 2];
#pragma unroll
        for (int ni = 0; ni < 8; ni++) {
            float2 o1, o2;
            o1.x = acc[mi][ni][0] * s1 + b1;
            o1.y = acc[mi][ni][1] * s1 + b1;
            o2.x = acc[mi][ni][2] * s2 + b2;
            o2.y = acc[mi][ni][3] * s2 + b2;
            *reinterpret_cast<float2*>(y1 + ni * 8) = o1;
            *reinterpret_cast<float2*>(y2 + ni * 8) = o2;
        }
    }
}

// ---------------------------------------------------------------------------
// qkv GEMM with FUSED split epilogue: Q/K single fp16 (Q pre-scaled),
// V fp16 pair.
// ---------------------------------------------------------------------------
__global__ __launch_bounds__(256, 2)
void hmma_qkv(const bf16* __restrict__ Ah, const bf16* __restrict__ Al,
              const bf16* __restrict__ Bh, const bf16* __restrict__ Bl,
              const float* __restrict__ scale, const float* __restrict__ bias)
{
    extern __shared__ char smem[];
    const unsigned sb = smem_u32(smem);
    const int tid = threadIdx.x;
    const int wid = tid >> 5, lane = tid & 31;
    const int wm = wid & 3, wn = wid >> 2;
    const int n0 = blockIdx.x * 128;
    const int m0 = blockIdx.y * 128;     // head h = blockIdx.y
    const long bz = blockIdx.z;
    const int K = CH, N = LPIX;
    const bf16* Bhb = Bh + bz * (long)N * K;
    const bf16* Blb = Bl + bz * (long)N * K;

    float acc[2][8][4];
#pragma unroll
    for (int mi = 0; mi < 2; mi++)
#pragma unroll
        for (int ni = 0; ni < 8; ni++)
#pragma unroll
            for (int j = 0; j < 4; j++) acc[mi][ni][j] = 0.f;

    const unsigned aRow = (unsigned)(wm * 32 + (lane & 15));
    const unsigned bRow = (unsigned)(wn * 64 + (lane & 15));
    const unsigned kHalf = (unsigned)((lane >> 4) * 8);

    auto load_chunk = [&](int st, int kc) {
        unsigned db = sb + st * G2_STAGE;
#pragma unroll
        for (int i = 0; i < 2; i++) {
            int f = tid + i * 256;
            int r = f >> 2, c4 = f & 3;
            unsigned d0 = db + r * 80 + c4 * 16;
            cpa16(d0,                 Ah  + (long)(m0 + r) * K + kc + c4 * 8);
            cpa16(d0 + G2_TILEB,      Al  + (long)(m0 + r) * K + kc + c4 * 8);
            cpa16(d0 + 2 * G2_TILEB,  Bhb + (long)(n0 + r) * K + kc + c4 * 8);
            cpa16(d0 + 3 * G2_TILEB,  Blb + (long)(n0 + r) * K + kc + c4 * 8);
        }
    };

    const int NCH = K / 32;
    load_chunk(0, 0);
    CP_COMMIT;
    CP_WAIT0;
    __syncthreads();

    for (int c = 0; c < NCH; c++) {
        const int st = c & 1;
        if (c + 1 < NCH) { load_chunk(1 - st, (c + 1) * 32); CP_COMMIT; }

        unsigned base = sb + st * G2_STAGE;
#pragma unroll
        for (int k16 = 0; k16 < 32; k16 += 16) {
            unsigned ah[2][4], al[2][4];
#pragma unroll
            for (int mi = 0; mi < 2; mi++) {
                unsigned eo = ((aRow + mi * 16) * G2_PAD + kHalf + k16) * 2;
                ldm_x4(ah[mi], base + eo);
                ldm_x4(al[mi], base + G2_TILEB + eo);
            }
            unsigned bh[8][2], bl[8][2];
#pragma unroll
            for (int np = 0; np < 4; np++) {
                unsigned eo = ((bRow + np * 16) * G2_PAD + kHalf + k16) * 2;
                unsigned r4[4];
                ldm_x4(r4, base + 2 * G2_TILEB + eo);
                bh[np * 2][0] = r4[0]; bh[np * 2][1] = r4[2];
                bh[np * 2 + 1][0] = r4[1]; bh[np * 2 + 1][1] = r4[3];
                ldm_x4(r4, base + 3 * G2_TILEB + eo);
                bl[np * 2][0] = r4[0]; bl[np * 2][1] = r4[2];
                bl[np * 2 + 1][0] = r4[1]; bl[np * 2 + 1][1] = r4[3];
            }
#pragma unroll
            for (int mi = 0; mi < 2; mi++)
#pragma unroll
                for (int ni = 0; ni < 8; ni++)
                    mma_bf16(acc[mi][ni], ah[mi], bh[ni][0], bh[ni][1]);
#pragma unroll
            for (int mi = 0; mi < 2; mi++)
#pragma unroll
                for (int ni = 0; ni < 8; ni++)
                    mma_bf16(acc[mi][ni], ah[mi], bl[ni][0], bl[ni][1]);
#pragma unroll
            for (int mi = 0; mi < 2; mi++)
#pragma unroll
                for (int ni = 0; ni < 8; ni++)
                    mma_bf16(acc[mi][ni], al[mi], bh[ni][0], bh[ni][1]);
        }
        if (c + 1 < NCH) CP_WAIT0;
        __syncthreads();
    }

    // ---- fused epilogue: stage BN'd tile [128][133] then split-write ----
    float* st = (float*)smem;
#pragma unroll
    for (int mi = 0; mi < 2; mi++) {
        int rl1 = wm * 32 + mi * 16 + (lane >> 2);
        int rl2 = rl1 + 8;
        float s1 = scale[m0 + rl1], b1 = bias[m0 + rl1];
        float s2 = scale[m0 + rl2], b2 = bias[m0 + rl2];
#pragma unroll
        for (int ni = 0; ni < 8; ni++) {
            int cj = wn * 64 + ni * 8 + (lane & 3) * 2;
            st[rl1 * 133 + cj]     = acc[mi][ni][0] * s1 + b1;
            st[rl1 * 133 + cj + 1] = acc[mi][ni][1] * s1 + b1;
            st[rl2 * 133 + cj]     = acc[mi][ni][2] * s2 + b2;
            st[rl2 * 133 + cj + 1] = acc[mi][ni][3] * s2 + b2;
        }
    }
    __syncthreads();

    const int bh_ = (int)bz * 4 + blockIdx.y;
    // Q rows 0..31 -> [l][32] single fp16, pre-scaled
#pragma unroll
    for (int i = 0; i < 16; i++) {
        int f = tid + i * 256;
        int j = f >> 5, d = f & 31;
        g_q[((long)bh_ * LPIX + n0 + j) * 32 + d] =
            __float2half(st[d * 133 + j] * SCALE);
    }
    // K rows 32..63 -> [l][32] single fp16
#pragma unroll
    for (int i = 0; i < 16; i++) {
        int f = tid + i * 256;
        int j = f >> 5, d = f & 31;
        g_k[((long)bh_ * LPIX + n0 + j) * 32 + d] =
            __float2half(st[(32 + d) * 133 + j]);
    }
    // V rows 64..127 -> [d][l] fp16 pair
#pragma unroll
    for (int i = 0; i < 32; i++) {
        int f = tid + i * 256;
        int d = f >> 7, j = f & 127;
        float v = st[(64 + d) * 133 + j];
        __half hv = __float2half(v);
        long o = ((long)bh_ * 64 + d) * LPIX + n0 + j;
        g_vh[o] = hv;
        g_vl[o] = __float2half(v - __half2float(hv));
    }
}

// ---------------------------------------------------------------------------
// HMMA flash attention. S = QK^T single fp16 (1 MMA/tile). PV: P fp16,
// V fp16 pair (2 MMAs/tile). Epilogue: inline dw conv + BN + add, split-write.
// smem: Q @0 (10240) | K stages @10240+st*5120 | V stages @20480+st*18432
// epilogue: sOut[128][65] @0 | wsm @33280 | vsm @35584.  AT_SMEM 88064
// ---------------------------------------------------------------------------
#define AT_SMEM 88064

__global__ __launch_bounds__(256, 2)
void attn_hmma(const float* __restrict__ w_dw, const float* __restrict__ s_dw,
               const float* __restrict__ b_dw)
{
    extern __shared__ char smraw[];
    const unsigned sb = smem_u32(smraw);
    const int tid = threadIdx.x;
    const int wid = tid >> 5, lane = tid & 31;
    const int qt = blockIdx.x, h = blockIdx.y, b = blockIdx.z;
    const int bh = b * 4 + h;

    const __half* qp = g_q + ((long)bh * LPIX + qt * 128) * 32;
    const __half* kp = g_k + (long)bh * LPIX * 32;
    const __half* vhp = g_vh + (long)bh * 64 * LPIX;
    const __half* vlp = g_vl + (long)bh * 64 * LPIX;

    // Q tile: 128 rows x 64B single
#pragma unroll
    for (int i = 0; i < 2; i++) {
        int f = tid + i * 256;
        int r = f >> 2, c4 = f & 3;
        cpa16(sb + r * 80 + c4 * 16, qp + r * 32 + c4 * 8);
    }

    auto load_kv = [&](int st, int kt) {
        unsigned kb = sb + 10240 + st * 5120;
        unsigned vb = sb + 20480 + st * 18432;
        {
            int r = tid >> 2, c4 = tid & 3;
            cpa16(kb + r * 80 + c4 * 16, kp + (long)(kt * 64 + r) * 32 + c4 * 8);
        }
#pragma unroll
        for (int i = 0; i < 2; i++) {
            int f = tid + i * 256;
            int d = f >> 3, j8 = f & 7;
            cpa16(vb + d * 144 + j8 * 16,        vhp + (long)d * LPIX + kt * 64 + j8 * 8);
            cpa16(vb + 9216 + d * 144 + j8 * 16, vlp + (long)d * LPIX + kt * 64 + j8 * 8);
        }
    };

    load_kv(0, 0);
    CP_COMMIT;
    CP_WAIT0;
    __syncthreads();

    float oacc[8][4];
#pragma unroll
    for (int n = 0; n < 8; n++)
#pragma unroll
        for (int j = 0; j < 4; j++) oacc[n][j] = 0.f;
    float m0 = -INFINITY, m1 = -INFINITY, l0 = 0.f, l1 = 0.f;

    const unsigned rowA = (unsigned)(wid * 16 + (lane & 15));
    const unsigned rowB = (unsigned)(lane & 15);
    const unsigned kHalf = (unsigned)((lane >> 4) * 8);

    for (int kt = 0; kt < 16; kt++) {
        const int st = kt & 1;
        if (kt + 1 < 16) { load_kv(1 - st, kt + 1); CP_COMMIT; }

        const unsigned sKb = sb + 10240 + st * 5120;
        const unsigned sVh = sb + 20480 + st * 18432;
        const unsigned sVl = sVh + 9216;

        // ---- S = Q K^T : single fp16, 1 MMA per tile ----
        float sacc[8][4];
#pragma unroll
        for (int n = 0; n < 8; n++)
#pragma unroll
            for (int j = 0; j < 4; j++) sacc[n][j] = 0.f;

#pragma unroll
        for (int t = 0; t < 2; t++) {
            unsigned aq[4];
            unsigned eo = (rowA * 40 + kHalf + 16 * t) * 2;
            ldm_x4(aq, sb + eo);
            unsigned bk[8][2];
#pragma unroll
            for (int np = 0; np < 4; np++) {
                unsigned eo2 = ((rowB + np * 16) * 40 + kHalf + 16 * t) * 2;
                unsigned r4[4];
                ldm_x4(r4, sKb + eo2);
                bk[np * 2][0] = r4[0]; bk[np * 2][1] = r4[2];
                bk[np * 2 + 1][0] = r4[1]; bk[np * 2 + 1][1] = r4[3];
            }
#pragma unroll
            for (int n = 0; n < 8; n++)
                mma_f16(sacc[n], aq, bk[n][0], bk[n][1]);
        }

        // ---- online softmax ----
        float mx0 = sacc[0][0], mx1 = sacc[0][2];
#pragma unroll
        for (int n = 0; n < 8; n++) {
            mx0 = fmaxf(mx0, fmaxf(sacc[n][0], sacc[n][1]));
            mx1 = fmaxf(mx1, fmaxf(sacc[n][2], sacc[n][3]));
        }
        mx0 = fmaxf(mx0, __shfl_xor_sync(0xffffffffu, mx0, 1));
        mx0 = fmaxf(mx0, __shfl_xor_sync(0xffffffffu, mx0, 2));
        mx1 = fmaxf(mx1, __shfl_xor_sync(0xffffffffu, mx1, 1));
        mx1 = fmaxf(mx1, __shfl_xor_sync(0xffffffffu, mx1, 2));
        float mn0 = fmaxf(m0, mx0), mn1 = fmaxf(m1, mx1);
        float c0 = __expf(m0 - mn0), c1 = __expf(m1 - mn1);
        m0 = mn0; m1 = mn1;
        l0 *= c0; l1 *= c1;
#pragma unroll
        for (int n = 0; n < 8; n++) {
            oacc[n][0] *= c0; oacc[n][1] *= c0;
            oacc[n][2] *= c1; oacc[n][3] *= c1;
        }

        // ---- P = exp(S-m) fp16; O += P V (V pair) ----
        float sum0 = 0.f, sum1 = 0.f;
#pragma unroll
        for (int t = 0; t < 4; t++) {
            float p0 = __expf(sacc[2 * t][0] - m0);
            float p1 = __expf(sacc[2 * t][1] - m0);
            float p2 = __expf(sacc[2 * t][2] - m1);
            float p3 = __expf(sacc[2 * t][3] - m1);
            float p4 = __expf(sacc[2 * t + 1][0] - m0);
            float p5 = __expf(sacc[2 * t + 1][1] - m0);
            float p6 = __expf(sacc[2 * t + 1][2] - m1);
            float p7 = __expf(sacc[2 * t + 1][3] - m1);

            unsigned aph[4];
            aph[0] = hfpack(p0, p1);
            aph[1] = hfpack(p2, p3);
            aph[2] = hfpack(p4, p5);
            aph[3] = hfpack(p6, p7);
            float2 q0 = hunpack(aph[0]);
            float2 q1 = hunpack(aph[1]);
            float2 q2 = hunpack(aph[2]);
            float2 q3 = hunpack(aph[3]);
            sum0 += (q0.x + q0.y) + (q2.x + q2.y);
            sum1 += (q1.x + q1.y) + (q3.x + q3.y);

            unsigned vh2[8][2], vl2[8][2];
#pragma unroll
            for (int np = 0; np < 4; np++) {
                unsigned eo2 = ((rowB + np * 16) * 72 + kHalf + 16 * t) * 2;
                unsigned v4[4];
                ldm_x4(v4, sVh + eo2);
                vh2[np * 2][0] = v4[0]; vh2[np * 2][1] = v4[2];
                vh2[np * 2 + 1][0] = v4[1]; vh2[np * 2 + 1][1] = v4[3];
                ldm_x4(v4, sVl + eo2);
                vl2[np * 2][0] = v4[0]; vl2[np * 2][1] = v4[2];
                vl2[np * 2 + 1][0] = v4[1]; vl2[np * 2 + 1][1] = v4[3];
            }
#pragma unroll
            for (int n = 0; n < 8; n++)
                mma_f16(oacc[n], aph, vh2[n][0], vh2[n][1]);
#pragma unroll
            for (int n = 0; n < 8; n++)
                mma_f16(oacc[n], aph, vl2[n][0], vl2[n][1]);
        }
        sum0 += __shfl_xor_sync(0xffffffffu, sum0, 1);
        sum0 += __shfl_xor_sync(0xffffffffu, sum0, 2);
        sum1 += __shfl_xor_sync(0xffffffffu, sum1, 1);
        sum1 += __shfl_xor_sync(0xffffffffu, sum1, 2);
        l0 += sum0; l1 += sum1;

        if (kt + 1 < 16) CP_WAIT0;
        __syncthreads();
    }

    // ---- epilogue part 1: normalize attn -> sOut[l][65] ----
    float* sOut = (float*)smraw;
    float* wsm  = (float*)(smraw + 33280);
    float* vsm  = (float*)(smraw + 35584);
    float il0 = 1.f / l0, il1 = 1.f / l1;
    int r0q = wid * 16 + (lane >> 2);
#pragma unroll
    for (int n = 0; n < 8; n++) {
        int d = n * 8 + (lane & 3) * 2;
        sOut[r0q * 65 + d]           = oacc[n][0] * il0;
        sOut[r0q * 65 + d + 1]       = oacc[n][1] * il0;
        sOut[(r0q + 8) * 65 + d]     = oacc[n][2] * il1;
        sOut[(r0q + 8) * 65 + d + 1] = oacc[n][3] * il1;
    }

    // ---- epilogue part 2: load dw weights + V halo slice ----
    for (int i = tid; i < 576; i += 256)
        wsm[i] = w_dw[h * 64 * 9 + i];
#pragma unroll
    for (int i = 0; i < 48; i++) {
        int f = tid + i * 256;
        int d = f / 192;
        int rx = f - d * 192;
        int y = qt * 4 - 1 + (rx >> 5);
        float v = 0.f;
        if (y >= 0 && y < 32) {
            long vo = (long)d * LPIX + y * 32 + (rx & 31);
            v = __half2float(vhp[vo]) + __half2float(vlp[vo]);
        }
        vsm[rx * 68 + d] = v;
    }
    __syncthreads();

    // ---- epilogue part 3: dw conv + BN, add into sOut ----
    {
        int d = tid & 63, ly = tid >> 6;
        float wv[9];
#pragma unroll
        for (int t = 0; t < 9; t++) wv[t] = wsm[d * 9 + t];
        float sdw = s_dw[h * 64 + d], bdw = b_dw[h * 64 + d];
#pragma unroll 4
        for (int lx = 0; lx < 32; lx++) {
            float acc = 0.f;
#pragma unroll
            for (int ky = 0; ky < 3; ky++) {
#pragma unroll
                for (int kx = 0; kx < 3; kx++) {
                    int xx = lx + kx - 1;
                    if (xx >= 0 && xx < 32)
                        acc = fmaf(vsm[((ly + ky) * 32 + xx) * 68 + d],
                                   wv[ky * 3 + kx], acc);
                }
            }
            sOut[(ly * 32 + lx) * 65 + d] += acc * sdw + bdw;
        }
    }
    __syncthreads();

    // ---- epilogue part 4: split-write transposed mid -> g_mth/g_mtl ----
    bf16* th = g_mth + ((long)b * LPIX + qt * 128) * CH + h * 64;
    bf16* tl = g_mtl + ((long)b * LPIX + qt * 128) * CH + h * 64;
#pragma unroll
    for (int it = 0; it < 32; it++) {
        int f = tid + it * 256;
        int l = f >> 6, d = f & 63;
        float v = sOut[l * 65 + d];
        bf16 hv = __float2bfloat16(v);
        th[(long)l * CH + d] = hv;
        tl[(long)l * CH + d] = __float2bfloat16(v - __bfloat162float(hv));
    }
}

// ---------------------------------------------------------------------------
extern "C" void kernel_launch(void* const* d_in, const int* in_sizes, int n_in,
                              void* d_out, int out_size)
{
    const float* x     = (const float*)d_in[0];
    const float* w_qkv = (const float*)d_in[1];
    const float* s_qkv = (const float*)d_in[2];
    const float* b_qkv = (const float*)d_in[3];
    const float* w_dw  = (const float*)d_in[4];
    const float* s_dw  = (const float*)d_in[5];
    const float* b_dw  = (const float*)d_in[6];
    const float* w_pw  = (const float*)d_in[7];
    const float* s_pw  = (const float*)d_in[8];
    const float* b_pw  = (const float*)d_in[9];
    float* out = (float*)d_out;

    bf16 *wqh, *wql, *wph, *wpl, *xth, *xtl, *mth, *mtl;
    cudaGetSymbolAddress((void**)&wqh, g_wqh);
    cudaGetSymbolAddress((void**)&wql, g_wql);
    cudaGetSymbolAddress((void**)&wph, g_wph);
    cudaGetSymbolAddress((void**)&wpl, g_wpl);
    cudaGetSymbolAddress((void**)&xth, g_xth);
    cudaGetSymbolAddress((void**)&xtl, g_xtl);
    cudaGetSymbolAddress((void**)&mth, g_mth);
    cudaGetSymbolAddress((void**)&mtl, g_mtl);

    cudaFuncSetAttribute(attn_hmma, cudaFuncAttributeMaxDynamicSharedMemorySize, AT_SMEM);
    cudaFuncSetAttribute(hmma_gemm_bn, cudaFuncAttributeMaxDynamicSharedMemorySize, G2_SMEM);
    cudaFuncSetAttribute(hmma_qkv, cudaFuncAttributeMaxDynamicSharedMemorySize, G2_SMEM);

    // Prep: split weights; transpose+split x
    split_w_kernel<<<(CQKV * CH + 255) / 256, 256>>>(w_qkv, wqh, wql, CQKV * CH);
    split_w_kernel<<<(CH * CH + 255) / 256, 256>>>(w_pw, wph, wpl, CH * CH);
    split_t_kernel<<<dim3(LPIX / 64, CH / 64, BATCH), 256>>>(x, xth, xtl, CH, LPIX);

    // 1) qkv GEMM with fused split epilogue -> g_q/g_k/g_vh/g_vl
    hmma_qkv<<<dim3(8, 4, 16), 256, G2_SMEM>>>(wqh, wql, xth, xtl, s_qkv, b_qkv);
    // 2) attention; epilogue computes dwconv inline, adds, writes split mth/mtl
    attn_hmma<<<dim3(8, 4, 16), 256, AT_SMEM>>>(w_dw, s_dw, b_dw);
    // 3) out = bn(W_pw @ (attn + dwconv))
    hmma_gemm_bn<<<dim3(8, 2, 16), 256, G2_SMEM>>>(wph, wpl, mth, mtl, out,
                                                   s_pw, b_pw, CH, LPIX, CH);
}